// round 7
// baseline (speedup 1.0000x reference)
#include <cuda_runtime.h>
#include <math.h>

// ---------------------------------------------------------------------------
// StateModelEncoder — round 5: round-3 skeleton (atomic z-scatter for ei_h /
// ei_in) + fused RGCN/hop1, p-form state hops, MLP-unrolled gathers, fused
// dense chain and head.
// ---------------------------------------------------------------------------

#define NVn 100000
#define NSn 50000
#define EVVmax 1600000
#define ESSmax 800000

// ------------------------- scratch (device globals) ------------------------
__device__ __align__(16) float g_xpad[NVn * 8];
__device__ float g_dinv_v[NVn];
__device__ __align__(16) float g_z[NVn * 40];          // [x5|rgcn15|hops15|0 pad5]
__device__ __align__(16) float g_pv[2][NVn * 8];
__device__ __align__(16) float g_Wz[40 * 64];
__device__ float g_c0[64];
__device__ __align__(16) float g_WzW[4][40 * 64];
__device__ float g_c0W[4][64];
__device__ __align__(16) float g_aggw[NSn * 40];
__device__ __align__(16) float g_aggu[NSn * 40];
__device__ float g_cnt_h[NSn];
__device__ float g_wsum_h[NSn];
__device__ __align__(16) float g_aggin[NSn * 40];
__device__ float g_cnt_in[NSn];
__device__ __align__(16) float g_sx5[NSn * 64];
__device__ __align__(16) float g_pin[NSn * 64];
__device__ __align__(16) float g_pk[3][NSn * 64];
__device__ __align__(16) float g_sx6[NSn * 64];
__device__ __align__(16) float g_accs5[NSn * 64];
__device__ float g_dinv_s[NSn];
__device__ float g_sqd_s[NSn];
__device__ float g_cntf_s[NSn];

// CSR structures (vv, ss only)
__device__ int g_deg_vv[NVn]; __device__ int g_off_vv[NVn]; __device__ int g_cur_vv[NVn];
__device__ int g_tmp_vv[NVn]; __device__ int g_part_vv[128];
__device__ int g_csr_vv[EVVmax];                       // src | (etype<<20)
__device__ int g_deg_ss[NSn]; __device__ int g_off_ss[NSn]; __device__ int g_cur_ss[NSn];
__device__ int g_tmp_ss[NSn]; __device__ int g_part_ss[128];
__device__ int g_csr_ss[ESSmax];

// ------------------------------- helpers -----------------------------------
__device__ __forceinline__ void red4(float* p, float a, float b, float c, float d) {
    asm volatile("red.global.add.v4.f32 [%0], {%1,%2,%3,%4};"
                 :: "l"(p), "f"(a), "f"(b), "f"(c), "f"(d) : "memory");
}
__device__ __forceinline__ void red4v(float* p, float4 v) { red4(p, v.x, v.y, v.z, v.w); }

// ------------------------------ CSR build ----------------------------------
__global__ void k_count_i(const int* __restrict__ ei, int* __restrict__ deg, int E) {
    int e = blockIdx.x * blockDim.x + threadIdx.x;
    if (e >= E) return;
    atomicAdd(deg + ei[E + e], 1);
}

__global__ void k_scan1(const int* __restrict__ deg, int* __restrict__ incl,
                        int* __restrict__ part, int n) {
    __shared__ int sh[1024];
    int i = blockIdx.x * 1024 + threadIdx.x;
    int v = (i < n) ? deg[i] : 0;
    sh[threadIdx.x] = v;
    __syncthreads();
    for (int o = 1; o < 1024; o <<= 1) {
        int t = (threadIdx.x >= o) ? sh[threadIdx.x - o] : 0;
        __syncthreads();
        sh[threadIdx.x] += t;
        __syncthreads();
    }
    if (i < n) incl[i] = sh[threadIdx.x];
    if (threadIdx.x == 1023) part[blockIdx.x] = sh[1023];
}

__global__ void k_scan2(int* __restrict__ part, int nb) {
    __shared__ int sh[128];
    int v = (threadIdx.x < nb) ? part[threadIdx.x] : 0;
    sh[threadIdx.x] = v;
    __syncthreads();
    for (int o = 1; o < 128; o <<= 1) {
        int t = (threadIdx.x >= o) ? sh[threadIdx.x - o] : 0;
        __syncthreads();
        sh[threadIdx.x] += t;
        __syncthreads();
    }
    if (threadIdx.x < nb) part[threadIdx.x] = sh[threadIdx.x] - v;  // exclusive
}

__global__ void k_scan3(const int* __restrict__ deg, const int* __restrict__ incl,
                        const int* __restrict__ part, int* __restrict__ off,
                        int* __restrict__ cur, int n) {
    int i = blockIdx.x * blockDim.x + threadIdx.x;
    if (i >= n) return;
    int o = incl[i] - deg[i] + part[i >> 10];
    off[i] = o;
    cur[i] = o;
}

__global__ void k_fill_vv(const int* __restrict__ ei, const int* __restrict__ et, int E) {
    int e = blockIdx.x * blockDim.x + threadIdx.x;
    if (e >= E) return;
    int s = ei[e], d = ei[E + e], t = et[e];
    int slot = atomicAdd(g_cur_vv + d, 1);
    g_csr_vv[slot] = s | (t << 20);
}

__global__ void k_fill_ss(const int* __restrict__ ei, int E) {
    int e = blockIdx.x * blockDim.x + threadIdx.x;
    if (e >= E) return;
    int slot = atomicAdd(g_cur_ss + ei[E + e], 1);
    g_csr_ss[slot] = ei[e];
}

__global__ void k_dinv_v() {
    int v = blockIdx.x * blockDim.x + threadIdx.x;
    if (v >= NVn) return;
    int d = g_deg_vv[v];
    g_dinv_v[v] = (d > 0) ? rsqrtf((float)d) : 0.f;
}

__global__ void k_dinv_s() {
    int v = blockIdx.x * blockDim.x + threadIdx.x;
    if (v >= NSn) return;
    int d = g_deg_ss[v];
    g_dinv_s[v] = (d > 0) ? rsqrtf((float)d) : 0.f;
    g_sqd_s[v]  = sqrtf((float)d);
    g_cntf_s[v] = (float)d;
}

// ------------------------------ weight prep --------------------------------
__global__ void k_prep1(const float* __restrict__ W1_rel, const float* __restrict__ W1_root,
                        const float* __restrict__ b1,
                        const float* __restrict__ W12, const float* __restrict__ b12) {
    int t = blockIdx.x * blockDim.x + threadIdx.x;
    if (t < 64) g_c0[t] = b1[t] + b12[t];
    if (t >= 40 * 64) return;
    int i = t >> 6, c = t & 63;
    float w = 0.f;
    if (i < 5)        w = W1_root[i * 64 + c] + W12[i * 64 + c];
    else if (i < 20)  w = W1_rel[(i - 5) * 64 + c];
    else if (i < 35)  w = W12[(i - 15) * 64 + c];
    g_Wz[t] = w;
}

__global__ void k_prep2(const float* __restrict__ W3_rel, const float* __restrict__ W32_l,
                        const float* __restrict__ W4_l,  const float* __restrict__ W42_l) {
    int t = blockIdx.x * blockDim.x + threadIdx.x;
    if (t >= 4 * 41 * 64) return;
    int m = t / (41 * 64);
    int r = t % (41 * 64);
    int i = r >> 6, c = r & 63;
    const float* Wm = (m == 0) ? W3_rel : (m == 1) ? W32_l : (m == 2) ? W4_l : W42_l;
    float acc = 0.f;
    if (i < 40) {
        const float* zr = g_Wz + i * 64;
#pragma unroll 8
        for (int j = 0; j < 64; j++) acc += zr[j] * Wm[j * 64 + c];
        g_WzW[m][i * 64 + c] = acc;
    } else {
#pragma unroll 8
        for (int j = 0; j < 64; j++) acc += g_c0[j] * Wm[j * 64 + c];
        g_c0W[m][c] = acc;
    }
}

// --------------------------- game-graph kernels ----------------------------
__global__ void k_pad(const float* __restrict__ x) {
    int t = blockIdx.x * blockDim.x + threadIdx.x;
    if (t >= NVn * 8) return;
    int v = t >> 3, i = t & 7;
    float xv = (i < 5) ? x[v * 5 + i] : 0.f;
    g_xpad[t] = xv;
    if (i < 5) g_z[(size_t)v * 40 + i] = xv;
}

// RGCN per-rel means + TAG-game hop1 fused; zeros the z padding tail.
__global__ void k_rgcn_hop1(float* __restrict__ p1) {
    int gt = blockIdx.x * blockDim.x + threadIdx.x;
    int w = gt >> 5, lane = gt & 31;
    if (w >= NVn) return;
    int base = g_off_vv[w], deg = g_deg_vv[w];
    int sub = lane >> 3, li = lane & 7;
    float a0 = 0.f, a1 = 0.f, a2 = 0.f, ah = 0.f;
    float c0 = 0.f, c1 = 0.f, c2 = 0.f;
#pragma unroll 4
    for (int j = sub; j < deg; j += 4) {
        int pk = g_csr_vv[base + j];
        int s = pk & 0xFFFFF, t = pk >> 20;
        float xv = g_xpad[(size_t)s * 8 + li];
        ah += g_dinv_v[s] * xv;
        if (t == 0)      { a0 += xv; c0 += 1.f; }
        else if (t == 1) { a1 += xv; c1 += 1.f; }
        else             { a2 += xv; c2 += 1.f; }
    }
#pragma unroll
    for (int o = 8; o < 32; o <<= 1) {
        a0 += __shfl_xor_sync(0xffffffffu, a0, o);
        a1 += __shfl_xor_sync(0xffffffffu, a1, o);
        a2 += __shfl_xor_sync(0xffffffffu, a2, o);
        ah += __shfl_xor_sync(0xffffffffu, ah, o);
        c0 += __shfl_xor_sync(0xffffffffu, c0, o);
        c1 += __shfl_xor_sync(0xffffffffu, c1, o);
        c2 += __shfl_xor_sync(0xffffffffu, c2, o);
    }
    if (sub == 0) {
        float dvd = g_dinv_v[w];
        float h1 = dvd * ah;
        if (li < 5) {
            float* zz = g_z + (size_t)w * 40;
            zz[5 + li]  = a0 / fmaxf(c0, 1.f);
            zz[10 + li] = a1 / fmaxf(c1, 1.f);
            zz[15 + li] = a2 / fmaxf(c2, 1.f);
            zz[20 + li] = h1;
            zz[35 + li] = 0.f;          // padding read by float4 scatters
        }
        p1[(size_t)w * 8 + li] = dvd * h1;
    }
}

// TAG-game hop k (1,2): h = dinv_d * sum(p_prev[src]); write z slice (+p_next).
__global__ void k_hop8_gather(const float* __restrict__ pprev, float* __restrict__ pnext,
                              int k, int write_p) {
    int gt = blockIdx.x * blockDim.x + threadIdx.x;
    int w = gt >> 5, lane = gt & 31;
    if (w >= NVn) return;
    int base = g_off_vv[w], deg = g_deg_vv[w];
    int sub = lane >> 3, li = lane & 7;
    float acc = 0.f;
#pragma unroll 4
    for (int j = sub; j < deg; j += 4) {
        int s = g_csr_vv[base + j] & 0xFFFFF;
        acc += pprev[(size_t)s * 8 + li];
    }
#pragma unroll
    for (int o = 8; o < 32; o <<= 1)
        acc += __shfl_xor_sync(0xffffffffu, acc, o);
    if (sub == 0) {
        float dv = g_dinv_v[w];
        float h = dv * acc;
        if (li < 5) g_z[(size_t)w * 40 + 20 + k * 5 + li] = h;
        if (write_p) pnext[(size_t)w * 8 + li] = dv * h;
    }
}

// --------------------------- v->s atomic scatters --------------------------
__global__ void k_scatter_h(const int* __restrict__ ei, const float* __restrict__ ew, int E) {
    int gt = blockIdx.x * blockDim.x + threadIdx.x;
    int warp = gt >> 5, lane = gt & 31;
    int sub = lane >> 4, li = lane & 15;
    int e = warp * 2 + sub;
    if (e >= E) return;
    int s = 0, d = 0; float wt = 0.f;
    if (li == 0) { s = ei[e]; d = ei[E + e]; wt = ew[e]; }
    s  = __shfl_sync(0xffffffffu, s, 0, 16);
    d  = __shfl_sync(0xffffffffu, d, 0, 16);
    wt = __shfl_sync(0xffffffffu, wt, 0, 16);
    if (li < 10) {
        float4 v = ((const float4*)(g_z + (size_t)s * 40))[li];
        float* pw = g_aggw + (size_t)d * 40 + li * 4;
        float* pu = g_aggu + (size_t)d * 40 + li * 4;
        red4(pw, wt * v.x, wt * v.y, wt * v.z, wt * v.w);
        red4v(pu, v);
    } else if (li == 10) {
        atomicAdd(g_cnt_h + d, 1.f);
    } else if (li == 11) {
        atomicAdd(g_wsum_h + d, wt);
    }
}

__global__ void k_scatter_in(const int* __restrict__ ei, int E) {
    int gt = blockIdx.x * blockDim.x + threadIdx.x;
    int warp = gt >> 5, lane = gt & 31;
    int sub = lane >> 4, li = lane & 15;
    int e = warp * 2 + sub;
    if (e >= E) return;
    int s = 0, d = 0;
    if (li == 0) { s = ei[e]; d = ei[E + e]; }
    s = __shfl_sync(0xffffffffu, s, 0, 16);
    d = __shfl_sync(0xffffffffu, d, 0, 16);
    if (li < 10) {
        float4 v = ((const float4*)(g_z + (size_t)s * 40))[li];
        red4v(g_aggin + (size_t)d * 40 + li * 4, v);
    } else if (li == 10) {
        atomicAdd(g_cnt_in + d, 1.f);
    }
}

// --------------- fused state dense chain (layers 2-5), 4 nodes/block -------
__global__ void __launch_bounds__(256) k_state_dense(
        const float* __restrict__ state_x, const float* __restrict__ W3_root,
        const float* __restrict__ b3, const float* __restrict__ W32_r,
        const float* __restrict__ b32, const float* __restrict__ W4_r,
        const float* __restrict__ b4, const float* __restrict__ W42_r,
        const float* __restrict__ b42) {
    __shared__ float s_aggw[4][35];
    __shared__ float s_aggu[4][35];
    __shared__ float s_aggin[4][35];
    __shared__ float s_sx[2][4][64];
    int tid = threadIdx.x;
    int n = tid >> 6, c = tid & 63;
    int v = blockIdx.x * 4 + n;

    if (c < 35) {
        s_aggw[n][c]  = g_aggw [(size_t)v * 40 + c];
        s_aggu[n][c]  = g_aggu [(size_t)v * 40 + c];
        s_aggin[n][c] = g_aggin[(size_t)v * 40 + c];
    }
    __syncthreads();

    float ch = g_cnt_h[v], ci = g_cnt_in[v], ws = g_wsum_h[v];

    // L2: graph_conv
    {
        float acc = b3[c] + ws * g_c0W[0][c];
        const float* W = g_WzW[0];
#pragma unroll 7
        for (int i = 0; i < 35; i++) acc += s_aggw[n][i] * W[i * 64 + c];
        const float* xv = state_x + (size_t)v * 5;
#pragma unroll
        for (int j = 0; j < 5; j++) acc += xv[j] * W3_root[j * 64 + c];
        s_sx[0][n][c] = fmaxf(acc, 0.f);
    }
    __syncthreads();
    // L3: conv32 (mean over ei_h)
    {
        float inv = 1.f / fmaxf(ch, 1.f);
        const float* W = g_WzW[1];
        float sa = 0.f;
#pragma unroll 7
        for (int i = 0; i < 35; i++) sa += s_aggu[n][i] * W[i * 64 + c];
        float acc = b32[c] + sa * inv + ((ch > 0.f) ? g_c0W[1][c] : 0.f);
#pragma unroll 8
        for (int j = 0; j < 64; j++) acc += s_sx[0][n][j] * W32_r[j * 64 + c];
        s_sx[1][n][c] = fmaxf(acc, 0.f);
    }
    __syncthreads();
    // L4: conv4 (mean over ei_in)
    {
        float inv = 1.f / fmaxf(ci, 1.f);
        const float* W = g_WzW[2];
        float sa = 0.f;
#pragma unroll 7
        for (int i = 0; i < 35; i++) sa += s_aggin[n][i] * W[i * 64 + c];
        float acc = b4[c] + sa * inv + ((ci > 0.f) ? g_c0W[2][c] : 0.f);
#pragma unroll 8
        for (int j = 0; j < 64; j++) acc += s_sx[1][n][j] * W4_r[j * 64 + c];
        s_sx[0][n][c] = fmaxf(acc, 0.f);
    }
    __syncthreads();
    // L5: conv42
    {
        float inv = 1.f / fmaxf(ci, 1.f);
        const float* W = g_WzW[3];
        float sa = 0.f;
#pragma unroll 7
        for (int i = 0; i < 35; i++) sa += s_aggin[n][i] * W[i * 64 + c];
        float acc = b42[c] + sa * inv + ((ci > 0.f) ? g_c0W[3][c] : 0.f);
#pragma unroll 8
        for (int j = 0; j < 64; j++) acc += s_sx[0][n][j] * W42_r[j * 64 + c];
        float sx5 = fmaxf(acc, 0.f);
        g_sx5[(size_t)v * 64 + c] = sx5;
        g_pin[(size_t)v * 64 + c] = g_dinv_s[v] * sx5;
    }
}

// --- TAG-state hop, p-form: p_next = dinv^2 * sum(p_prev[src]).
// warp/node, 2 edges in flight (16-lane subgroups, float4 lanes), unrolled.
__global__ void k_hop64p(const float* __restrict__ pprev, float* __restrict__ pnext) {
    int gt = blockIdx.x * blockDim.x + threadIdx.x;
    int w = gt >> 5, lane = gt & 31;
    if (w >= NSn) return;
    int base = g_off_ss[w], deg = g_deg_ss[w];
    int sub = lane >> 4, li = lane & 15;
    float4 a = make_float4(0.f, 0.f, 0.f, 0.f);
    int j0 = 0;
    for (; j0 + 32 <= deg; j0 += 32) {
        int sl = g_csr_ss[base + j0 + lane];
#pragma unroll
        for (int jj = 0; jj < 16; jj++) {
            int s = __shfl_sync(0xffffffffu, sl, 2 * jj + sub);
            float4 v = ((const float4*)(pprev + (size_t)s * 64))[li];
            a.x += v.x; a.y += v.y; a.z += v.z; a.w += v.w;
        }
    }
    {   // tail
        int rem = deg - j0;
        int sl = (j0 + lane < deg) ? g_csr_ss[base + j0 + lane] : 0;
        for (int jj = 0; jj < 16; jj++) {
            int ei2 = 2 * jj + sub;
            if (ei2 < rem) {
                int s = __shfl_sync(0xffffffffu, sl, ei2);
                float4 v = ((const float4*)(pprev + (size_t)s * 64))[li];
                a.x += v.x; a.y += v.y; a.z += v.z; a.w += v.w;
            } else {
                __shfl_sync(0xffffffffu, sl, ei2 & 31);
            }
        }
    }
    a.x += __shfl_xor_sync(0xffffffffu, a.x, 16);
    a.y += __shfl_xor_sync(0xffffffffu, a.y, 16);
    a.z += __shfl_xor_sync(0xffffffffu, a.z, 16);
    a.w += __shfl_xor_sync(0xffffffffu, a.w, 16);
    if (sub == 0) {
        float dv = g_dinv_s[w];
        float dv2 = dv * dv;
        float4 o = make_float4(dv2 * a.x, dv2 * a.y, dv2 * a.z, dv2 * a.w);
        ((float4*)(pnext + (size_t)w * 64))[li] = o;
    }
}

// conv5 sum gather (same structure, no scaling).
__global__ void k_sum64_gather(const float* __restrict__ feat, float* __restrict__ acc) {
    int gt = blockIdx.x * blockDim.x + threadIdx.x;
    int w = gt >> 5, lane = gt & 31;
    if (w >= NSn) return;
    int base = g_off_ss[w], deg = g_deg_ss[w];
    int sub = lane >> 4, li = lane & 15;
    float4 a = make_float4(0.f, 0.f, 0.f, 0.f);
    int j0 = 0;
    for (; j0 + 32 <= deg; j0 += 32) {
        int sl = g_csr_ss[base + j0 + lane];
#pragma unroll
        for (int jj = 0; jj < 16; jj++) {
            int s = __shfl_sync(0xffffffffu, sl, 2 * jj + sub);
            float4 v = ((const float4*)(feat + (size_t)s * 64))[li];
            a.x += v.x; a.y += v.y; a.z += v.z; a.w += v.w;
        }
    }
    {
        int rem = deg - j0;
        int sl = (j0 + lane < deg) ? g_csr_ss[base + j0 + lane] : 0;
        for (int jj = 0; jj < 16; jj++) {
            int ei2 = 2 * jj + sub;
            if (ei2 < rem) {
                int s = __shfl_sync(0xffffffffu, sl, ei2);
                float4 v = ((const float4*)(feat + (size_t)s * 64))[li];
                a.x += v.x; a.y += v.y; a.z += v.z; a.w += v.w;
            } else {
                __shfl_sync(0xffffffffu, sl, ei2 & 31);
            }
        }
    }
    a.x += __shfl_xor_sync(0xffffffffu, a.x, 16);
    a.y += __shfl_xor_sync(0xffffffffu, a.y, 16);
    a.z += __shfl_xor_sync(0xffffffffu, a.z, 16);
    a.w += __shfl_xor_sync(0xffffffffu, a.w, 16);
    if (sub == 0)
        ((float4*)(acc + (size_t)w * 64))[li] = a;
}

// TAG-state out: relu(b2 + sx5@W2_0 + sqrt(deg) * sum_k p_k@W2_{k+1})
__global__ void k_tag_out(const float* __restrict__ W2, const float* __restrict__ b2) {
    int t = blockIdx.x * blockDim.x + threadIdx.x;
    int v = t >> 6, c = t & 63;
    if (v >= NSn) return;
    float acc = b2[c];
    const float* s0 = g_sx5 + (size_t)v * 64;
#pragma unroll 8
    for (int j = 0; j < 64; j++) acc += s0[j] * W2[j * 64 + c];
    float h = 0.f;
#pragma unroll
    for (int k = 0; k < 3; k++) {
        const float* pk = g_pk[k] + (size_t)v * 64;
        const float* wk = W2 + (size_t)(k + 1) * 4096;
#pragma unroll 8
        for (int j = 0; j < 64; j++) h += pk[j] * wk[j * 64 + c];
    }
    acc += g_sqd_s[v] * h;
    g_sx6[(size_t)v * 64 + c] = fmaxf(acc, 0.f);
}

// conv5 SAGE + linear head, fused.
__global__ void __launch_bounds__(256) k_conv5_final(
        const float* __restrict__ W5_l, const float* __restrict__ W5_r,
        const float* __restrict__ b5, const float* __restrict__ Wl,
        const float* __restrict__ bl, float* __restrict__ out) {
    __shared__ float s7[4][64];
    int tid = threadIdx.x;
    int n = tid >> 6, c = tid & 63;
    int v = blockIdx.x * 4 + n;
    float inv = 1.f / fmaxf(g_cntf_s[v], 1.f);
    const float* av = g_accs5 + (size_t)v * 64;
    float sa = 0.f;
#pragma unroll 8
    for (int j = 0; j < 64; j++) sa += av[j] * W5_l[j * 64 + c];
    float acc = b5[c] + sa * inv;
    const float* xv = g_sx6 + (size_t)v * 64;
#pragma unroll 8
    for (int j = 0; j < 64; j++) acc += xv[j] * W5_r[j * 64 + c];
    s7[n][c] = fmaxf(acc, 0.f);
    __syncthreads();
    if (c < 8) {
        float o = bl[c];
#pragma unroll 8
        for (int j = 0; j < 64; j++) o += s7[n][j] * Wl[j * 8 + c];
        out[(size_t)v * 8 + c] = o;
    }
}

// ------------------------------- launch ------------------------------------

extern "C" void kernel_launch(void* const* d_in, const int* in_sizes, int n_in,
                              void* d_out, int out_size) {
    const float* game_x  = (const float*)d_in[0];
    const float* state_x = (const float*)d_in[1];
    const int*   ei_vv   = (const int*)d_in[2];
    const int*   et_vv   = (const int*)d_in[3];
    const int*   ei_h    = (const int*)d_in[4];
    const float* ew_h    = (const float*)d_in[5];
    const int*   ei_in   = (const int*)d_in[6];
    const int*   ei_ss   = (const int*)d_in[7];
    const float* W1_rel  = (const float*)d_in[8];
    const float* W1_root = (const float*)d_in[9];
    const float* b1      = (const float*)d_in[10];
    const float* W12     = (const float*)d_in[11];
    const float* b12     = (const float*)d_in[12];
    const float* W2      = (const float*)d_in[13];
    const float* b2      = (const float*)d_in[14];
    const float* W3_rel  = (const float*)d_in[15];
    const float* W3_root = (const float*)d_in[16];
    const float* b3      = (const float*)d_in[17];
    const float* W32_l   = (const float*)d_in[18];
    const float* W32_r   = (const float*)d_in[19];
    const float* b32     = (const float*)d_in[20];
    const float* W4_l    = (const float*)d_in[21];
    const float* W4_r    = (const float*)d_in[22];
    const float* b4      = (const float*)d_in[23];
    const float* W42_l   = (const float*)d_in[24];
    const float* W42_r   = (const float*)d_in[25];
    const float* b42     = (const float*)d_in[26];
    const float* W5_l    = (const float*)d_in[27];
    const float* W5_r    = (const float*)d_in[28];
    const float* b5      = (const float*)d_in[29];
    const float* Wl      = (const float*)d_in[30];
    const float* bl      = (const float*)d_in[31];
    float* out = (float*)d_out;

    int Evv = in_sizes[2] / 2;
    int Eh  = in_sizes[4] / 2;
    int Ein = in_sizes[6] / 2;
    int Ess = in_sizes[7] / 2;

    // symbol addresses
    int *pi_deg_vv, *pi_tmp_vv, *pi_part_vv, *pi_off_vv, *pi_cur_vv;
    int *pi_deg_ss, *pi_tmp_ss, *pi_part_ss, *pi_off_ss, *pi_cur_ss;
    float *p_pv, *p_pin, *p_pk, *p_sx6, *p_accs5;
    float *p_aggw, *p_aggu, *p_cnt_h, *p_wsum_h, *p_aggin, *p_cnt_in;
    cudaGetSymbolAddress((void**)&pi_deg_vv, g_deg_vv);
    cudaGetSymbolAddress((void**)&pi_tmp_vv, g_tmp_vv);
    cudaGetSymbolAddress((void**)&pi_part_vv,g_part_vv);
    cudaGetSymbolAddress((void**)&pi_off_vv, g_off_vv);
    cudaGetSymbolAddress((void**)&pi_cur_vv, g_cur_vv);
    cudaGetSymbolAddress((void**)&pi_deg_ss, g_deg_ss);
    cudaGetSymbolAddress((void**)&pi_tmp_ss, g_tmp_ss);
    cudaGetSymbolAddress((void**)&pi_part_ss,g_part_ss);
    cudaGetSymbolAddress((void**)&pi_off_ss, g_off_ss);
    cudaGetSymbolAddress((void**)&pi_cur_ss, g_cur_ss);
    cudaGetSymbolAddress((void**)&p_pv,     g_pv);
    cudaGetSymbolAddress((void**)&p_pin,    g_pin);
    cudaGetSymbolAddress((void**)&p_pk,     g_pk);
    cudaGetSymbolAddress((void**)&p_sx6,    g_sx6);
    cudaGetSymbolAddress((void**)&p_accs5,  g_accs5);
    cudaGetSymbolAddress((void**)&p_aggw,   g_aggw);
    cudaGetSymbolAddress((void**)&p_aggu,   g_aggu);
    cudaGetSymbolAddress((void**)&p_cnt_h,  g_cnt_h);
    cudaGetSymbolAddress((void**)&p_wsum_h, g_wsum_h);
    cudaGetSymbolAddress((void**)&p_aggin,  g_aggin);
    cudaGetSymbolAddress((void**)&p_cnt_in, g_cnt_in);

    float* p_pv0 = p_pv;
    float* p_pv1 = p_pv + (size_t)NVn * 8;
    float* p_pk0 = p_pk;
    float* p_pk1 = p_pk + (size_t)NSn * 64;
    float* p_pk2 = p_pk1 + (size_t)NSn * 64;

    const int T = 256;
    auto nb = [](long n, int t) { return (int)((n + t - 1) / t); };
    auto wb = [](long edges, int t) {
        long warps = (edges + 1) / 2;
        return (int)((warps * 32 + t - 1) / t);
    };
    int nbv_warp = nb((long)NVn * 32, T);
    int nbs_warp = nb((long)NSn * 32, T);

    // 0) zero accumulators + degree arrays
    cudaMemsetAsync(p_aggw,   0, (size_t)NSn * 40 * 4, 0);
    cudaMemsetAsync(p_aggu,   0, (size_t)NSn * 40 * 4, 0);
    cudaMemsetAsync(p_cnt_h,  0, (size_t)NSn * 4, 0);
    cudaMemsetAsync(p_wsum_h, 0, (size_t)NSn * 4, 0);
    cudaMemsetAsync(p_aggin,  0, (size_t)NSn * 40 * 4, 0);
    cudaMemsetAsync(p_cnt_in, 0, (size_t)NSn * 4, 0);
    cudaMemsetAsync(pi_deg_vv, 0, (size_t)NVn * 4, 0);
    cudaMemsetAsync(pi_deg_ss, 0, (size_t)NSn * 4, 0);

    // 1) weight prep
    k_prep1<<<nb(40 * 64, T), T>>>(W1_rel, W1_root, b1, W12, b12);
    k_prep2<<<nb(4 * 41 * 64, T), T>>>(W3_rel, W32_l, W4_l, W42_l);

    // 2) CSR builds (vv, ss)
    k_count_i<<<nb(Evv, T), T>>>(ei_vv, pi_deg_vv, Evv);
    k_scan1<<<nb(NVn, 1024), 1024>>>(pi_deg_vv, pi_tmp_vv, pi_part_vv, NVn);
    k_scan2<<<1, 128>>>(pi_part_vv, nb(NVn, 1024));
    k_scan3<<<nb(NVn, T), T>>>(pi_deg_vv, pi_tmp_vv, pi_part_vv, pi_off_vv, pi_cur_vv, NVn);
    k_fill_vv<<<nb(Evv, T), T>>>(ei_vv, et_vv, Evv);
    k_dinv_v<<<nb(NVn, T), T>>>();

    k_count_i<<<nb(Ess, T), T>>>(ei_ss, pi_deg_ss, Ess);
    k_scan1<<<nb(NSn, 1024), 1024>>>(pi_deg_ss, pi_tmp_ss, pi_part_ss, NSn);
    k_scan2<<<1, 128>>>(pi_part_ss, nb(NSn, 1024));
    k_scan3<<<nb(NSn, T), T>>>(pi_deg_ss, pi_tmp_ss, pi_part_ss, pi_off_ss, pi_cur_ss, NSn);
    k_fill_ss<<<nb(Ess, T), T>>>(ei_ss, Ess);
    k_dinv_s<<<nb(NSn, T), T>>>();

    // 3) game graph -> z
    k_pad<<<nb((long)NVn * 8, T), T>>>(game_x);
    k_rgcn_hop1<<<nbv_warp, T>>>(p_pv0);
    k_hop8_gather<<<nbv_warp, T>>>(p_pv0, p_pv1, 1, 1);
    k_hop8_gather<<<nbv_warp, T>>>(p_pv1, p_pv0, 2, 0);

    // 4) v->s z-space scatters (atomic, proven)
    k_scatter_h<<<wb(Eh, T), T>>>(ei_h, ew_h, Eh);
    k_scatter_in<<<wb(Ein, T), T>>>(ei_in, Ein);

    // 5) fused state dense chain -> sx5, pin
    k_state_dense<<<NSn / 4, 256>>>(state_x, W3_root, b3, W32_r, b32, W4_r, b4, W42_r, b42);

    // 6) TAG-state hops (p-form) + output
    k_hop64p<<<nbs_warp, T>>>(p_pin, p_pk0);
    k_hop64p<<<nbs_warp, T>>>(p_pk0, p_pk1);
    k_hop64p<<<nbs_warp, T>>>(p_pk1, p_pk2);
    k_tag_out<<<nb((long)NSn * 64, T), T>>>(W2, b2);

    // 7) conv5 + head
    k_sum64_gather<<<nbs_warp, T>>>(p_sx6, p_accs5);
    k_conv5_final<<<NSn / 4, 256>>>(W5_l, W5_r, b5, Wl, bl, out);
}

// round 8
// speedup vs baseline: 1.6683x; 1.6683x over previous
#include <cuda_runtime.h>
#include <math.h>

// ---------------------------------------------------------------------------
// StateModelEncoder — round 6: unified CSR build for all 4 edge sets, zero
// feature atomics (all gathers), mega-fused state chain, ~19 launches total.
// ---------------------------------------------------------------------------

#define NVn 100000
#define NSn 50000
#define EVVmax 1600000
#define ESSmax 800000
#define EHmax  800000
#define EINmax 800000
#define NDEG   (NVn + 3 * NSn)          // concatenated degree space
#define ETOT   (EVVmax + ESSmax + EHmax + EINmax)

// ------------------------- scratch (device globals) ------------------------
__device__ __align__(16) float g_xpad[NVn * 8];
__device__ float g_dinv_v[NVn];
__device__ __align__(16) float g_z[NVn * 40];          // [x5|rgcn15|hops15|0 pad5]
__device__ __align__(16) float g_pv[2][NVn * 8];
__device__ __align__(16) float g_WzW[4][40 * 64];
__device__ float g_c0W[4][64];
__device__ __align__(16) float g_sx5[NSn * 64];
__device__ __align__(16) float g_pin[NSn * 64];
__device__ __align__(16) float g_pk[3][NSn * 64];
__device__ __align__(16) float g_sx6[NSn * 64];
__device__ __align__(16) float g_accs5[NSn * 64];
__device__ float g_dinv_s[NSn];
__device__ float g_sqd_s[NSn];
__device__ float g_cntf_s[NSn];

// unified CSR
__device__ int g_deg_all[NDEG];
__device__ int g_incl_all[NDEG];
__device__ int g_off_all[NDEG];
__device__ int g_cur_all[NDEG];
__device__ int g_part[256];
__device__ int g_csr_all[ETOT];     // vv segment packs src | (etype<<20)
__device__ float g_csrw[EHmax];     // weights for ei_h segment (index - whbase)

// ------------------------------ CSR build ----------------------------------
__global__ void k_count_all(const int* __restrict__ ei_vv, const int* __restrict__ ei_ss,
                            const int* __restrict__ ei_h,  const int* __restrict__ ei_in,
                            int Evv, int Ess, int Eh, int Ein) {
    int t = blockIdx.x * blockDim.x + threadIdx.x;
    if (t < Evv) { atomicAdd(g_deg_all + ei_vv[Evv + t], 1); return; }
    t -= Evv;
    if (t < Ess) { atomicAdd(g_deg_all + NVn + ei_ss[Ess + t], 1); return; }
    t -= Ess;
    if (t < Eh)  { atomicAdd(g_deg_all + NVn + NSn + ei_h[Eh + t], 1); return; }
    t -= Eh;
    if (t < Ein) { atomicAdd(g_deg_all + NVn + 2 * NSn + ei_in[Ein + t], 1); }
}

__global__ void k_scan1(int n) {
    __shared__ int sh[1024];
    int i = blockIdx.x * 1024 + threadIdx.x;
    int v = (i < n) ? g_deg_all[i] : 0;
    sh[threadIdx.x] = v;
    __syncthreads();
    for (int o = 1; o < 1024; o <<= 1) {
        int t = (threadIdx.x >= o) ? sh[threadIdx.x - o] : 0;
        __syncthreads();
        sh[threadIdx.x] += t;
        __syncthreads();
    }
    if (i < n) g_incl_all[i] = sh[threadIdx.x];
    if (threadIdx.x == 1023) g_part[blockIdx.x] = sh[1023];
}

__global__ void k_scan2(int nb) {
    __shared__ int sh[256];
    int v = (threadIdx.x < nb) ? g_part[threadIdx.x] : 0;
    sh[threadIdx.x] = v;
    __syncthreads();
    for (int o = 1; o < 256; o <<= 1) {
        int t = (threadIdx.x >= o) ? sh[threadIdx.x - o] : 0;
        __syncthreads();
        sh[threadIdx.x] += t;
        __syncthreads();
    }
    if (threadIdx.x < nb) g_part[threadIdx.x] = sh[threadIdx.x] - v;  // exclusive
}

__global__ void k_scan3(int n) {
    int i = blockIdx.x * blockDim.x + threadIdx.x;
    if (i >= n) return;
    int o = g_incl_all[i] - g_deg_all[i] + g_part[i >> 10];
    g_off_all[i] = o;
    g_cur_all[i] = o;
}

__global__ void k_fill_all(const int* __restrict__ ei_vv, const int* __restrict__ et_vv,
                           const int* __restrict__ ei_ss, const int* __restrict__ ei_h,
                           const float* __restrict__ ew_h, const int* __restrict__ ei_in,
                           int Evv, int Ess, int Eh, int Ein) {
    int t = blockIdx.x * blockDim.x + threadIdx.x;
    if (t < Evv) {
        int slot = atomicAdd(g_cur_all + ei_vv[Evv + t], 1);
        g_csr_all[slot] = ei_vv[t] | (et_vv[t] << 20);
        return;
    }
    t -= Evv;
    if (t < Ess) {
        int slot = atomicAdd(g_cur_all + NVn + ei_ss[Ess + t], 1);
        g_csr_all[slot] = ei_ss[t];
        return;
    }
    t -= Ess;
    if (t < Eh) {
        int slot = atomicAdd(g_cur_all + NVn + NSn + ei_h[Eh + t], 1);
        g_csr_all[slot] = ei_h[t];
        g_csrw[slot - (Evv + Ess)] = ew_h[t];
        return;
    }
    t -= Eh;
    if (t < Ein) {
        int slot = atomicAdd(g_cur_all + NVn + 2 * NSn + ei_in[Ein + t], 1);
        g_csr_all[slot] = ei_in[t];
    }
}

// pad game_x (8-wide + z cols 0..4) and compute dinv_v / dinv_s / sqd / cnt.
__global__ void k_pad_dinv(const float* __restrict__ x) {
    int t = blockIdx.x * blockDim.x + threadIdx.x;
    if (t < NVn * 8) {
        int v = t >> 3, i = t & 7;
        float xv = (i < 5) ? x[v * 5 + i] : 0.f;
        g_xpad[t] = xv;
        if (i < 5) g_z[(size_t)v * 40 + i] = xv;
    }
    if (t < NVn) {
        int d = g_deg_all[t];
        g_dinv_v[t] = (d > 0) ? rsqrtf((float)d) : 0.f;
    }
    if (t < NSn) {
        int d = g_deg_all[NVn + t];
        g_dinv_s[t] = (d > 0) ? rsqrtf((float)d) : 0.f;
        g_sqd_s[t]  = sqrtf((float)d);
        g_cntf_s[t] = (float)d;
    }
}

// ------------------------------ weight prep --------------------------------
// Computes WzW[m] = Wz @ Wm and c0W[m] = c0 @ Wm, recomputing Wz/c0 inline.
__global__ void k_prep(const float* __restrict__ W1_rel, const float* __restrict__ W1_root,
                       const float* __restrict__ b1,
                       const float* __restrict__ W12, const float* __restrict__ b12,
                       const float* __restrict__ W3_rel, const float* __restrict__ W32_l,
                       const float* __restrict__ W4_l,  const float* __restrict__ W42_l) {
    int t = blockIdx.x * blockDim.x + threadIdx.x;
    if (t >= 4 * 41 * 64) return;
    int m = t / (41 * 64);
    int r = t % (41 * 64);
    int i = r >> 6, c = r & 63;
    const float* Wm = (m == 0) ? W3_rel : (m == 1) ? W32_l : (m == 2) ? W4_l : W42_l;
    float acc = 0.f;
    if (i < 40) {
        if (i >= 35) return;   // padding rows: never read (z pad is zero anyway)
#pragma unroll 8
        for (int j = 0; j < 64; j++) {
            float wz;
            if (i < 5)       wz = W1_root[i * 64 + j] + W12[i * 64 + j];
            else if (i < 20) wz = W1_rel[(i - 5) * 64 + j];
            else             wz = W12[(i - 15) * 64 + j];
            acc += wz * Wm[j * 64 + c];
        }
        g_WzW[m][i * 64 + c] = acc;
    } else {
#pragma unroll 8
        for (int j = 0; j < 64; j++) acc += (b1[j] + b12[j]) * Wm[j * 64 + c];
        g_c0W[m][c] = acc;
    }
}

// --------------------------- game-graph kernels ----------------------------
// RGCN per-rel means + TAG-game hop1 fused; zeroes the z padding tail.
__global__ void k_rgcn_hop1(float* __restrict__ p1) {
    int gt = blockIdx.x * blockDim.x + threadIdx.x;
    int w = gt >> 5, lane = gt & 31;
    if (w >= NVn) return;
    int base = g_off_all[w], deg = g_deg_all[w];
    int sub = lane >> 3, li = lane & 7;
    float a0 = 0.f, a1 = 0.f, a2 = 0.f, ah = 0.f;
    float c0 = 0.f, c1 = 0.f, c2 = 0.f;
#pragma unroll 4
    for (int j = sub; j < deg; j += 4) {
        int pk = g_csr_all[base + j];
        int s = pk & 0xFFFFF, t = pk >> 20;
        float xv = g_xpad[(size_t)s * 8 + li];
        ah += g_dinv_v[s] * xv;
        if (t == 0)      { a0 += xv; c0 += 1.f; }
        else if (t == 1) { a1 += xv; c1 += 1.f; }
        else             { a2 += xv; c2 += 1.f; }
    }
#pragma unroll
    for (int o = 8; o < 32; o <<= 1) {
        a0 += __shfl_xor_sync(0xffffffffu, a0, o);
        a1 += __shfl_xor_sync(0xffffffffu, a1, o);
        a2 += __shfl_xor_sync(0xffffffffu, a2, o);
        ah += __shfl_xor_sync(0xffffffffu, ah, o);
        c0 += __shfl_xor_sync(0xffffffffu, c0, o);
        c1 += __shfl_xor_sync(0xffffffffu, c1, o);
        c2 += __shfl_xor_sync(0xffffffffu, c2, o);
    }
    if (sub == 0) {
        float dvd = g_dinv_v[w];
        float h1 = dvd * ah;
        if (li < 5) {
            float* zz = g_z + (size_t)w * 40;
            zz[5 + li]  = a0 / fmaxf(c0, 1.f);
            zz[10 + li] = a1 / fmaxf(c1, 1.f);
            zz[15 + li] = a2 / fmaxf(c2, 1.f);
            zz[20 + li] = h1;
            zz[35 + li] = 0.f;          // padding read by float4 gathers
        }
        p1[(size_t)w * 8 + li] = dvd * h1;
    }
}

// TAG-game hop k (1,2): h = dinv_d * sum(p_prev[src]); write z slice (+p_next).
__global__ void k_hop8_gather(const float* __restrict__ pprev, float* __restrict__ pnext,
                              int k, int write_p) {
    int gt = blockIdx.x * blockDim.x + threadIdx.x;
    int w = gt >> 5, lane = gt & 31;
    if (w >= NVn) return;
    int base = g_off_all[w], deg = g_deg_all[w];
    int sub = lane >> 3, li = lane & 7;
    float acc = 0.f;
#pragma unroll 4
    for (int j = sub; j < deg; j += 4) {
        int s = g_csr_all[base + j] & 0xFFFFF;
        acc += pprev[(size_t)s * 8 + li];
    }
#pragma unroll
    for (int o = 8; o < 32; o <<= 1)
        acc += __shfl_xor_sync(0xffffffffu, acc, o);
    if (sub == 0) {
        float dv = g_dinv_v[w];
        float h = dv * acc;
        if (li < 5) g_z[(size_t)w * 40 + 20 + k * 5 + li] = h;
        if (write_p) pnext[(size_t)w * 8 + li] = dv * h;
    }
}

// -------- mega kernel: ei_h + ei_in z-gathers and state layers 2-5 ---------
// 4 nodes/block. Warps 0-3: ei_h gather for node (warp). Warps 4-7: ei_in.
// Gather: 2 edges in flight per warp (16-lane subgroups, float4 chunk/lane).
__global__ void __launch_bounds__(256) k_state_mega(
        const float* __restrict__ state_x, const float* __restrict__ W3_root,
        const float* __restrict__ b3, const float* __restrict__ W32_r,
        const float* __restrict__ b32, const float* __restrict__ W4_r,
        const float* __restrict__ b4, const float* __restrict__ W42_r,
        const float* __restrict__ b42, int whbase) {
    __shared__ float4 s_aggw4[4][10];
    __shared__ float4 s_aggu4[4][10];
    __shared__ float4 s_aggin4[4][10];
    __shared__ float s_wsum[4];
    __shared__ float s_sx[2][4][64];
    int tid = threadIdx.x;
    int warp = tid >> 5, lane = tid & 31;
    int sub = lane >> 4, li = lane & 15;
    int vbase = blockIdx.x * 4;

    {
        int n = warp & 3;
        int v = vbase + n;
        if (warp < 4) {   // ei_h: weighted + unweighted sums + weight-sum
            int base = g_off_all[NVn + NSn + v], deg = g_deg_all[NVn + NSn + v];
            float4 aW = make_float4(0.f, 0.f, 0.f, 0.f);
            float4 aU = make_float4(0.f, 0.f, 0.f, 0.f);
            float wsum = 0.f;
            for (int j0 = 0; j0 < deg; j0 += 32) {
                int idx = j0 + lane;
                int sl = 0; float wl = 0.f;
                if (idx < deg) { sl = g_csr_all[base + idx]; wl = g_csrw[base + idx - whbase]; }
                wsum += wl;
                int mres = deg - j0; if (mres > 32) mres = 32;
#pragma unroll
                for (int jj = 0; jj < 16; jj++) {
                    int e2 = 2 * jj + sub;
                    int s = __shfl_sync(0xffffffffu, sl, e2);
                    float wt = __shfl_sync(0xffffffffu, wl, e2);
                    if (e2 < mres && li < 10) {
                        float4 t = ((const float4*)(g_z + (size_t)s * 40))[li];
                        aU.x += t.x; aU.y += t.y; aU.z += t.z; aU.w += t.w;
                        aW.x += wt * t.x; aW.y += wt * t.y; aW.z += wt * t.z; aW.w += wt * t.w;
                    }
                }
            }
            aU.x += __shfl_xor_sync(0xffffffffu, aU.x, 16);
            aU.y += __shfl_xor_sync(0xffffffffu, aU.y, 16);
            aU.z += __shfl_xor_sync(0xffffffffu, aU.z, 16);
            aU.w += __shfl_xor_sync(0xffffffffu, aU.w, 16);
            aW.x += __shfl_xor_sync(0xffffffffu, aW.x, 16);
            aW.y += __shfl_xor_sync(0xffffffffu, aW.y, 16);
            aW.z += __shfl_xor_sync(0xffffffffu, aW.z, 16);
            aW.w += __shfl_xor_sync(0xffffffffu, aW.w, 16);
#pragma unroll
            for (int o = 16; o; o >>= 1) wsum += __shfl_xor_sync(0xffffffffu, wsum, o);
            if (sub == 0 && li < 10) { s_aggu4[n][li] = aU; s_aggw4[n][li] = aW; }
            if (lane == 0) s_wsum[n] = wsum;
        } else {          // ei_in: plain sum
            int base = g_off_all[NVn + 2 * NSn + v], deg = g_deg_all[NVn + 2 * NSn + v];
            float4 aU = make_float4(0.f, 0.f, 0.f, 0.f);
            for (int j0 = 0; j0 < deg; j0 += 32) {
                int idx = j0 + lane;
                int sl = (idx < deg) ? g_csr_all[base + idx] : 0;
                int mres = deg - j0; if (mres > 32) mres = 32;
#pragma unroll
                for (int jj = 0; jj < 16; jj++) {
                    int e2 = 2 * jj + sub;
                    int s = __shfl_sync(0xffffffffu, sl, e2);
                    if (e2 < mres && li < 10) {
                        float4 t = ((const float4*)(g_z + (size_t)s * 40))[li];
                        aU.x += t.x; aU.y += t.y; aU.z += t.z; aU.w += t.w;
                    }
                }
            }
            aU.x += __shfl_xor_sync(0xffffffffu, aU.x, 16);
            aU.y += __shfl_xor_sync(0xffffffffu, aU.y, 16);
            aU.z += __shfl_xor_sync(0xffffffffu, aU.z, 16);
            aU.w += __shfl_xor_sync(0xffffffffu, aU.w, 16);
            if (sub == 0 && li < 10) s_aggin4[n][li] = aU;
        }
    }
    __syncthreads();

    // dense phase: 64 threads per node
    int n = tid >> 6, c = tid & 63;
    int v = vbase + n;
    const float* s_aggw  = (const float*)s_aggw4[n];
    const float* s_aggu  = (const float*)s_aggu4[n];
    const float* s_aggin = (const float*)s_aggin4[n];
    float ch = (float)g_deg_all[NVn + NSn + v];
    float ci = (float)g_deg_all[NVn + 2 * NSn + v];

    // L2: graph_conv
    {
        float acc = b3[c] + s_wsum[n] * g_c0W[0][c];
        const float* W = g_WzW[0];
#pragma unroll 7
        for (int i = 0; i < 35; i++) acc += s_aggw[i] * W[i * 64 + c];
        const float* xv = state_x + (size_t)v * 5;
#pragma unroll
        for (int j = 0; j < 5; j++) acc += xv[j] * W3_root[j * 64 + c];
        s_sx[0][n][c] = fmaxf(acc, 0.f);
    }
    __syncthreads();
    // L3: conv32 (mean over ei_h)
    {
        float inv = 1.f / fmaxf(ch, 1.f);
        const float* W = g_WzW[1];
        float sa = 0.f;
#pragma unroll 7
        for (int i = 0; i < 35; i++) sa += s_aggu[i] * W[i * 64 + c];
        float acc = b32[c] + sa * inv + ((ch > 0.f) ? g_c0W[1][c] : 0.f);
#pragma unroll 8
        for (int j = 0; j < 64; j++) acc += s_sx[0][n][j] * W32_r[j * 64 + c];
        s_sx[1][n][c] = fmaxf(acc, 0.f);
    }
    __syncthreads();
    // L4: conv4 (mean over ei_in)
    {
        float inv = 1.f / fmaxf(ci, 1.f);
        const float* W = g_WzW[2];
        float sa = 0.f;
#pragma unroll 7
        for (int i = 0; i < 35; i++) sa += s_aggin[i] * W[i * 64 + c];
        float acc = b4[c] + sa * inv + ((ci > 0.f) ? g_c0W[2][c] : 0.f);
#pragma unroll 8
        for (int j = 0; j < 64; j++) acc += s_sx[1][n][j] * W4_r[j * 64 + c];
        s_sx[0][n][c] = fmaxf(acc, 0.f);
    }
    __syncthreads();
    // L5: conv42
    {
        float inv = 1.f / fmaxf(ci, 1.f);
        const float* W = g_WzW[3];
        float sa = 0.f;
#pragma unroll 7
        for (int i = 0; i < 35; i++) sa += s_aggin[i] * W[i * 64 + c];
        float acc = b42[c] + sa * inv + ((ci > 0.f) ? g_c0W[3][c] : 0.f);
#pragma unroll 8
        for (int j = 0; j < 64; j++) acc += s_sx[0][n][j] * W42_r[j * 64 + c];
        float sx5 = fmaxf(acc, 0.f);
        g_sx5[(size_t)v * 64 + c] = sx5;
        g_pin[(size_t)v * 64 + c] = g_dinv_s[v] * sx5;
    }
}

// TAG-state hop, p-form: p_next = dinv^2 * sum(p_prev[src]).
__global__ void k_hop64p(const float* __restrict__ pprev, float* __restrict__ pnext) {
    int gt = blockIdx.x * blockDim.x + threadIdx.x;
    int w = gt >> 5, lane = gt & 31;
    if (w >= NSn) return;
    int base = g_off_all[NVn + w], deg = g_deg_all[NVn + w];
    int sub = lane >> 4, li = lane & 15;
    float4 a = make_float4(0.f, 0.f, 0.f, 0.f);
    for (int j0 = 0; j0 < deg; j0 += 32) {
        int idx = j0 + lane;
        int sl = (idx < deg) ? g_csr_all[base + idx] : 0;
        int mres = deg - j0; if (mres > 32) mres = 32;
#pragma unroll
        for (int jj = 0; jj < 16; jj++) {
            int e2 = 2 * jj + sub;
            int s = __shfl_sync(0xffffffffu, sl, e2);
            if (e2 < mres) {
                float4 v = ((const float4*)(pprev + (size_t)s * 64))[li];
                a.x += v.x; a.y += v.y; a.z += v.z; a.w += v.w;
            }
        }
    }
    a.x += __shfl_xor_sync(0xffffffffu, a.x, 16);
    a.y += __shfl_xor_sync(0xffffffffu, a.y, 16);
    a.z += __shfl_xor_sync(0xffffffffu, a.z, 16);
    a.w += __shfl_xor_sync(0xffffffffu, a.w, 16);
    if (sub == 0) {
        float dv = g_dinv_s[w];
        float dv2 = dv * dv;
        ((float4*)(pnext + (size_t)w * 64))[li] =
            make_float4(dv2 * a.x, dv2 * a.y, dv2 * a.z, dv2 * a.w);
    }
}

// conv5 sum gather over ei_ss.
__global__ void k_sum64_gather(const float* __restrict__ feat, float* __restrict__ acc) {
    int gt = blockIdx.x * blockDim.x + threadIdx.x;
    int w = gt >> 5, lane = gt & 31;
    if (w >= NSn) return;
    int base = g_off_all[NVn + w], deg = g_deg_all[NVn + w];
    int sub = lane >> 4, li = lane & 15;
    float4 a = make_float4(0.f, 0.f, 0.f, 0.f);
    for (int j0 = 0; j0 < deg; j0 += 32) {
        int idx = j0 + lane;
        int sl = (idx < deg) ? g_csr_all[base + idx] : 0;
        int mres = deg - j0; if (mres > 32) mres = 32;
#pragma unroll
        for (int jj = 0; jj < 16; jj++) {
            int e2 = 2 * jj + sub;
            int s = __shfl_sync(0xffffffffu, sl, e2);
            if (e2 < mres) {
                float4 v = ((const float4*)(feat + (size_t)s * 64))[li];
                a.x += v.x; a.y += v.y; a.z += v.z; a.w += v.w;
            }
        }
    }
    a.x += __shfl_xor_sync(0xffffffffu, a.x, 16);
    a.y += __shfl_xor_sync(0xffffffffu, a.y, 16);
    a.z += __shfl_xor_sync(0xffffffffu, a.z, 16);
    a.w += __shfl_xor_sync(0xffffffffu, a.w, 16);
    if (sub == 0)
        ((float4*)(acc + (size_t)w * 64))[li] = a;
}

// TAG-state out: relu(b2 + sx5@W2_0 + sqrt(deg) * sum_k p_k@W2_{k+1})
__global__ void k_tag_out(const float* __restrict__ W2, const float* __restrict__ b2) {
    int t = blockIdx.x * blockDim.x + threadIdx.x;
    int v = t >> 6, c = t & 63;
    if (v >= NSn) return;
    float acc = b2[c];
    const float* s0 = g_sx5 + (size_t)v * 64;
#pragma unroll 8
    for (int j = 0; j < 64; j++) acc += s0[j] * W2[j * 64 + c];
    float h = 0.f;
#pragma unroll
    for (int k = 0; k < 3; k++) {
        const float* pk = g_pk[k] + (size_t)v * 64;
        const float* wk = W2 + (size_t)(k + 1) * 4096;
#pragma unroll 8
        for (int j = 0; j < 64; j++) h += pk[j] * wk[j * 64 + c];
    }
    acc += g_sqd_s[v] * h;
    g_sx6[(size_t)v * 64 + c] = fmaxf(acc, 0.f);
}

// conv5 SAGE + linear head, fused.
__global__ void __launch_bounds__(256) k_conv5_final(
        const float* __restrict__ W5_l, const float* __restrict__ W5_r,
        const float* __restrict__ b5, const float* __restrict__ Wl,
        const float* __restrict__ bl, float* __restrict__ out) {
    __shared__ float s7[4][64];
    int tid = threadIdx.x;
    int n = tid >> 6, c = tid & 63;
    int v = blockIdx.x * 4 + n;
    float inv = 1.f / fmaxf(g_cntf_s[v], 1.f);
    const float* av = g_accs5 + (size_t)v * 64;
    float sa = 0.f;
#pragma unroll 8
    for (int j = 0; j < 64; j++) sa += av[j] * W5_l[j * 64 + c];
    float acc = b5[c] + sa * inv;
    const float* xv = g_sx6 + (size_t)v * 64;
#pragma unroll 8
    for (int j = 0; j < 64; j++) acc += xv[j] * W5_r[j * 64 + c];
    s7[n][c] = fmaxf(acc, 0.f);
    __syncthreads();
    if (c < 8) {
        float o = bl[c];
#pragma unroll 8
        for (int j = 0; j < 64; j++) o += s7[n][j] * Wl[j * 8 + c];
        out[(size_t)v * 8 + c] = o;
    }
}

// ------------------------------- launch ------------------------------------

extern "C" void kernel_launch(void* const* d_in, const int* in_sizes, int n_in,
                              void* d_out, int out_size) {
    const float* game_x  = (const float*)d_in[0];
    const float* state_x = (const float*)d_in[1];
    const int*   ei_vv   = (const int*)d_in[2];
    const int*   et_vv   = (const int*)d_in[3];
    const int*   ei_h    = (const int*)d_in[4];
    const float* ew_h    = (const float*)d_in[5];
    const int*   ei_in   = (const int*)d_in[6];
    const int*   ei_ss   = (const int*)d_in[7];
    const float* W1_rel  = (const float*)d_in[8];
    const float* W1_root = (const float*)d_in[9];
    const float* b1      = (const float*)d_in[10];
    const float* W12     = (const float*)d_in[11];
    const float* b12     = (const float*)d_in[12];
    const float* W2      = (const float*)d_in[13];
    const float* b2      = (const float*)d_in[14];
    const float* W3_rel  = (const float*)d_in[15];
    const float* W3_root = (const float*)d_in[16];
    const float* b3      = (const float*)d_in[17];
    const float* W32_l   = (const float*)d_in[18];
    const float* W32_r   = (const float*)d_in[19];
    const float* b32     = (const float*)d_in[20];
    const float* W4_l    = (const float*)d_in[21];
    const float* W4_r    = (const float*)d_in[22];
    const float* b4      = (const float*)d_in[23];
    const float* W42_l   = (const float*)d_in[24];
    const float* W42_r   = (const float*)d_in[25];
    const float* b42     = (const float*)d_in[26];
    const float* W5_l    = (const float*)d_in[27];
    const float* W5_r    = (const float*)d_in[28];
    const float* b5      = (const float*)d_in[29];
    const float* Wl      = (const float*)d_in[30];
    const float* bl      = (const float*)d_in[31];
    float* out = (float*)d_out;

    int Evv = in_sizes[2] / 2;
    int Eh  = in_sizes[4] / 2;
    int Ein = in_sizes[6] / 2;
    int Ess = in_sizes[7] / 2;
    int Etot = Evv + Ess + Eh + Ein;
    int whbase = Evv + Ess;   // csrw index base for ei_h segment

    int* pi_deg;
    float *p_pv, *p_pin, *p_pk, *p_sx6, *p_accs5;
    cudaGetSymbolAddress((void**)&pi_deg,  g_deg_all);
    cudaGetSymbolAddress((void**)&p_pv,    g_pv);
    cudaGetSymbolAddress((void**)&p_pin,   g_pin);
    cudaGetSymbolAddress((void**)&p_pk,    g_pk);
    cudaGetSymbolAddress((void**)&p_sx6,   g_sx6);
    cudaGetSymbolAddress((void**)&p_accs5, g_accs5);

    float* p_pv0 = p_pv;
    float* p_pv1 = p_pv + (size_t)NVn * 8;
    float* p_pk0 = p_pk;
    float* p_pk1 = p_pk + (size_t)NSn * 64;
    float* p_pk2 = p_pk1 + (size_t)NSn * 64;

    const int T = 256;
    auto nb = [](long n, int t) { return (int)((n + t - 1) / t); };
    int nbv_warp = nb((long)NVn * 32, T);
    int nbs_warp = nb((long)NSn * 32, T);
    int nscan = nb(NDEG, 1024);

    // 0) zero unified degree array (only memset in the whole pipeline)
    cudaMemsetAsync(pi_deg, 0, (size_t)NDEG * 4, 0);

    // 1) unified CSR build
    k_count_all<<<nb(Etot, T), T>>>(ei_vv, ei_ss, ei_h, ei_in, Evv, Ess, Eh, Ein);
    k_scan1<<<nscan, 1024>>>(NDEG);
    k_scan2<<<1, 256>>>(nscan);
    k_scan3<<<nb(NDEG, T), T>>>(NDEG);
    k_fill_all<<<nb(Etot, T), T>>>(ei_vv, et_vv, ei_ss, ei_h, ew_h, ei_in,
                                   Evv, Ess, Eh, Ein);

    // 2) pad + dinv, weight prep
    k_pad_dinv<<<nb((long)NVn * 8, T), T>>>(game_x);
    k_prep<<<nb(4 * 41 * 64, T), T>>>(W1_rel, W1_root, b1, W12, b12,
                                      W3_rel, W32_l, W4_l, W42_l);

    // 3) game graph -> z
    k_rgcn_hop1<<<nbv_warp, T>>>(p_pv0);
    k_hop8_gather<<<nbv_warp, T>>>(p_pv0, p_pv1, 1, 1);
    k_hop8_gather<<<nbv_warp, T>>>(p_pv1, p_pv0, 2, 0);

    // 4) mega: ei_h + ei_in gathers + state layers 2-5 -> sx5, pin
    k_state_mega<<<NSn / 4, 256>>>(state_x, W3_root, b3, W32_r, b32,
                                   W4_r, b4, W42_r, b42, whbase);

    // 5) TAG-state hops (p-form) + output
    k_hop64p<<<nbs_warp, T>>>(p_pin, p_pk0);
    k_hop64p<<<nbs_warp, T>>>(p_pk0, p_pk1);
    k_hop64p<<<nbs_warp, T>>>(p_pk1, p_pk2);
    k_tag_out<<<nb((long)NSn * 64, T), T>>>(W2, b2);

    // 6) conv5 + head
    k_sum64_gather<<<nbs_warp, T>>>(p_sx6, p_accs5);
    k_conv5_final<<<NSn / 4, 256>>>(W5_l, W5_r, b5, Wl, bl, out);
}

// round 10
// speedup vs baseline: 1.9971x; 1.1971x over previous
#include <cuda_runtime.h>
#include <math.h>

// ---------------------------------------------------------------------------
// StateModelEncoder — round 10: round-9 structure with the csrw indexing bug
// fixed (csrw sized to full unified CSR, indexed by slot directly).
// 13 launches, zero feature atomics.
// ---------------------------------------------------------------------------

#define NVn 100000
#define NSn 50000
#define EVVmax 1600000
#define ESSmax 800000
#define EHmax  800000
#define EINmax 800000
#define NDEG   (NVn + 3 * NSn)
#define ETOT   (EVVmax + ESSmax + EHmax + EINmax)

// ------------------------- scratch (device globals) ------------------------
__device__ __align__(16) float g_xpad[NVn * 8];
__device__ float g_dinv_v[NVn];
__device__ __align__(16) float g_z[NVn * 40];          // [x5|rgcn15|hops15|0 pad5]
__device__ __align__(16) float g_pv[2][NVn * 8];
__device__ __align__(16) float g_WzW[4][40 * 64];
__device__ float g_c0W[4][64];
__device__ __align__(16) float g_sx5[NSn * 64];
__device__ __align__(16) float g_pin[NSn * 64];
__device__ __align__(16) float g_pk[2][NSn * 64];
__device__ __align__(16) float g_sx6[NSn * 64];
__device__ float g_dinv_s[NSn];
__device__ float g_sqd_s[NSn];
__device__ float g_cntf_s[NSn];

// unified CSR
__device__ int g_deg_all[NDEG];
__device__ int g_off_all[NDEG];
__device__ int g_cur_all[NDEG];
__device__ int g_scan_base;
__device__ int g_csr_all[ETOT];     // vv segment packs src | (etype<<20)
__device__ float g_csrw[ETOT];      // edge weights, indexed by CSR slot (ei_h only)

// ------------------------------ CSR build ----------------------------------
__global__ void k_count_all(const int* __restrict__ ei_vv, const int* __restrict__ ei_ss,
                            const int* __restrict__ ei_h,  const int* __restrict__ ei_in,
                            int Evv, int Ess, int Eh, int Ein) {
    int t = blockIdx.x * blockDim.x + threadIdx.x;
    if (t == 0) g_scan_base = 0;
    if (t < Evv) { atomicAdd(g_deg_all + ei_vv[Evv + t], 1); return; }
    t -= Evv;
    if (t < Ess) { atomicAdd(g_deg_all + NVn + ei_ss[Ess + t], 1); return; }
    t -= Ess;
    if (t < Eh)  { atomicAdd(g_deg_all + NVn + NSn + ei_h[Eh + t], 1); return; }
    t -= Eh;
    if (t < Ein) { atomicAdd(g_deg_all + NVn + 2 * NSn + ei_in[Ein + t], 1); }
}

// one-pass scan: block-local inclusive scan + atomic block base.
// CSR slice placement is arrival-ordered; per-node slices remain unique and
// contiguous, so all per-node gathers are unaffected.
__global__ void k_scan(int n) {
    __shared__ int sh[1024];
    __shared__ int s_base;
    int i = blockIdx.x * 1024 + threadIdx.x;
    int v = (i < n) ? g_deg_all[i] : 0;
    sh[threadIdx.x] = v;
    __syncthreads();
    for (int o = 1; o < 1024; o <<= 1) {
        int t = (threadIdx.x >= o) ? sh[threadIdx.x - o] : 0;
        __syncthreads();
        sh[threadIdx.x] += t;
        __syncthreads();
    }
    if (threadIdx.x == 1023) s_base = atomicAdd(&g_scan_base, sh[1023]);
    __syncthreads();
    if (i < n) {
        int o = s_base + sh[threadIdx.x] - v;   // exclusive within block + base
        g_off_all[i] = o;
        g_cur_all[i] = o;
    }
}

__global__ void k_fill_all(const int* __restrict__ ei_vv, const int* __restrict__ et_vv,
                           const int* __restrict__ ei_ss, const int* __restrict__ ei_h,
                           const float* __restrict__ ew_h, const int* __restrict__ ei_in,
                           int Evv, int Ess, int Eh, int Ein) {
    int t = blockIdx.x * blockDim.x + threadIdx.x;
    if (t < Evv) {
        int slot = atomicAdd(g_cur_all + ei_vv[Evv + t], 1);
        g_csr_all[slot] = ei_vv[t] | (et_vv[t] << 20);
        return;
    }
    t -= Evv;
    if (t < Ess) {
        int slot = atomicAdd(g_cur_all + NVn + ei_ss[Ess + t], 1);
        g_csr_all[slot] = ei_ss[t];
        return;
    }
    t -= Ess;
    if (t < Eh) {
        int slot = atomicAdd(g_cur_all + NVn + NSn + ei_h[Eh + t], 1);
        g_csr_all[slot] = ei_h[t];
        g_csrw[slot] = ew_h[t];          // slot-indexed (fix)
        return;
    }
    t -= Eh;
    if (t < Ein) {
        int slot = atomicAdd(g_cur_all + NVn + 2 * NSn + ei_in[Ein + t], 1);
        g_csr_all[slot] = ei_in[t];
    }
}

// pad game_x + dinv arrays + weight products, one kernel.
__global__ void k_pad_prep(const float* __restrict__ x,
                           const float* __restrict__ W1_rel, const float* __restrict__ W1_root,
                           const float* __restrict__ b1,
                           const float* __restrict__ W12, const float* __restrict__ b12,
                           const float* __restrict__ W3_rel, const float* __restrict__ W32_l,
                           const float* __restrict__ W4_l,  const float* __restrict__ W42_l) {
    int t = blockIdx.x * blockDim.x + threadIdx.x;
    if (t < NVn * 8) {
        int v = t >> 3, i = t & 7;
        float xv = (i < 5) ? x[v * 5 + i] : 0.f;
        g_xpad[t] = xv;
        if (i < 5) g_z[(size_t)v * 40 + i] = xv;
    }
    if (t < NVn) {
        int d = g_deg_all[t];
        g_dinv_v[t] = (d > 0) ? rsqrtf((float)d) : 0.f;
    }
    if (t < NSn) {
        int d = g_deg_all[NVn + t];
        g_dinv_s[t] = (d > 0) ? rsqrtf((float)d) : 0.f;
        g_sqd_s[t]  = sqrtf((float)d);
        g_cntf_s[t] = (float)d;
    }
    if (t < 4 * 41 * 64) {
        int m = t / (41 * 64);
        int r = t % (41 * 64);
        int i = r >> 6, c = r & 63;
        const float* Wm = (m == 0) ? W3_rel : (m == 1) ? W32_l : (m == 2) ? W4_l : W42_l;
        float acc = 0.f;
        if (i < 40) {
            if (i < 35) {
#pragma unroll 8
                for (int j = 0; j < 64; j++) {
                    float wz;
                    if (i < 5)       wz = W1_root[i * 64 + j] + W12[i * 64 + j];
                    else if (i < 20) wz = W1_rel[(i - 5) * 64 + j];
                    else             wz = W12[(i - 15) * 64 + j];
                    acc += wz * Wm[j * 64 + c];
                }
                g_WzW[m][i * 64 + c] = acc;
            }
        } else {
#pragma unroll 8
            for (int j = 0; j < 64; j++) acc += (b1[j] + b12[j]) * Wm[j * 64 + c];
            g_c0W[m][c] = acc;
        }
    }
}

// --------------------------- game-graph kernels ----------------------------
__global__ void k_rgcn_hop1(float* __restrict__ p1) {
    int gt = blockIdx.x * blockDim.x + threadIdx.x;
    int w = gt >> 5, lane = gt & 31;
    if (w >= NVn) return;
    int base = g_off_all[w], deg = g_deg_all[w];
    int sub = lane >> 3, li = lane & 7;
    float a0 = 0.f, a1 = 0.f, a2 = 0.f, ah = 0.f;
    float c0 = 0.f, c1 = 0.f, c2 = 0.f;
#pragma unroll 4
    for (int j = sub; j < deg; j += 4) {
        int pk = g_csr_all[base + j];
        int s = pk & 0xFFFFF, t = pk >> 20;
        float xv = g_xpad[(size_t)s * 8 + li];
        ah += g_dinv_v[s] * xv;
        if (t == 0)      { a0 += xv; c0 += 1.f; }
        else if (t == 1) { a1 += xv; c1 += 1.f; }
        else             { a2 += xv; c2 += 1.f; }
    }
#pragma unroll
    for (int o = 8; o < 32; o <<= 1) {
        a0 += __shfl_xor_sync(0xffffffffu, a0, o);
        a1 += __shfl_xor_sync(0xffffffffu, a1, o);
        a2 += __shfl_xor_sync(0xffffffffu, a2, o);
        ah += __shfl_xor_sync(0xffffffffu, ah, o);
        c0 += __shfl_xor_sync(0xffffffffu, c0, o);
        c1 += __shfl_xor_sync(0xffffffffu, c1, o);
        c2 += __shfl_xor_sync(0xffffffffu, c2, o);
    }
    if (sub == 0) {
        float dvd = g_dinv_v[w];
        float h1 = dvd * ah;
        if (li < 5) {
            float* zz = g_z + (size_t)w * 40;
            zz[5 + li]  = a0 / fmaxf(c0, 1.f);
            zz[10 + li] = a1 / fmaxf(c1, 1.f);
            zz[15 + li] = a2 / fmaxf(c2, 1.f);
            zz[20 + li] = h1;
            zz[35 + li] = 0.f;
        }
        p1[(size_t)w * 8 + li] = dvd * h1;
    }
}

__global__ void k_hop8_gather(const float* __restrict__ pprev, float* __restrict__ pnext,
                              int k, int write_p) {
    int gt = blockIdx.x * blockDim.x + threadIdx.x;
    int w = gt >> 5, lane = gt & 31;
    if (w >= NVn) return;
    int base = g_off_all[w], deg = g_deg_all[w];
    int sub = lane >> 3, li = lane & 7;
    float acc = 0.f;
#pragma unroll 4
    for (int j = sub; j < deg; j += 4) {
        int s = g_csr_all[base + j] & 0xFFFFF;
        acc += pprev[(size_t)s * 8 + li];
    }
#pragma unroll
    for (int o = 8; o < 32; o <<= 1)
        acc += __shfl_xor_sync(0xffffffffu, acc, o);
    if (sub == 0) {
        float dv = g_dinv_v[w];
        float h = dv * acc;
        if (li < 5) g_z[(size_t)w * 40 + 20 + k * 5 + li] = h;
        if (write_p) pnext[(size_t)w * 8 + li] = dv * h;
    }
}

// -------- mega kernel: ei_h + ei_in z-gathers and state layers 2-5 ---------
__global__ void __launch_bounds__(256) k_state_mega(
        const float* __restrict__ state_x, const float* __restrict__ W3_root,
        const float* __restrict__ b3, const float* __restrict__ W32_r,
        const float* __restrict__ b32, const float* __restrict__ W4_r,
        const float* __restrict__ b4, const float* __restrict__ W42_r,
        const float* __restrict__ b42) {
    __shared__ float4 s_aggw4[4][10];
    __shared__ float4 s_aggu4[4][10];
    __shared__ float4 s_aggin4[4][10];
    __shared__ float s_wsum[4];
    __shared__ float s_sx[2][4][64];
    int tid = threadIdx.x;
    int warp = tid >> 5, lane = tid & 31;
    int sub = lane >> 4, li = lane & 15;
    int vbase = blockIdx.x * 4;

    {
        int n = warp & 3;
        int v = vbase + n;
        if (warp < 4) {
            int base = g_off_all[NVn + NSn + v], deg = g_deg_all[NVn + NSn + v];
            float4 aW = make_float4(0.f, 0.f, 0.f, 0.f);
            float4 aU = make_float4(0.f, 0.f, 0.f, 0.f);
            float wsum = 0.f;
            for (int j0 = 0; j0 < deg; j0 += 32) {
                int idx = j0 + lane;
                int sl = 0; float wl = 0.f;
                if (idx < deg) { sl = g_csr_all[base + idx]; wl = g_csrw[base + idx]; }
                wsum += wl;
                int mres = deg - j0; if (mres > 32) mres = 32;
#pragma unroll
                for (int jj = 0; jj < 16; jj++) {
                    int e2 = 2 * jj + sub;
                    int s = __shfl_sync(0xffffffffu, sl, e2);
                    float wt = __shfl_sync(0xffffffffu, wl, e2);
                    if (e2 < mres && li < 10) {
                        float4 t = ((const float4*)(g_z + (size_t)s * 40))[li];
                        aU.x += t.x; aU.y += t.y; aU.z += t.z; aU.w += t.w;
                        aW.x += wt * t.x; aW.y += wt * t.y; aW.z += wt * t.z; aW.w += wt * t.w;
                    }
                }
            }
            aU.x += __shfl_xor_sync(0xffffffffu, aU.x, 16);
            aU.y += __shfl_xor_sync(0xffffffffu, aU.y, 16);
            aU.z += __shfl_xor_sync(0xffffffffu, aU.z, 16);
            aU.w += __shfl_xor_sync(0xffffffffu, aU.w, 16);
            aW.x += __shfl_xor_sync(0xffffffffu, aW.x, 16);
            aW.y += __shfl_xor_sync(0xffffffffu, aW.y, 16);
            aW.z += __shfl_xor_sync(0xffffffffu, aW.z, 16);
            aW.w += __shfl_xor_sync(0xffffffffu, aW.w, 16);
#pragma unroll
            for (int o = 16; o; o >>= 1) wsum += __shfl_xor_sync(0xffffffffu, wsum, o);
            if (sub == 0 && li < 10) { s_aggu4[n][li] = aU; s_aggw4[n][li] = aW; }
            if (lane == 0) s_wsum[n] = wsum;
        } else {
            int base = g_off_all[NVn + 2 * NSn + v], deg = g_deg_all[NVn + 2 * NSn + v];
            float4 aU = make_float4(0.f, 0.f, 0.f, 0.f);
            for (int j0 = 0; j0 < deg; j0 += 32) {
                int idx = j0 + lane;
                int sl = (idx < deg) ? g_csr_all[base + idx] : 0;
                int mres = deg - j0; if (mres > 32) mres = 32;
#pragma unroll
                for (int jj = 0; jj < 16; jj++) {
                    int e2 = 2 * jj + sub;
                    int s = __shfl_sync(0xffffffffu, sl, e2);
                    if (e2 < mres && li < 10) {
                        float4 t = ((const float4*)(g_z + (size_t)s * 40))[li];
                        aU.x += t.x; aU.y += t.y; aU.z += t.z; aU.w += t.w;
                    }
                }
            }
            aU.x += __shfl_xor_sync(0xffffffffu, aU.x, 16);
            aU.y += __shfl_xor_sync(0xffffffffu, aU.y, 16);
            aU.z += __shfl_xor_sync(0xffffffffu, aU.z, 16);
            aU.w += __shfl_xor_sync(0xffffffffu, aU.w, 16);
            if (sub == 0 && li < 10) s_aggin4[n][li] = aU;
        }
    }
    __syncthreads();

    int n = tid >> 6, c = tid & 63;
    int v = vbase + n;
    const float* s_aggw  = (const float*)s_aggw4[n];
    const float* s_aggu  = (const float*)s_aggu4[n];
    const float* s_aggin = (const float*)s_aggin4[n];
    float ch = (float)g_deg_all[NVn + NSn + v];
    float ci = (float)g_deg_all[NVn + 2 * NSn + v];

    {   // L2: graph_conv
        float acc = b3[c] + s_wsum[n] * g_c0W[0][c];
        const float* W = g_WzW[0];
#pragma unroll 7
        for (int i = 0; i < 35; i++) acc += s_aggw[i] * W[i * 64 + c];
        const float* xv = state_x + (size_t)v * 5;
#pragma unroll
        for (int j = 0; j < 5; j++) acc += xv[j] * W3_root[j * 64 + c];
        s_sx[0][n][c] = fmaxf(acc, 0.f);
    }
    __syncthreads();
    {   // L3: conv32
        float inv = 1.f / fmaxf(ch, 1.f);
        const float* W = g_WzW[1];
        float sa = 0.f;
#pragma unroll 7
        for (int i = 0; i < 35; i++) sa += s_aggu[i] * W[i * 64 + c];
        float acc = b32[c] + sa * inv + ((ch > 0.f) ? g_c0W[1][c] : 0.f);
#pragma unroll 8
        for (int j = 0; j < 64; j++) acc += s_sx[0][n][j] * W32_r[j * 64 + c];
        s_sx[1][n][c] = fmaxf(acc, 0.f);
    }
    __syncthreads();
    {   // L4: conv4
        float inv = 1.f / fmaxf(ci, 1.f);
        const float* W = g_WzW[2];
        float sa = 0.f;
#pragma unroll 7
        for (int i = 0; i < 35; i++) sa += s_aggin[i] * W[i * 64 + c];
        float acc = b4[c] + sa * inv + ((ci > 0.f) ? g_c0W[2][c] : 0.f);
#pragma unroll 8
        for (int j = 0; j < 64; j++) acc += s_sx[1][n][j] * W4_r[j * 64 + c];
        s_sx[0][n][c] = fmaxf(acc, 0.f);
    }
    __syncthreads();
    {   // L5: conv42
        float inv = 1.f / fmaxf(ci, 1.f);
        const float* W = g_WzW[3];
        float sa = 0.f;
#pragma unroll 7
        for (int i = 0; i < 35; i++) sa += s_aggin[i] * W[i * 64 + c];
        float acc = b42[c] + sa * inv + ((ci > 0.f) ? g_c0W[3][c] : 0.f);
#pragma unroll 8
        for (int j = 0; j < 64; j++) acc += s_sx[0][n][j] * W42_r[j * 64 + c];
        float sx5 = fmaxf(acc, 0.f);
        g_sx5[(size_t)v * 64 + c] = sx5;
        g_pin[(size_t)v * 64 + c] = g_dinv_s[v] * sx5;
    }
}

// TAG-state hop, p-form: p_next = dinv^2 * sum(p_prev[src]).
__global__ void k_hop64p(const float* __restrict__ pprev, float* __restrict__ pnext) {
    int gt = blockIdx.x * blockDim.x + threadIdx.x;
    int w = gt >> 5, lane = gt & 31;
    if (w >= NSn) return;
    int base = g_off_all[NVn + w], deg = g_deg_all[NVn + w];
    int sub = lane >> 4, li = lane & 15;
    float4 a = make_float4(0.f, 0.f, 0.f, 0.f);
    for (int j0 = 0; j0 < deg; j0 += 32) {
        int idx = j0 + lane;
        int sl = (idx < deg) ? g_csr_all[base + idx] : 0;
        int mres = deg - j0; if (mres > 32) mres = 32;
#pragma unroll
        for (int jj = 0; jj < 16; jj++) {
            int e2 = 2 * jj + sub;
            int s = __shfl_sync(0xffffffffu, sl, e2);
            if (e2 < mres) {
                float4 v = ((const float4*)(pprev + (size_t)s * 64))[li];
                a.x += v.x; a.y += v.y; a.z += v.z; a.w += v.w;
            }
        }
    }
    a.x += __shfl_xor_sync(0xffffffffu, a.x, 16);
    a.y += __shfl_xor_sync(0xffffffffu, a.y, 16);
    a.z += __shfl_xor_sync(0xffffffffu, a.z, 16);
    a.w += __shfl_xor_sync(0xffffffffu, a.w, 16);
    if (sub == 0) {
        float dv = g_dinv_s[w];
        float dv2 = dv * dv;
        ((float4*)(pnext + (size_t)w * 64))[li] =
            make_float4(dv2 * a.x, dv2 * a.y, dv2 * a.z, dv2 * a.w);
    }
}

// Fused: hop3 gather (pk1 -> pk2 in shared) + TAG output dense. 8 nodes/block.
__global__ void __launch_bounds__(256) k_hop3_tagout(
        const float* __restrict__ pk1, const float* __restrict__ pk0,
        const float* __restrict__ W2, const float* __restrict__ b2) {
    __shared__ float s_pk2[8][64];
    __shared__ float s_pk0[8][64];
    __shared__ float s_pk1[8][64];
    __shared__ float s_sx5[8][64];
    int tid = threadIdx.x;
    int warp = tid >> 5, lane = tid & 31;
    int sub = lane >> 4, li = lane & 15;
    int v = blockIdx.x * 8 + warp;

    s_sx5[warp][lane]      = g_sx5[(size_t)v * 64 + lane];
    s_sx5[warp][lane + 32] = g_sx5[(size_t)v * 64 + lane + 32];
    s_pk0[warp][lane]      = pk0[(size_t)v * 64 + lane];
    s_pk0[warp][lane + 32] = pk0[(size_t)v * 64 + lane + 32];
    s_pk1[warp][lane]      = pk1[(size_t)v * 64 + lane];
    s_pk1[warp][lane + 32] = pk1[(size_t)v * 64 + lane + 32];

    {   // hop3 gather
        int base = g_off_all[NVn + v], deg = g_deg_all[NVn + v];
        float4 a = make_float4(0.f, 0.f, 0.f, 0.f);
        for (int j0 = 0; j0 < deg; j0 += 32) {
            int idx = j0 + lane;
            int sl = (idx < deg) ? g_csr_all[base + idx] : 0;
            int mres = deg - j0; if (mres > 32) mres = 32;
#pragma unroll
            for (int jj = 0; jj < 16; jj++) {
                int e2 = 2 * jj + sub;
                int s = __shfl_sync(0xffffffffu, sl, e2);
                if (e2 < mres) {
                    float4 t = ((const float4*)(pk1 + (size_t)s * 64))[li];
                    a.x += t.x; a.y += t.y; a.z += t.z; a.w += t.w;
                }
            }
        }
        a.x += __shfl_xor_sync(0xffffffffu, a.x, 16);
        a.y += __shfl_xor_sync(0xffffffffu, a.y, 16);
        a.z += __shfl_xor_sync(0xffffffffu, a.z, 16);
        a.w += __shfl_xor_sync(0xffffffffu, a.w, 16);
        if (sub == 0) {
            float dv = g_dinv_s[v];
            float dv2 = dv * dv;
            ((float4*)s_pk2[warp])[li] =
                make_float4(dv2 * a.x, dv2 * a.y, dv2 * a.z, dv2 * a.w);
        }
    }
    __syncthreads();

    int n = warp;
    float sq = g_sqd_s[v];
    int c0 = lane, c1 = lane + 32;
    float acc0 = b2[c0], acc1 = b2[c1];
    float h0 = 0.f, h1 = 0.f;
#pragma unroll 8
    for (int j = 0; j < 64; j++) {
        float w0 = W2[j * 64 + c0],           w1 = W2[j * 64 + c1];
        acc0 += s_sx5[n][j] * w0;             acc1 += s_sx5[n][j] * w1;
        float u0 = W2[4096 + j * 64 + c0],    u1 = W2[4096 + j * 64 + c1];
        h0 += s_pk0[n][j] * u0;               h1 += s_pk0[n][j] * u1;
        float v0 = W2[8192 + j * 64 + c0],    v1 = W2[8192 + j * 64 + c1];
        h0 += s_pk1[n][j] * v0;               h1 += s_pk1[n][j] * v1;
        float x0 = W2[12288 + j * 64 + c0],   x1 = W2[12288 + j * 64 + c1];
        h0 += s_pk2[n][j] * x0;               h1 += s_pk2[n][j] * x1;
    }
    g_sx6[(size_t)v * 64 + c0] = fmaxf(acc0 + sq * h0, 0.f);
    g_sx6[(size_t)v * 64 + c1] = fmaxf(acc1 + sq * h1, 0.f);
}

// Fused: conv5 neighbor-sum gather + SAGE dense + linear head. 8 nodes/block.
__global__ void __launch_bounds__(256) k_conv5_final(
        const float* __restrict__ W5_l, const float* __restrict__ W5_r,
        const float* __restrict__ b5, const float* __restrict__ Wl,
        const float* __restrict__ bl, float* __restrict__ out) {
    __shared__ float s_acc[8][64];
    __shared__ float s_x[8][64];
    __shared__ float s7[8][64];
    int tid = threadIdx.x;
    int warp = tid >> 5, lane = tid & 31;
    int sub = lane >> 4, li = lane & 15;
    int v = blockIdx.x * 8 + warp;

    s_x[warp][lane]      = g_sx6[(size_t)v * 64 + lane];
    s_x[warp][lane + 32] = g_sx6[(size_t)v * 64 + lane + 32];

    {   // neighbor sum over ei_ss
        int base = g_off_all[NVn + v], deg = g_deg_all[NVn + v];
        float4 a = make_float4(0.f, 0.f, 0.f, 0.f);
        for (int j0 = 0; j0 < deg; j0 += 32) {
            int idx = j0 + lane;
            int sl = (idx < deg) ? g_csr_all[base + idx] : 0;
            int mres = deg - j0; if (mres > 32) mres = 32;
#pragma unroll
            for (int jj = 0; jj < 16; jj++) {
                int e2 = 2 * jj + sub;
                int s = __shfl_sync(0xffffffffu, sl, e2);
                if (e2 < mres) {
                    float4 t = ((const float4*)(g_sx6 + (size_t)s * 64))[li];
                    a.x += t.x; a.y += t.y; a.z += t.z; a.w += t.w;
                }
            }
        }
        a.x += __shfl_xor_sync(0xffffffffu, a.x, 16);
        a.y += __shfl_xor_sync(0xffffffffu, a.y, 16);
        a.z += __shfl_xor_sync(0xffffffffu, a.z, 16);
        a.w += __shfl_xor_sync(0xffffffffu, a.w, 16);
        if (sub == 0) ((float4*)s_acc[warp])[li] = a;
    }
    __syncthreads();

    int n = warp;
    float inv = 1.f / fmaxf(g_cntf_s[v], 1.f);
    int c0 = lane, c1 = lane + 32;
    float sa0 = 0.f, sa1 = 0.f, r0 = b5[c0], r1 = b5[c1];
#pragma unroll 8
    for (int j = 0; j < 64; j++) {
        float l0 = W5_l[j * 64 + c0], l1 = W5_l[j * 64 + c1];
        sa0 += s_acc[n][j] * l0;      sa1 += s_acc[n][j] * l1;
        float q0 = W5_r[j * 64 + c0], q1 = W5_r[j * 64 + c1];
        r0 += s_x[n][j] * q0;         r1 += s_x[n][j] * q1;
    }
    s7[n][c0] = fmaxf(r0 + sa0 * inv, 0.f);
    s7[n][c1] = fmaxf(r1 + sa1 * inv, 0.f);
    __syncthreads();
    if (lane < 8) {
        float o = bl[lane];
#pragma unroll 8
        for (int j = 0; j < 64; j++) o += s7[n][j] * Wl[j * 8 + lane];
        out[(size_t)v * 8 + lane] = o;
    }
}

// ------------------------------- launch ------------------------------------

extern "C" void kernel_launch(void* const* d_in, const int* in_sizes, int n_in,
                              void* d_out, int out_size) {
    const float* game_x  = (const float*)d_in[0];
    const float* state_x = (const float*)d_in[1];
    const int*   ei_vv   = (const int*)d_in[2];
    const int*   et_vv   = (const int*)d_in[3];
    const int*   ei_h    = (const int*)d_in[4];
    const float* ew_h    = (const float*)d_in[5];
    const int*   ei_in   = (const int*)d_in[6];
    const int*   ei_ss   = (const int*)d_in[7];
    const float* W1_rel  = (const float*)d_in[8];
    const float* W1_root = (const float*)d_in[9];
    const float* b1      = (const float*)d_in[10];
    const float* W12     = (const float*)d_in[11];
    const float* b12     = (const float*)d_in[12];
    const float* W2      = (const float*)d_in[13];
    const float* b2      = (const float*)d_in[14];
    const float* W3_rel  = (const float*)d_in[15];
    const float* W3_root = (const float*)d_in[16];
    const float* b3      = (const float*)d_in[17];
    const float* W32_l   = (const float*)d_in[18];
    const float* W32_r   = (const float*)d_in[19];
    const float* b32     = (const float*)d_in[20];
    const float* W4_l    = (const float*)d_in[21];
    const float* W4_r    = (const float*)d_in[22];
    const float* b4      = (const float*)d_in[23];
    const float* W42_l   = (const float*)d_in[24];
    const float* W42_r   = (const float*)d_in[25];
    const float* b42     = (const float*)d_in[26];
    const float* W5_l    = (const float*)d_in[27];
    const float* W5_r    = (const float*)d_in[28];
    const float* b5      = (const float*)d_in[29];
    const float* Wl      = (const float*)d_in[30];
    const float* bl      = (const float*)d_in[31];
    float* out = (float*)d_out;

    int Evv = in_sizes[2] / 2;
    int Eh  = in_sizes[4] / 2;
    int Ein = in_sizes[6] / 2;
    int Ess = in_sizes[7] / 2;
    int Etot = Evv + Ess + Eh + Ein;

    int* pi_deg;
    float *p_pv, *p_pin, *p_pk;
    cudaGetSymbolAddress((void**)&pi_deg, g_deg_all);
    cudaGetSymbolAddress((void**)&p_pv,   g_pv);
    cudaGetSymbolAddress((void**)&p_pin,  g_pin);
    cudaGetSymbolAddress((void**)&p_pk,   g_pk);

    float* p_pv0 = p_pv;
    float* p_pv1 = p_pv + (size_t)NVn * 8;
    float* p_pk0 = p_pk;
    float* p_pk1 = p_pk + (size_t)NSn * 64;

    const int T = 256;
    auto nb = [](long n, int t) { return (int)((n + t - 1) / t); };
    int nbv_warp = nb((long)NVn * 32, T);
    int nbs_warp = nb((long)NSn * 32, T);

    // 0) zero unified degree array
    cudaMemsetAsync(pi_deg, 0, (size_t)NDEG * 4, 0);

    // 1) unified CSR build (count / scan / fill)
    k_count_all<<<nb(Etot, T), T>>>(ei_vv, ei_ss, ei_h, ei_in, Evv, Ess, Eh, Ein);
    k_scan<<<nb(NDEG, 1024), 1024>>>(NDEG);
    k_fill_all<<<nb(Etot, T), T>>>(ei_vv, et_vv, ei_ss, ei_h, ew_h, ei_in,
                                   Evv, Ess, Eh, Ein);

    // 2) pad + dinv + weight prep (one kernel)
    k_pad_prep<<<nb((long)NVn * 8, T), T>>>(game_x, W1_rel, W1_root, b1, W12, b12,
                                            W3_rel, W32_l, W4_l, W42_l);

    // 3) game graph -> z
    k_rgcn_hop1<<<nbv_warp, T>>>(p_pv0);
    k_hop8_gather<<<nbv_warp, T>>>(p_pv0, p_pv1, 1, 1);
    k_hop8_gather<<<nbv_warp, T>>>(p_pv1, p_pv0, 2, 0);

    // 4) mega: ei_h + ei_in gathers + state layers 2-5 -> sx5, pin
    k_state_mega<<<NSn / 4, 256>>>(state_x, W3_root, b3, W32_r, b32,
                                   W4_r, b4, W42_r, b42);

    // 5) TAG-state hops 1-2, then fused hop3 + tag output
    k_hop64p<<<nbs_warp, T>>>(p_pin, p_pk0);
    k_hop64p<<<nbs_warp, T>>>(p_pk0, p_pk1);
    k_hop3_tagout<<<NSn / 8, 256>>>(p_pk1, p_pk0, W2, b2);

    // 6) fused conv5 gather + dense + head
    k_conv5_final<<<NSn / 8, 256>>>(W5_l, W5_r, b5, Wl, bl, out);
}

// round 12
// speedup vs baseline: 2.4874x; 1.2455x over previous
#include <cuda_runtime.h>
#include <math.h>

// ---------------------------------------------------------------------------
// StateModelEncoder — round 12: round-11 tiled-GEMM dense phases with the
// k_conv5_head shared-memory race fixed (sync after scale-array init).
// 16 launches, zero feature atomics.
// ---------------------------------------------------------------------------

#define NVn 100000
#define NSn 50000
#define EVVmax 1600000
#define ESSmax 800000
#define EHmax  800000
#define EINmax 800000
#define NDEG   (NVn + 3 * NSn)
#define ETOT   (EVVmax + ESSmax + EHmax + EINmax)
#define AST    68                      // transposed-act smem row stride

// ------------------------- scratch (device globals) ------------------------
__device__ __align__(16) float g_xpad[NVn * 8];
__device__ float g_dinv_v[NVn];
__device__ __align__(16) float g_z[NVn * 40];
__device__ __align__(16) float g_pv[2][NVn * 8];
__device__ __align__(16) float g_WzW[4][40 * 64];
__device__ float g_c0W[4][64];
__device__ __align__(16) float g_aggw[(size_t)NSn * 36];
__device__ __align__(16) float g_aggu[(size_t)NSn * 36];
__device__ __align__(16) float g_aggin[(size_t)NSn * 36];
__device__ float g_wsum[NSn];
__device__ __align__(16) float g_ta[(size_t)NSn * 64];
__device__ __align__(16) float g_tb[(size_t)NSn * 64];
__device__ __align__(16) float g_sx5[(size_t)NSn * 64];
__device__ __align__(16) float g_pin[(size_t)NSn * 64];
__device__ __align__(16) float g_pk[3][(size_t)NSn * 64];
__device__ __align__(16) float g_sx6[(size_t)NSn * 64];
__device__ __align__(16) float g_accs5[(size_t)NSn * 64];
__device__ float g_dinv_s[NSn];
__device__ float g_sqd_s[NSn];
__device__ float g_cntf_s[NSn];

// unified CSR
__device__ int g_deg_all[NDEG];
__device__ int g_off_all[NDEG];
__device__ int g_cur_all[NDEG];
__device__ int g_scan_base;
__device__ int g_csr_all[ETOT];
__device__ float g_csrw[ETOT];

// ------------------------------ CSR build ----------------------------------
__global__ void k_count_all(const int* __restrict__ ei_vv, const int* __restrict__ ei_ss,
                            const int* __restrict__ ei_h,  const int* __restrict__ ei_in,
                            int Evv, int Ess, int Eh, int Ein) {
    int t = blockIdx.x * blockDim.x + threadIdx.x;
    if (t == 0) g_scan_base = 0;
    if (t < Evv) { atomicAdd(g_deg_all + ei_vv[Evv + t], 1); return; }
    t -= Evv;
    if (t < Ess) { atomicAdd(g_deg_all + NVn + ei_ss[Ess + t], 1); return; }
    t -= Ess;
    if (t < Eh)  { atomicAdd(g_deg_all + NVn + NSn + ei_h[Eh + t], 1); return; }
    t -= Eh;
    if (t < Ein) { atomicAdd(g_deg_all + NVn + 2 * NSn + ei_in[Ein + t], 1); }
}

// one-pass scan (arrival-ordered block bases) + dinv/sqd/cnt computation.
__global__ void k_scan(int n) {
    __shared__ int sh[1024];
    __shared__ int s_base;
    int i = blockIdx.x * 1024 + threadIdx.x;
    int v = (i < n) ? g_deg_all[i] : 0;
    sh[threadIdx.x] = v;
    __syncthreads();
    for (int o = 1; o < 1024; o <<= 1) {
        int t = (threadIdx.x >= o) ? sh[threadIdx.x - o] : 0;
        __syncthreads();
        sh[threadIdx.x] += t;
        __syncthreads();
    }
    if (threadIdx.x == 1023) s_base = atomicAdd(&g_scan_base, sh[1023]);
    __syncthreads();
    if (i < n) {
        int o = s_base + sh[threadIdx.x] - v;
        g_off_all[i] = o;
        g_cur_all[i] = o;
        if (i < NVn) {
            g_dinv_v[i] = (v > 0) ? rsqrtf((float)v) : 0.f;
        } else if (i < NVn + NSn) {
            int s = i - NVn;
            g_dinv_s[s] = (v > 0) ? rsqrtf((float)v) : 0.f;
            g_sqd_s[s]  = sqrtf((float)v);
            g_cntf_s[s] = (float)v;
        }
    }
}

__global__ void k_fill_all(const int* __restrict__ ei_vv, const int* __restrict__ et_vv,
                           const int* __restrict__ ei_ss, const int* __restrict__ ei_h,
                           const float* __restrict__ ew_h, const int* __restrict__ ei_in,
                           int Evv, int Ess, int Eh, int Ein) {
    int t = blockIdx.x * blockDim.x + threadIdx.x;
    if (t < Evv) {
        int slot = atomicAdd(g_cur_all + ei_vv[Evv + t], 1);
        g_csr_all[slot] = ei_vv[t] | (et_vv[t] << 20);
        return;
    }
    t -= Evv;
    if (t < Ess) {
        int slot = atomicAdd(g_cur_all + NVn + ei_ss[Ess + t], 1);
        g_csr_all[slot] = ei_ss[t];
        return;
    }
    t -= Ess;
    if (t < Eh) {
        int slot = atomicAdd(g_cur_all + NVn + NSn + ei_h[Eh + t], 1);
        g_csr_all[slot] = ei_h[t];
        g_csrw[slot] = ew_h[t];
        return;
    }
    t -= Eh;
    if (t < Ein) {
        int slot = atomicAdd(g_cur_all + NVn + 2 * NSn + ei_in[Ein + t], 1);
        g_csr_all[slot] = ei_in[t];
    }
}

// pad game_x + weight products.
__global__ void k_pad_prep(const float* __restrict__ x,
                           const float* __restrict__ W1_rel, const float* __restrict__ W1_root,
                           const float* __restrict__ b1,
                           const float* __restrict__ W12, const float* __restrict__ b12,
                           const float* __restrict__ W3_rel, const float* __restrict__ W32_l,
                           const float* __restrict__ W4_l,  const float* __restrict__ W42_l) {
    int t = blockIdx.x * blockDim.x + threadIdx.x;
    if (t < NVn * 8) {
        int v = t >> 3, i = t & 7;
        float xv = (i < 5) ? x[v * 5 + i] : 0.f;
        g_xpad[t] = xv;
        if (i < 5) g_z[(size_t)v * 40 + i] = xv;
    }
    if (t < 4 * 41 * 64) {
        int m = t / (41 * 64);
        int r = t % (41 * 64);
        int i = r >> 6, c = r & 63;
        const float* Wm = (m == 0) ? W3_rel : (m == 1) ? W32_l : (m == 2) ? W4_l : W42_l;
        float acc = 0.f;
        if (i < 40) {
            if (i < 35) {
#pragma unroll 8
                for (int j = 0; j < 64; j++) {
                    float wz;
                    if (i < 5)       wz = W1_root[i * 64 + j] + W12[i * 64 + j];
                    else if (i < 20) wz = W1_rel[(i - 5) * 64 + j];
                    else             wz = W12[(i - 15) * 64 + j];
                    acc += wz * Wm[j * 64 + c];
                }
                g_WzW[m][i * 64 + c] = acc;
            }
        } else {
#pragma unroll 8
            for (int j = 0; j < 64; j++) acc += (b1[j] + b12[j]) * Wm[j * 64 + c];
            g_c0W[m][c] = acc;
        }
    }
}

// --------------------------- game-graph kernels ----------------------------
__global__ void k_rgcn_hop1(float* __restrict__ p1) {
    int gt = blockIdx.x * blockDim.x + threadIdx.x;
    int w = gt >> 5, lane = gt & 31;
    if (w >= NVn) return;
    int base = g_off_all[w], deg = g_deg_all[w];
    int sub = lane >> 3, li = lane & 7;
    float a0 = 0.f, a1 = 0.f, a2 = 0.f, ah = 0.f;
    float c0 = 0.f, c1 = 0.f, c2 = 0.f;
#pragma unroll 4
    for (int j = sub; j < deg; j += 4) {
        int pk = g_csr_all[base + j];
        int s = pk & 0xFFFFF, t = pk >> 20;
        float xv = g_xpad[(size_t)s * 8 + li];
        ah += g_dinv_v[s] * xv;
        if (t == 0)      { a0 += xv; c0 += 1.f; }
        else if (t == 1) { a1 += xv; c1 += 1.f; }
        else             { a2 += xv; c2 += 1.f; }
    }
#pragma unroll
    for (int o = 8; o < 32; o <<= 1) {
        a0 += __shfl_xor_sync(0xffffffffu, a0, o);
        a1 += __shfl_xor_sync(0xffffffffu, a1, o);
        a2 += __shfl_xor_sync(0xffffffffu, a2, o);
        ah += __shfl_xor_sync(0xffffffffu, ah, o);
        c0 += __shfl_xor_sync(0xffffffffu, c0, o);
        c1 += __shfl_xor_sync(0xffffffffu, c1, o);
        c2 += __shfl_xor_sync(0xffffffffu, c2, o);
    }
    if (sub == 0) {
        float dvd = g_dinv_v[w];
        float h1 = dvd * ah;
        if (li < 5) {
            float* zz = g_z + (size_t)w * 40;
            zz[5 + li]  = a0 / fmaxf(c0, 1.f);
            zz[10 + li] = a1 / fmaxf(c1, 1.f);
            zz[15 + li] = a2 / fmaxf(c2, 1.f);
            zz[20 + li] = h1;
            zz[35 + li] = 0.f;
        }
        p1[(size_t)w * 8 + li] = dvd * h1;
    }
}

__global__ void k_hop8_gather(const float* __restrict__ pprev, float* __restrict__ pnext,
                              int k, int write_p) {
    int gt = blockIdx.x * blockDim.x + threadIdx.x;
    int w = gt >> 5, lane = gt & 31;
    if (w >= NVn) return;
    int base = g_off_all[w], deg = g_deg_all[w];
    int sub = lane >> 3, li = lane & 7;
    float acc = 0.f;
#pragma unroll 4
    for (int j = sub; j < deg; j += 4) {
        int s = g_csr_all[base + j] & 0xFFFFF;
        acc += pprev[(size_t)s * 8 + li];
    }
#pragma unroll
    for (int o = 8; o < 32; o <<= 1)
        acc += __shfl_xor_sync(0xffffffffu, acc, o);
    if (sub == 0) {
        float dv = g_dinv_v[w];
        float h = dv * acc;
        if (li < 5) g_z[(size_t)w * 40 + 20 + k * 5 + li] = h;
        if (write_p) pnext[(size_t)w * 8 + li] = dv * h;
    }
}

// ----------------- ei_h + ei_in z-gathers (warp per node) ------------------
__global__ void k_gather_hin() {
    int gt = blockIdx.x * blockDim.x + threadIdx.x;
    int w = gt >> 5, lane = gt & 31;
    if (w >= NSn) return;
    int sub = lane >> 4, li = lane & 15;

    {   // ei_h: weighted + unweighted + weight-sum
        int base = g_off_all[NVn + NSn + w], deg = g_deg_all[NVn + NSn + w];
        float4 aW = make_float4(0.f, 0.f, 0.f, 0.f);
        float4 aU = make_float4(0.f, 0.f, 0.f, 0.f);
        float wsum = 0.f;
        for (int j0 = 0; j0 < deg; j0 += 32) {
            int idx = j0 + lane;
            int sl = 0; float wl = 0.f;
            if (idx < deg) { sl = g_csr_all[base + idx]; wl = g_csrw[base + idx]; }
            wsum += wl;
            int mres = deg - j0; if (mres > 32) mres = 32;
#pragma unroll
            for (int jj = 0; jj < 16; jj++) {
                int e2 = 2 * jj + sub;
                int s = __shfl_sync(0xffffffffu, sl, e2);
                float wt = __shfl_sync(0xffffffffu, wl, e2);
                if (e2 < mres && li < 10) {
                    float4 t = ((const float4*)(g_z + (size_t)s * 40))[li];
                    aU.x += t.x; aU.y += t.y; aU.z += t.z; aU.w += t.w;
                    aW.x += wt * t.x; aW.y += wt * t.y; aW.z += wt * t.z; aW.w += wt * t.w;
                }
            }
        }
        aU.x += __shfl_xor_sync(0xffffffffu, aU.x, 16);
        aU.y += __shfl_xor_sync(0xffffffffu, aU.y, 16);
        aU.z += __shfl_xor_sync(0xffffffffu, aU.z, 16);
        aU.w += __shfl_xor_sync(0xffffffffu, aU.w, 16);
        aW.x += __shfl_xor_sync(0xffffffffu, aW.x, 16);
        aW.y += __shfl_xor_sync(0xffffffffu, aW.y, 16);
        aW.z += __shfl_xor_sync(0xffffffffu, aW.z, 16);
        aW.w += __shfl_xor_sync(0xffffffffu, aW.w, 16);
#pragma unroll
        for (int o = 16; o; o >>= 1) wsum += __shfl_xor_sync(0xffffffffu, wsum, o);
        if (sub == 0 && li < 9) {
            ((float4*)(g_aggu + (size_t)w * 36))[li] = aU;
            ((float4*)(g_aggw + (size_t)w * 36))[li] = aW;
        }
        if (lane == 0) g_wsum[w] = wsum;
    }
    {   // ei_in: plain sum
        int base = g_off_all[NVn + 2 * NSn + w], deg = g_deg_all[NVn + 2 * NSn + w];
        float4 aU = make_float4(0.f, 0.f, 0.f, 0.f);
        for (int j0 = 0; j0 < deg; j0 += 32) {
            int idx = j0 + lane;
            int sl = (idx < deg) ? g_csr_all[base + idx] : 0;
            int mres = deg - j0; if (mres > 32) mres = 32;
#pragma unroll
            for (int jj = 0; jj < 16; jj++) {
                int e2 = 2 * jj + sub;
                int s = __shfl_sync(0xffffffffu, sl, e2);
                if (e2 < mres && li < 10) {
                    float4 t = ((const float4*)(g_z + (size_t)s * 40))[li];
                    aU.x += t.x; aU.y += t.y; aU.z += t.z; aU.w += t.w;
                }
            }
        }
        aU.x += __shfl_xor_sync(0xffffffffu, aU.x, 16);
        aU.y += __shfl_xor_sync(0xffffffffu, aU.y, 16);
        aU.z += __shfl_xor_sync(0xffffffffu, aU.z, 16);
        aU.w += __shfl_xor_sync(0xffffffffu, aU.w, 16);
        if (sub == 0 && li < 9)
            ((float4*)(g_aggin + (size_t)w * 36))[li] = aU;
    }
}

// ---------------------- tiled GEMM building blocks -------------------------
__device__ __forceinline__ void stage_w(float* sW, const float* __restrict__ g, int n) {
    for (int e = threadIdx.x; e < n; e += 256) sW[e] = g[e];
}
__device__ __forceinline__ void stage_a64(float* sA, const float* __restrict__ g,
                                          int vbase, const float* sScale) {
    for (int e = threadIdx.x; e < 64 * 64; e += 256) {
        int n = e >> 6, j = e & 63;
        int v = vbase + n; if (v >= NSn) v = NSn - 1;
        float s = sScale ? sScale[n] : 1.f;
        sA[j * AST + n] = g[(size_t)v * 64 + j] * s;
    }
}
__device__ __forceinline__ void stage_a36(float* sA, const float* __restrict__ g,
                                          int vbase, const float* sScale) {
    for (int e = threadIdx.x; e < 64 * 36; e += 256) {
        int n = e / 36, j = e - n * 36;
        int v = vbase + n; if (v >= NSn) v = NSn - 1;
        float s = sScale ? sScale[n] : 1.f;
        sA[j * AST + n] = g[(size_t)v * 36 + j] * s;
    }
}
__device__ __forceinline__ void gemm16(const float* __restrict__ sW, const float* __restrict__ sA,
                                       int J, int c4, int n0, float acc[4][4]) {
#pragma unroll 4
    for (int j = 0; j < J; j++) {
        float4 wv = *(const float4*)(sW + j * 64 + c4);
        float4 av = *(const float4*)(sA + j * AST + n0);
        acc[0][0] += av.x * wv.x; acc[0][1] += av.x * wv.y; acc[0][2] += av.x * wv.z; acc[0][3] += av.x * wv.w;
        acc[1][0] += av.y * wv.x; acc[1][1] += av.y * wv.y; acc[1][2] += av.y * wv.z; acc[1][3] += av.y * wv.w;
        acc[2][0] += av.z * wv.x; acc[2][1] += av.z * wv.y; acc[2][2] += av.z * wv.z; acc[2][3] += av.z * wv.w;
        acc[3][0] += av.w * wv.x; acc[3][1] += av.w * wv.y; acc[3][2] += av.w * wv.z; acc[3][3] += av.w * wv.w;
    }
}

// --------------------- state dense chain (layers 2-5) ----------------------
__global__ void __launch_bounds__(256) k_state_dense(
        const float* __restrict__ state_x, const float* __restrict__ W3_root,
        const float* __restrict__ b3, const float* __restrict__ W32_r,
        const float* __restrict__ b32, const float* __restrict__ W4_r,
        const float* __restrict__ b4, const float* __restrict__ W42_r,
        const float* __restrict__ b42) {
    __shared__ float sW[64 * 64];
    __shared__ float sA[64 * AST];
    __shared__ float sInvH[64], sInvI[64], sWsum[64], sPosH[64], sPosI[64], sDin[64];
    int tid = threadIdx.x;
    int vbase = blockIdx.x * 64;
    if (tid < 64) {
        int v = vbase + tid; if (v >= NSn) v = NSn - 1;
        float ch = (float)g_deg_all[NVn + NSn + v];
        float ci = (float)g_deg_all[NVn + 2 * NSn + v];
        sInvH[tid] = 1.f / fmaxf(ch, 1.f);
        sInvI[tid] = 1.f / fmaxf(ci, 1.f);
        sPosH[tid] = (ch > 0.f) ? 1.f : 0.f;
        sPosI[tid] = (ci > 0.f) ? 1.f : 0.f;
        sWsum[tid] = g_wsum[v];
        sDin[tid]  = g_dinv_s[v];
    }
    __syncthreads();   // scale arrays visible to all staging below
    int c4 = (tid & 15) * 4, n0 = (tid >> 4) * 4;
    float acc[4][4];
    float4 bv, cv;

    // ---- L2: graph_conv ----
    stage_a36(sA, g_aggw, vbase, nullptr);
    stage_w(sW, g_WzW[0], 35 * 64);
    __syncthreads();
    bv = *(const float4*)(b3 + c4);
    cv = *(const float4*)(g_c0W[0] + c4);
#pragma unroll
    for (int i = 0; i < 4; i++) {
        float ws = sWsum[n0 + i];
        acc[i][0] = bv.x + ws * cv.x; acc[i][1] = bv.y + ws * cv.y;
        acc[i][2] = bv.z + ws * cv.z; acc[i][3] = bv.w + ws * cv.w;
    }
    gemm16(sW, sA, 35, c4, n0, acc);
    __syncthreads();
    for (int e = tid; e < 64 * 5; e += 256) {
        int n = e / 5, j = e - n * 5;
        int v = vbase + n; if (v >= NSn) v = NSn - 1;
        sA[j * AST + n] = state_x[(size_t)v * 5 + j];
    }
    stage_w(sW, W3_root, 5 * 64);
    __syncthreads();
    gemm16(sW, sA, 5, c4, n0, acc);
#pragma unroll
    for (int i = 0; i < 4; i++) {
        int v = vbase + n0 + i;
        if (v < NSn) {
            float4 o = make_float4(fmaxf(acc[i][0], 0.f), fmaxf(acc[i][1], 0.f),
                                   fmaxf(acc[i][2], 0.f), fmaxf(acc[i][3], 0.f));
            *(float4*)(g_ta + (size_t)v * 64 + c4) = o;
        }
    }
    __syncthreads();

    // ---- L3: conv32 ----
    stage_a36(sA, g_aggu, vbase, sInvH);
    stage_w(sW, g_WzW[1], 35 * 64);
    __syncthreads();
    bv = *(const float4*)(b32 + c4);
    cv = *(const float4*)(g_c0W[1] + c4);
#pragma unroll
    for (int i = 0; i < 4; i++) {
        float p = sPosH[n0 + i];
        acc[i][0] = bv.x + p * cv.x; acc[i][1] = bv.y + p * cv.y;
        acc[i][2] = bv.z + p * cv.z; acc[i][3] = bv.w + p * cv.w;
    }
    gemm16(sW, sA, 35, c4, n0, acc);
    __syncthreads();
    stage_a64(sA, g_ta, vbase, nullptr);
    stage_w(sW, W32_r, 64 * 64);
    __syncthreads();
    gemm16(sW, sA, 64, c4, n0, acc);
#pragma unroll
    for (int i = 0; i < 4; i++) {
        int v = vbase + n0 + i;
        if (v < NSn) {
            float4 o = make_float4(fmaxf(acc[i][0], 0.f), fmaxf(acc[i][1], 0.f),
                                   fmaxf(acc[i][2], 0.f), fmaxf(acc[i][3], 0.f));
            *(float4*)(g_tb + (size_t)v * 64 + c4) = o;
        }
    }
    __syncthreads();

    // ---- L4: conv4 ----
    stage_a36(sA, g_aggin, vbase, sInvI);
    stage_w(sW, g_WzW[2], 35 * 64);
    __syncthreads();
    bv = *(const float4*)(b4 + c4);
    cv = *(const float4*)(g_c0W[2] + c4);
#pragma unroll
    for (int i = 0; i < 4; i++) {
        float p = sPosI[n0 + i];
        acc[i][0] = bv.x + p * cv.x; acc[i][1] = bv.y + p * cv.y;
        acc[i][2] = bv.z + p * cv.z; acc[i][3] = bv.w + p * cv.w;
    }
    gemm16(sW, sA, 35, c4, n0, acc);
    __syncthreads();
    stage_a64(sA, g_tb, vbase, nullptr);
    stage_w(sW, W4_r, 64 * 64);
    __syncthreads();
    gemm16(sW, sA, 64, c4, n0, acc);
#pragma unroll
    for (int i = 0; i < 4; i++) {
        int v = vbase + n0 + i;
        if (v < NSn) {
            float4 o = make_float4(fmaxf(acc[i][0], 0.f), fmaxf(acc[i][1], 0.f),
                                   fmaxf(acc[i][2], 0.f), fmaxf(acc[i][3], 0.f));
            *(float4*)(g_ta + (size_t)v * 64 + c4) = o;
        }
    }
    __syncthreads();

    // ---- L5: conv42 -> sx5, pin ----
    stage_a36(sA, g_aggin, vbase, sInvI);
    stage_w(sW, g_WzW[3], 35 * 64);
    __syncthreads();
    bv = *(const float4*)(b42 + c4);
    cv = *(const float4*)(g_c0W[3] + c4);
#pragma unroll
    for (int i = 0; i < 4; i++) {
        float p = sPosI[n0 + i];
        acc[i][0] = bv.x + p * cv.x; acc[i][1] = bv.y + p * cv.y;
        acc[i][2] = bv.z + p * cv.z; acc[i][3] = bv.w + p * cv.w;
    }
    gemm16(sW, sA, 35, c4, n0, acc);
    __syncthreads();
    stage_a64(sA, g_ta, vbase, nullptr);
    stage_w(sW, W42_r, 64 * 64);
    __syncthreads();
    gemm16(sW, sA, 64, c4, n0, acc);
#pragma unroll
    for (int i = 0; i < 4; i++) {
        int v = vbase + n0 + i;
        if (v < NSn) {
            float dv = sDin[n0 + i];
            float4 o = make_float4(fmaxf(acc[i][0], 0.f), fmaxf(acc[i][1], 0.f),
                                   fmaxf(acc[i][2], 0.f), fmaxf(acc[i][3], 0.f));
            *(float4*)(g_sx5 + (size_t)v * 64 + c4) = o;
            *(float4*)(g_pin + (size_t)v * 64 + c4) =
                make_float4(dv * o.x, dv * o.y, dv * o.z, dv * o.w);
        }
    }
}

// TAG-state hop, p-form.
__global__ void k_hop64p(const float* __restrict__ pprev, float* __restrict__ pnext) {
    int gt = blockIdx.x * blockDim.x + threadIdx.x;
    int w = gt >> 5, lane = gt & 31;
    if (w >= NSn) return;
    int base = g_off_all[NVn + w], deg = g_deg_all[NVn + w];
    int sub = lane >> 4, li = lane & 15;
    float4 a = make_float4(0.f, 0.f, 0.f, 0.f);
    for (int j0 = 0; j0 < deg; j0 += 32) {
        int idx = j0 + lane;
        int sl = (idx < deg) ? g_csr_all[base + idx] : 0;
        int mres = deg - j0; if (mres > 32) mres = 32;
#pragma unroll
        for (int jj = 0; jj < 16; jj++) {
            int e2 = 2 * jj + sub;
            int s = __shfl_sync(0xffffffffu, sl, e2);
            if (e2 < mres) {
                float4 v = ((const float4*)(pprev + (size_t)s * 64))[li];
                a.x += v.x; a.y += v.y; a.z += v.z; a.w += v.w;
            }
        }
    }
    a.x += __shfl_xor_sync(0xffffffffu, a.x, 16);
    a.y += __shfl_xor_sync(0xffffffffu, a.y, 16);
    a.z += __shfl_xor_sync(0xffffffffu, a.z, 16);
    a.w += __shfl_xor_sync(0xffffffffu, a.w, 16);
    if (sub == 0) {
        float dv = g_dinv_s[w];
        float dv2 = dv * dv;
        ((float4*)(pnext + (size_t)w * 64))[li] =
            make_float4(dv2 * a.x, dv2 * a.y, dv2 * a.z, dv2 * a.w);
    }
}

// conv5 sum gather over ei_ss.
__global__ void k_sum64_gather(const float* __restrict__ feat, float* __restrict__ acc) {
    int gt = blockIdx.x * blockDim.x + threadIdx.x;
    int w = gt >> 5, lane = gt & 31;
    if (w >= NSn) return;
    int base = g_off_all[NVn + w], deg = g_deg_all[NVn + w];
    int sub = lane >> 4, li = lane & 15;
    float4 a = make_float4(0.f, 0.f, 0.f, 0.f);
    for (int j0 = 0; j0 < deg; j0 += 32) {
        int idx = j0 + lane;
        int sl = (idx < deg) ? g_csr_all[base + idx] : 0;
        int mres = deg - j0; if (mres > 32) mres = 32;
#pragma unroll
        for (int jj = 0; jj < 16; jj++) {
            int e2 = 2 * jj + sub;
            int s = __shfl_sync(0xffffffffu, sl, e2);
            if (e2 < mres) {
                float4 v = ((const float4*)(feat + (size_t)s * 64))[li];
                a.x += v.x; a.y += v.y; a.z += v.z; a.w += v.w;
            }
        }
    }
    a.x += __shfl_xor_sync(0xffffffffu, a.x, 16);
    a.y += __shfl_xor_sync(0xffffffffu, a.y, 16);
    a.z += __shfl_xor_sync(0xffffffffu, a.z, 16);
    a.w += __shfl_xor_sync(0xffffffffu, a.w, 16);
    if (sub == 0)
        ((float4*)(acc + (size_t)w * 64))[li] = a;
}

// TAG output dense: sx6 = relu(b2 + sx5@W2_0 + sum_k (sqd*pk_k)@W2_{k+1})
__global__ void __launch_bounds__(256) k_tag_dense(
        const float* __restrict__ W2, const float* __restrict__ b2) {
    __shared__ float sW[64 * 64];
    __shared__ float sA[64 * AST];
    __shared__ float sSq[64];
    int tid = threadIdx.x;
    int vbase = blockIdx.x * 64;
    if (tid < 64) {
        int v = vbase + tid; if (v >= NSn) v = NSn - 1;
        sSq[tid] = g_sqd_s[v];
    }
    __syncthreads();   // sSq visible before staged use
    int c4 = (tid & 15) * 4, n0 = (tid >> 4) * 4;
    float acc[4][4];
    float4 bv;

    stage_a64(sA, g_sx5, vbase, nullptr);
    stage_w(sW, W2, 64 * 64);
    __syncthreads();
    bv = *(const float4*)(b2 + c4);
#pragma unroll
    for (int i = 0; i < 4; i++) {
        acc[i][0] = bv.x; acc[i][1] = bv.y; acc[i][2] = bv.z; acc[i][3] = bv.w;
    }
    gemm16(sW, sA, 64, c4, n0, acc);
    __syncthreads();
#pragma unroll
    for (int k = 0; k < 3; k++) {
        stage_a64(sA, g_pk[k], vbase, sSq);
        stage_w(sW, W2 + (size_t)(k + 1) * 4096, 64 * 64);
        __syncthreads();
        gemm16(sW, sA, 64, c4, n0, acc);
        __syncthreads();
    }
#pragma unroll
    for (int i = 0; i < 4; i++) {
        int v = vbase + n0 + i;
        if (v < NSn) {
            float4 o = make_float4(fmaxf(acc[i][0], 0.f), fmaxf(acc[i][1], 0.f),
                                   fmaxf(acc[i][2], 0.f), fmaxf(acc[i][3], 0.f));
            *(float4*)(g_sx6 + (size_t)v * 64 + c4) = o;
        }
    }
}

// conv5 dense + head.
__global__ void __launch_bounds__(256) k_conv5_head(
        const float* __restrict__ W5_l, const float* __restrict__ W5_r,
        const float* __restrict__ b5, const float* __restrict__ Wl,
        const float* __restrict__ bl, float* __restrict__ out) {
    __shared__ float sW[64 * 64];
    __shared__ float sA[64 * AST];
    __shared__ float sInv[64];
    int tid = threadIdx.x;
    int vbase = blockIdx.x * 64;
    if (tid < 64) {
        int v = vbase + tid; if (v >= NSn) v = NSn - 1;
        sInv[tid] = 1.f / fmaxf(g_cntf_s[v], 1.f);
    }
    __syncthreads();   // FIX: sInv must be visible before stage_a64 reads it
    int c4 = (tid & 15) * 4, n0 = (tid >> 4) * 4;
    float acc[4][4];
    float4 bv;

    stage_a64(sA, g_accs5, vbase, sInv);
    stage_w(sW, W5_l, 64 * 64);
    __syncthreads();
    bv = *(const float4*)(b5 + c4);
#pragma unroll
    for (int i = 0; i < 4; i++) {
        acc[i][0] = bv.x; acc[i][1] = bv.y; acc[i][2] = bv.z; acc[i][3] = bv.w;
    }
    gemm16(sW, sA, 64, c4, n0, acc);
    __syncthreads();
    stage_a64(sA, g_sx6, vbase, nullptr);
    stage_w(sW, W5_r, 64 * 64);
    __syncthreads();
    gemm16(sW, sA, 64, c4, n0, acc);
    __syncthreads();
#pragma unroll
    for (int i = 0; i < 4; i++) {
#pragma unroll
        for (int k = 0; k < 4; k++)
            sA[(c4 + k) * AST + n0 + i] = fmaxf(acc[i][k], 0.f);
    }
    stage_w(sW, Wl, 64 * 8);
    __syncthreads();
#pragma unroll
    for (int u = 0; u < 2; u++) {
        int idx = tid * 2 + u;
        int n = idx >> 3, o = idx & 7;
        float s = bl[o];
#pragma unroll 8
        for (int j = 0; j < 64; j++) s += sA[j * AST + n] * sW[j * 8 + o];
        int v = vbase + n;
        if (v < NSn) out[(size_t)v * 8 + o] = s;
    }
}

// ------------------------------- launch ------------------------------------

extern "C" void kernel_launch(void* const* d_in, const int* in_sizes, int n_in,
                              void* d_out, int out_size) {
    const float* game_x  = (const float*)d_in[0];
    const float* state_x = (const float*)d_in[1];
    const int*   ei_vv   = (const int*)d_in[2];
    const int*   et_vv   = (const int*)d_in[3];
    const int*   ei_h    = (const int*)d_in[4];
    const float* ew_h    = (const float*)d_in[5];
    const int*   ei_in   = (const int*)d_in[6];
    const int*   ei_ss   = (const int*)d_in[7];
    const float* W1_rel  = (const float*)d_in[8];
    const float* W1_root = (const float*)d_in[9];
    const float* b1      = (const float*)d_in[10];
    const float* W12     = (const float*)d_in[11];
    const float* b12     = (const float*)d_in[12];
    const float* W2      = (const float*)d_in[13];
    const float* b2      = (const float*)d_in[14];
    const float* W3_rel  = (const float*)d_in[15];
    const float* W3_root = (const float*)d_in[16];
    const float* b3      = (const float*)d_in[17];
    const float* W32_l   = (const float*)d_in[18];
    const float* W32_r   = (const float*)d_in[19];
    const float* b32     = (const float*)d_in[20];
    const float* W4_l    = (const float*)d_in[21];
    const float* W4_r    = (const float*)d_in[22];
    const float* b4      = (const float*)d_in[23];
    const float* W42_l   = (const float*)d_in[24];
    const float* W42_r   = (const float*)d_in[25];
    const float* b42     = (const float*)d_in[26];
    const float* W5_l    = (const float*)d_in[27];
    const float* W5_r    = (const float*)d_in[28];
    const float* b5      = (const float*)d_in[29];
    const float* Wl      = (const float*)d_in[30];
    const float* bl      = (const float*)d_in[31];
    float* out = (float*)d_out;

    int Evv = in_sizes[2] / 2;
    int Eh  = in_sizes[4] / 2;
    int Ein = in_sizes[6] / 2;
    int Ess = in_sizes[7] / 2;
    int Etot = Evv + Ess + Eh + Ein;

    int* pi_deg;
    float *p_pv, *p_pin, *p_pk, *p_sx6, *p_accs5;
    cudaGetSymbolAddress((void**)&pi_deg,  g_deg_all);
    cudaGetSymbolAddress((void**)&p_pv,    g_pv);
    cudaGetSymbolAddress((void**)&p_pin,   g_pin);
    cudaGetSymbolAddress((void**)&p_pk,    g_pk);
    cudaGetSymbolAddress((void**)&p_sx6,   g_sx6);
    cudaGetSymbolAddress((void**)&p_accs5, g_accs5);

    float* p_pv0 = p_pv;
    float* p_pv1 = p_pv + (size_t)NVn * 8;
    float* p_pk0 = p_pk;
    float* p_pk1 = p_pk + (size_t)NSn * 64;
    float* p_pk2 = p_pk1 + (size_t)NSn * 64;

    const int T = 256;
    auto nb = [](long n, int t) { return (int)((n + t - 1) / t); };
    int nbv_warp = nb((long)NVn * 32, T);
    int nbs_warp = nb((long)NSn * 32, T);
    int ndense = nb(NSn, 64);

    // 0) zero unified degree array
    cudaMemsetAsync(pi_deg, 0, (size_t)NDEG * 4, 0);

    // 1) unified CSR build
    k_count_all<<<nb(Etot, T), T>>>(ei_vv, ei_ss, ei_h, ei_in, Evv, Ess, Eh, Ein);
    k_scan<<<nb(NDEG, 1024), 1024>>>(NDEG);
    k_fill_all<<<nb(Etot, T), T>>>(ei_vv, et_vv, ei_ss, ei_h, ew_h, ei_in,
                                   Evv, Ess, Eh, Ein);

    // 2) pad + weight prep
    k_pad_prep<<<nb((long)NVn * 8, T), T>>>(game_x, W1_rel, W1_root, b1, W12, b12,
                                            W3_rel, W32_l, W4_l, W42_l);

    // 3) game graph -> z
    k_rgcn_hop1<<<nbv_warp, T>>>(p_pv0);
    k_hop8_gather<<<nbv_warp, T>>>(p_pv0, p_pv1, 1, 1);
    k_hop8_gather<<<nbv_warp, T>>>(p_pv1, p_pv0, 2, 0);

    // 4) ei_h + ei_in gathers, then state dense chain
    k_gather_hin<<<nbs_warp, T>>>();
    k_state_dense<<<ndense, 256>>>(state_x, W3_root, b3, W32_r, b32,
                                   W4_r, b4, W42_r, b42);

    // 5) TAG-state hops + dense output
    k_hop64p<<<nbs_warp, T>>>(p_pin, p_pk0);
    k_hop64p<<<nbs_warp, T>>>(p_pk0, p_pk1);
    k_hop64p<<<nbs_warp, T>>>(p_pk1, p_pk2);
    k_tag_dense<<<ndense, 256>>>(W2, b2);

    // 6) conv5 gather + dense + head
    k_sum64_gather<<<nbs_warp, T>>>(p_sx6, p_accs5);
    k_conv5_head<<<ndense, 256>>>(W5_l, W5_r, b5, Wl, bl, out);
}

// round 13
// speedup vs baseline: 2.4983x; 1.0044x over previous
#include <cuda_runtime.h>
#include <math.h>

// ---------------------------------------------------------------------------
// StateModelEncoder — round 13: round-12 tiled-GEMM structure + pad/prep
// merged into the CSR count pass, z rows shrunk 40->36 floats. 15 launches.
// ---------------------------------------------------------------------------

#define NVn 100000
#define NSn 50000
#define EVVmax 1600000
#define ESSmax 800000
#define EHmax  800000
#define EINmax 800000
#define NDEG   (NVn + 3 * NSn)
#define ETOT   (EVVmax + ESSmax + EHmax + EINmax)
#define ZW     36                      // z row width (35 used + 1 zero pad)
#define AST    68                      // transposed-act smem row stride

// ------------------------- scratch (device globals) ------------------------
__device__ __align__(16) float g_xpad[NVn * 8];
__device__ float g_dinv_v[NVn];
__device__ __align__(16) float g_z[(size_t)NVn * ZW];
__device__ __align__(16) float g_pv[2][NVn * 8];
__device__ __align__(16) float g_WzW[4][40 * 64];
__device__ float g_c0W[4][64];
__device__ __align__(16) float g_aggw[(size_t)NSn * 36];
__device__ __align__(16) float g_aggu[(size_t)NSn * 36];
__device__ __align__(16) float g_aggin[(size_t)NSn * 36];
__device__ float g_wsum[NSn];
__device__ __align__(16) float g_ta[(size_t)NSn * 64];
__device__ __align__(16) float g_tb[(size_t)NSn * 64];
__device__ __align__(16) float g_sx5[(size_t)NSn * 64];
__device__ __align__(16) float g_pin[(size_t)NSn * 64];
__device__ __align__(16) float g_pk[3][(size_t)NSn * 64];
__device__ __align__(16) float g_sx6[(size_t)NSn * 64];
__device__ __align__(16) float g_accs5[(size_t)NSn * 64];
__device__ float g_dinv_s[NSn];
__device__ float g_sqd_s[NSn];
__device__ float g_cntf_s[NSn];

// unified CSR
__device__ int g_deg_all[NDEG];
__device__ int g_off_all[NDEG];
__device__ int g_cur_all[NDEG];
__device__ int g_scan_base;
__device__ int g_csr_all[ETOT];
__device__ float g_csrw[ETOT];

// ------------------ CSR count + pad + weight prep (fused) ------------------
__global__ void k_count_pad_prep(
        const int* __restrict__ ei_vv, const int* __restrict__ ei_ss,
        const int* __restrict__ ei_h,  const int* __restrict__ ei_in,
        int Evv, int Ess, int Eh, int Ein,
        const float* __restrict__ x,
        const float* __restrict__ W1_rel, const float* __restrict__ W1_root,
        const float* __restrict__ b1,
        const float* __restrict__ W12, const float* __restrict__ b12,
        const float* __restrict__ W3_rel, const float* __restrict__ W32_l,
        const float* __restrict__ W4_l,  const float* __restrict__ W42_l) {
    int t0 = blockIdx.x * blockDim.x + threadIdx.x;
    if (t0 == 0) g_scan_base = 0;

    // pad game_x (+ z cols 0..4)
    if (t0 < NVn * 8) {
        int v = t0 >> 3, i = t0 & 7;
        float xv = (i < 5) ? x[v * 5 + i] : 0.f;
        g_xpad[t0] = xv;
        if (i < 5) g_z[(size_t)v * ZW + i] = xv;
    }
    // weight products
    if (t0 < 4 * 41 * 64) {
        int m = t0 / (41 * 64);
        int r = t0 % (41 * 64);
        int i = r >> 6, c = r & 63;
        const float* Wm = (m == 0) ? W3_rel : (m == 1) ? W32_l : (m == 2) ? W4_l : W42_l;
        float acc = 0.f;
        if (i < 40) {
            if (i < 35) {
#pragma unroll 8
                for (int j = 0; j < 64; j++) {
                    float wz;
                    if (i < 5)       wz = W1_root[i * 64 + j] + W12[i * 64 + j];
                    else if (i < 20) wz = W1_rel[(i - 5) * 64 + j];
                    else             wz = W12[(i - 15) * 64 + j];
                    acc += wz * Wm[j * 64 + c];
                }
                g_WzW[m][i * 64 + c] = acc;
            }
        } else {
#pragma unroll 8
            for (int j = 0; j < 64; j++) acc += (b1[j] + b12[j]) * Wm[j * 64 + c];
            g_c0W[m][c] = acc;
        }
    }

    // degree counting (unified)
    int t = t0;
    if (t < Evv) { atomicAdd(g_deg_all + ei_vv[Evv + t], 1); return; }
    t -= Evv;
    if (t < Ess) { atomicAdd(g_deg_all + NVn + ei_ss[Ess + t], 1); return; }
    t -= Ess;
    if (t < Eh)  { atomicAdd(g_deg_all + NVn + NSn + ei_h[Eh + t], 1); return; }
    t -= Eh;
    if (t < Ein) { atomicAdd(g_deg_all + NVn + 2 * NSn + ei_in[Ein + t], 1); }
}

// one-pass scan (arrival-ordered block bases) + dinv/sqd/cnt.
__global__ void k_scan(int n) {
    __shared__ int sh[1024];
    __shared__ int s_base;
    int i = blockIdx.x * 1024 + threadIdx.x;
    int v = (i < n) ? g_deg_all[i] : 0;
    sh[threadIdx.x] = v;
    __syncthreads();
    for (int o = 1; o < 1024; o <<= 1) {
        int t = (threadIdx.x >= o) ? sh[threadIdx.x - o] : 0;
        __syncthreads();
        sh[threadIdx.x] += t;
        __syncthreads();
    }
    if (threadIdx.x == 1023) s_base = atomicAdd(&g_scan_base, sh[1023]);
    __syncthreads();
    if (i < n) {
        int o = s_base + sh[threadIdx.x] - v;
        g_off_all[i] = o;
        g_cur_all[i] = o;
        if (i < NVn) {
            g_dinv_v[i] = (v > 0) ? rsqrtf((float)v) : 0.f;
        } else if (i < NVn + NSn) {
            int s = i - NVn;
            g_dinv_s[s] = (v > 0) ? rsqrtf((float)v) : 0.f;
            g_sqd_s[s]  = sqrtf((float)v);
            g_cntf_s[s] = (float)v;
        }
    }
}

__global__ void k_fill_all(const int* __restrict__ ei_vv, const int* __restrict__ et_vv,
                           const int* __restrict__ ei_ss, const int* __restrict__ ei_h,
                           const float* __restrict__ ew_h, const int* __restrict__ ei_in,
                           int Evv, int Ess, int Eh, int Ein) {
    int t = blockIdx.x * blockDim.x + threadIdx.x;
    if (t < Evv) {
        int slot = atomicAdd(g_cur_all + ei_vv[Evv + t], 1);
        g_csr_all[slot] = ei_vv[t] | (et_vv[t] << 20);
        return;
    }
    t -= Evv;
    if (t < Ess) {
        int slot = atomicAdd(g_cur_all + NVn + ei_ss[Ess + t], 1);
        g_csr_all[slot] = ei_ss[t];
        return;
    }
    t -= Ess;
    if (t < Eh) {
        int slot = atomicAdd(g_cur_all + NVn + NSn + ei_h[Eh + t], 1);
        g_csr_all[slot] = ei_h[t];
        g_csrw[slot] = ew_h[t];
        return;
    }
    t -= Eh;
    if (t < Ein) {
        int slot = atomicAdd(g_cur_all + NVn + 2 * NSn + ei_in[Ein + t], 1);
        g_csr_all[slot] = ei_in[t];
    }
}

// --------------------------- game-graph kernels ----------------------------
__global__ void k_rgcn_hop1(float* __restrict__ p1) {
    int gt = blockIdx.x * blockDim.x + threadIdx.x;
    int w = gt >> 5, lane = gt & 31;
    if (w >= NVn) return;
    int base = g_off_all[w], deg = g_deg_all[w];
    int sub = lane >> 3, li = lane & 7;
    float a0 = 0.f, a1 = 0.f, a2 = 0.f, ah = 0.f;
    float c0 = 0.f, c1 = 0.f, c2 = 0.f;
#pragma unroll 4
    for (int j = sub; j < deg; j += 4) {
        int pk = g_csr_all[base + j];
        int s = pk & 0xFFFFF, t = pk >> 20;
        float xv = g_xpad[(size_t)s * 8 + li];
        ah += g_dinv_v[s] * xv;
        if (t == 0)      { a0 += xv; c0 += 1.f; }
        else if (t == 1) { a1 += xv; c1 += 1.f; }
        else             { a2 += xv; c2 += 1.f; }
    }
#pragma unroll
    for (int o = 8; o < 32; o <<= 1) {
        a0 += __shfl_xor_sync(0xffffffffu, a0, o);
        a1 += __shfl_xor_sync(0xffffffffu, a1, o);
        a2 += __shfl_xor_sync(0xffffffffu, a2, o);
        ah += __shfl_xor_sync(0xffffffffu, ah, o);
        c0 += __shfl_xor_sync(0xffffffffu, c0, o);
        c1 += __shfl_xor_sync(0xffffffffu, c1, o);
        c2 += __shfl_xor_sync(0xffffffffu, c2, o);
    }
    if (sub == 0) {
        float dvd = g_dinv_v[w];
        float h1 = dvd * ah;
        if (li < 5) {
            float* zz = g_z + (size_t)w * ZW;
            zz[5 + li]  = a0 / fmaxf(c0, 1.f);
            zz[10 + li] = a1 / fmaxf(c1, 1.f);
            zz[15 + li] = a2 / fmaxf(c2, 1.f);
            zz[20 + li] = h1;
            if (li == 0) zz[35] = 0.f;   // single pad element
        }
        p1[(size_t)w * 8 + li] = dvd * h1;
    }
}

__global__ void k_hop8_gather(const float* __restrict__ pprev, float* __restrict__ pnext,
                              int k, int write_p) {
    int gt = blockIdx.x * blockDim.x + threadIdx.x;
    int w = gt >> 5, lane = gt & 31;
    if (w >= NVn) return;
    int base = g_off_all[w], deg = g_deg_all[w];
    int sub = lane >> 3, li = lane & 7;
    float acc = 0.f;
#pragma unroll 4
    for (int j = sub; j < deg; j += 4) {
        int s = g_csr_all[base + j] & 0xFFFFF;
        acc += pprev[(size_t)s * 8 + li];
    }
#pragma unroll
    for (int o = 8; o < 32; o <<= 1)
        acc += __shfl_xor_sync(0xffffffffu, acc, o);
    if (sub == 0) {
        float dv = g_dinv_v[w];
        float h = dv * acc;
        if (li < 5) g_z[(size_t)w * ZW + 20 + k * 5 + li] = h;
        if (write_p) pnext[(size_t)w * 8 + li] = dv * h;
    }
}

// ----------------- ei_h + ei_in z-gathers (warp per node) ------------------
__global__ void k_gather_hin() {
    int gt = blockIdx.x * blockDim.x + threadIdx.x;
    int w = gt >> 5, lane = gt & 31;
    if (w >= NSn) return;
    int sub = lane >> 4, li = lane & 15;

    {   // ei_h: weighted + unweighted + weight-sum
        int base = g_off_all[NVn + NSn + w], deg = g_deg_all[NVn + NSn + w];
        float4 aW = make_float4(0.f, 0.f, 0.f, 0.f);
        float4 aU = make_float4(0.f, 0.f, 0.f, 0.f);
        float wsum = 0.f;
        for (int j0 = 0; j0 < deg; j0 += 32) {
            int idx = j0 + lane;
            int sl = 0; float wl = 0.f;
            if (idx < deg) { sl = g_csr_all[base + idx]; wl = g_csrw[base + idx]; }
            wsum += wl;
            int mres = deg - j0; if (mres > 32) mres = 32;
#pragma unroll
            for (int jj = 0; jj < 16; jj++) {
                int e2 = 2 * jj + sub;
                int s = __shfl_sync(0xffffffffu, sl, e2);
                float wt = __shfl_sync(0xffffffffu, wl, e2);
                if (e2 < mres && li < 9) {
                    float4 t = ((const float4*)(g_z + (size_t)s * ZW))[li];
                    aU.x += t.x; aU.y += t.y; aU.z += t.z; aU.w += t.w;
                    aW.x += wt * t.x; aW.y += wt * t.y; aW.z += wt * t.z; aW.w += wt * t.w;
                }
            }
        }
        aU.x += __shfl_xor_sync(0xffffffffu, aU.x, 16);
        aU.y += __shfl_xor_sync(0xffffffffu, aU.y, 16);
        aU.z += __shfl_xor_sync(0xffffffffu, aU.z, 16);
        aU.w += __shfl_xor_sync(0xffffffffu, aU.w, 16);
        aW.x += __shfl_xor_sync(0xffffffffu, aW.x, 16);
        aW.y += __shfl_xor_sync(0xffffffffu, aW.y, 16);
        aW.z += __shfl_xor_sync(0xffffffffu, aW.z, 16);
        aW.w += __shfl_xor_sync(0xffffffffu, aW.w, 16);
#pragma unroll
        for (int o = 16; o; o >>= 1) wsum += __shfl_xor_sync(0xffffffffu, wsum, o);
        if (sub == 0 && li < 9) {
            ((float4*)(g_aggu + (size_t)w * 36))[li] = aU;
            ((float4*)(g_aggw + (size_t)w * 36))[li] = aW;
        }
        if (lane == 0) g_wsum[w] = wsum;
    }
    {   // ei_in: plain sum
        int base = g_off_all[NVn + 2 * NSn + w], deg = g_deg_all[NVn + 2 * NSn + w];
        float4 aU = make_float4(0.f, 0.f, 0.f, 0.f);
        for (int j0 = 0; j0 < deg; j0 += 32) {
            int idx = j0 + lane;
            int sl = (idx < deg) ? g_csr_all[base + idx] : 0;
            int mres = deg - j0; if (mres > 32) mres = 32;
#pragma unroll
            for (int jj = 0; jj < 16; jj++) {
                int e2 = 2 * jj + sub;
                int s = __shfl_sync(0xffffffffu, sl, e2);
                if (e2 < mres && li < 9) {
                    float4 t = ((const float4*)(g_z + (size_t)s * ZW))[li];
                    aU.x += t.x; aU.y += t.y; aU.z += t.z; aU.w += t.w;
                }
            }
        }
        aU.x += __shfl_xor_sync(0xffffffffu, aU.x, 16);
        aU.y += __shfl_xor_sync(0xffffffffu, aU.y, 16);
        aU.z += __shfl_xor_sync(0xffffffffu, aU.z, 16);
        aU.w += __shfl_xor_sync(0xffffffffu, aU.w, 16);
        if (sub == 0 && li < 9)
            ((float4*)(g_aggin + (size_t)w * 36))[li] = aU;
    }
}

// ---------------------- tiled GEMM building blocks -------------------------
__device__ __forceinline__ void stage_w(float* sW, const float* __restrict__ g, int n) {
    for (int e = threadIdx.x; e < n; e += 256) sW[e] = g[e];
}
__device__ __forceinline__ void stage_a64(float* sA, const float* __restrict__ g,
                                          int vbase, const float* sScale) {
    for (int e = threadIdx.x; e < 64 * 64; e += 256) {
        int n = e >> 6, j = e & 63;
        int v = vbase + n; if (v >= NSn) v = NSn - 1;
        float s = sScale ? sScale[n] : 1.f;
        sA[j * AST + n] = g[(size_t)v * 64 + j] * s;
    }
}
__device__ __forceinline__ void stage_a36(float* sA, const float* __restrict__ g,
                                          int vbase, const float* sScale) {
    for (int e = threadIdx.x; e < 64 * 36; e += 256) {
        int n = e / 36, j = e - n * 36;
        int v = vbase + n; if (v >= NSn) v = NSn - 1;
        float s = sScale ? sScale[n] : 1.f;
        sA[j * AST + n] = g[(size_t)v * 36 + j] * s;
    }
}
__device__ __forceinline__ void gemm16(const float* __restrict__ sW, const float* __restrict__ sA,
                                       int J, int c4, int n0, float acc[4][4]) {
#pragma unroll 4
    for (int j = 0; j < J; j++) {
        float4 wv = *(const float4*)(sW + j * 64 + c4);
        float4 av = *(const float4*)(sA + j * AST + n0);
        acc[0][0] += av.x * wv.x; acc[0][1] += av.x * wv.y; acc[0][2] += av.x * wv.z; acc[0][3] += av.x * wv.w;
        acc[1][0] += av.y * wv.x; acc[1][1] += av.y * wv.y; acc[1][2] += av.y * wv.z; acc[1][3] += av.y * wv.w;
        acc[2][0] += av.z * wv.x; acc[2][1] += av.z * wv.y; acc[2][2] += av.z * wv.z; acc[2][3] += av.z * wv.w;
        acc[3][0] += av.w * wv.x; acc[3][1] += av.w * wv.y; acc[3][2] += av.w * wv.z; acc[3][3] += av.w * wv.w;
    }
}

// --------------------- state dense chain (layers 2-5) ----------------------
__global__ void __launch_bounds__(256) k_state_dense(
        const float* __restrict__ state_x, const float* __restrict__ W3_root,
        const float* __restrict__ b3, const float* __restrict__ W32_r,
        const float* __restrict__ b32, const float* __restrict__ W4_r,
        const float* __restrict__ b4, const float* __restrict__ W42_r,
        const float* __restrict__ b42) {
    __shared__ float sW[64 * 64];
    __shared__ float sA[64 * AST];
    __shared__ float sInvH[64], sInvI[64], sWsum[64], sPosH[64], sPosI[64], sDin[64];
    int tid = threadIdx.x;
    int vbase = blockIdx.x * 64;
    if (tid < 64) {
        int v = vbase + tid; if (v >= NSn) v = NSn - 1;
        float ch = (float)g_deg_all[NVn + NSn + v];
        float ci = (float)g_deg_all[NVn + 2 * NSn + v];
        sInvH[tid] = 1.f / fmaxf(ch, 1.f);
        sInvI[tid] = 1.f / fmaxf(ci, 1.f);
        sPosH[tid] = (ch > 0.f) ? 1.f : 0.f;
        sPosI[tid] = (ci > 0.f) ? 1.f : 0.f;
        sWsum[tid] = g_wsum[v];
        sDin[tid]  = g_dinv_s[v];
    }
    __syncthreads();
    int c4 = (tid & 15) * 4, n0 = (tid >> 4) * 4;
    float acc[4][4];
    float4 bv, cv;

    // ---- L2: graph_conv ----
    stage_a36(sA, g_aggw, vbase, nullptr);
    stage_w(sW, g_WzW[0], 35 * 64);
    __syncthreads();
    bv = *(const float4*)(b3 + c4);
    cv = *(const float4*)(g_c0W[0] + c4);
#pragma unroll
    for (int i = 0; i < 4; i++) {
        float ws = sWsum[n0 + i];
        acc[i][0] = bv.x + ws * cv.x; acc[i][1] = bv.y + ws * cv.y;
        acc[i][2] = bv.z + ws * cv.z; acc[i][3] = bv.w + ws * cv.w;
    }
    gemm16(sW, sA, 35, c4, n0, acc);
    __syncthreads();
    for (int e = tid; e < 64 * 5; e += 256) {
        int n = e / 5, j = e - n * 5;
        int v = vbase + n; if (v >= NSn) v = NSn - 1;
        sA[j * AST + n] = state_x[(size_t)v * 5 + j];
    }
    stage_w(sW, W3_root, 5 * 64);
    __syncthreads();
    gemm16(sW, sA, 5, c4, n0, acc);
#pragma unroll
    for (int i = 0; i < 4; i++) {
        int v = vbase + n0 + i;
        if (v < NSn) {
            float4 o = make_float4(fmaxf(acc[i][0], 0.f), fmaxf(acc[i][1], 0.f),
                                   fmaxf(acc[i][2], 0.f), fmaxf(acc[i][3], 0.f));
            *(float4*)(g_ta + (size_t)v * 64 + c4) = o;
        }
    }
    __syncthreads();

    // ---- L3: conv32 ----
    stage_a36(sA, g_aggu, vbase, sInvH);
    stage_w(sW, g_WzW[1], 35 * 64);
    __syncthreads();
    bv = *(const float4*)(b32 + c4);
    cv = *(const float4*)(g_c0W[1] + c4);
#pragma unroll
    for (int i = 0; i < 4; i++) {
        float p = sPosH[n0 + i];
        acc[i][0] = bv.x + p * cv.x; acc[i][1] = bv.y + p * cv.y;
        acc[i][2] = bv.z + p * cv.z; acc[i][3] = bv.w + p * cv.w;
    }
    gemm16(sW, sA, 35, c4, n0, acc);
    __syncthreads();
    stage_a64(sA, g_ta, vbase, nullptr);
    stage_w(sW, W32_r, 64 * 64);
    __syncthreads();
    gemm16(sW, sA, 64, c4, n0, acc);
#pragma unroll
    for (int i = 0; i < 4; i++) {
        int v = vbase + n0 + i;
        if (v < NSn) {
            float4 o = make_float4(fmaxf(acc[i][0], 0.f), fmaxf(acc[i][1], 0.f),
                                   fmaxf(acc[i][2], 0.f), fmaxf(acc[i][3], 0.f));
            *(float4*)(g_tb + (size_t)v * 64 + c4) = o;
        }
    }
    __syncthreads();

    // ---- L4: conv4 ----
    stage_a36(sA, g_aggin, vbase, sInvI);
    stage_w(sW, g_WzW[2], 35 * 64);
    __syncthreads();
    bv = *(const float4*)(b4 + c4);
    cv = *(const float4*)(g_c0W[2] + c4);
#pragma unroll
    for (int i = 0; i < 4; i++) {
        float p = sPosI[n0 + i];
        acc[i][0] = bv.x + p * cv.x; acc[i][1] = bv.y + p * cv.y;
        acc[i][2] = bv.z + p * cv.z; acc[i][3] = bv.w + p * cv.w;
    }
    gemm16(sW, sA, 35, c4, n0, acc);
    __syncthreads();
    stage_a64(sA, g_tb, vbase, nullptr);
    stage_w(sW, W4_r, 64 * 64);
    __syncthreads();
    gemm16(sW, sA, 64, c4, n0, acc);
#pragma unroll
    for (int i = 0; i < 4; i++) {
        int v = vbase + n0 + i;
        if (v < NSn) {
            float4 o = make_float4(fmaxf(acc[i][0], 0.f), fmaxf(acc[i][1], 0.f),
                                   fmaxf(acc[i][2], 0.f), fmaxf(acc[i][3], 0.f));
            *(float4*)(g_ta + (size_t)v * 64 + c4) = o;
        }
    }
    __syncthreads();

    // ---- L5: conv42 -> sx5, pin ----
    stage_a36(sA, g_aggin, vbase, sInvI);
    stage_w(sW, g_WzW[3], 35 * 64);
    __syncthreads();
    bv = *(const float4*)(b42 + c4);
    cv = *(const float4*)(g_c0W[3] + c4);
#pragma unroll
    for (int i = 0; i < 4; i++) {
        float p = sPosI[n0 + i];
        acc[i][0] = bv.x + p * cv.x; acc[i][1] = bv.y + p * cv.y;
        acc[i][2] = bv.z + p * cv.z; acc[i][3] = bv.w + p * cv.w;
    }
    gemm16(sW, sA, 35, c4, n0, acc);
    __syncthreads();
    stage_a64(sA, g_ta, vbase, nullptr);
    stage_w(sW, W42_r, 64 * 64);
    __syncthreads();
    gemm16(sW, sA, 64, c4, n0, acc);
#pragma unroll
    for (int i = 0; i < 4; i++) {
        int v = vbase + n0 + i;
        if (v < NSn) {
            float dv = sDin[n0 + i];
            float4 o = make_float4(fmaxf(acc[i][0], 0.f), fmaxf(acc[i][1], 0.f),
                                   fmaxf(acc[i][2], 0.f), fmaxf(acc[i][3], 0.f));
            *(float4*)(g_sx5 + (size_t)v * 64 + c4) = o;
            *(float4*)(g_pin + (size_t)v * 64 + c4) =
                make_float4(dv * o.x, dv * o.y, dv * o.z, dv * o.w);
        }
    }
}

// TAG-state hop, p-form.
__global__ void k_hop64p(const float* __restrict__ pprev, float* __restrict__ pnext) {
    int gt = blockIdx.x * blockDim.x + threadIdx.x;
    int w = gt >> 5, lane = gt & 31;
    if (w >= NSn) return;
    int base = g_off_all[NVn + w], deg = g_deg_all[NVn + w];
    int sub = lane >> 4, li = lane & 15;
    float4 a = make_float4(0.f, 0.f, 0.f, 0.f);
    for (int j0 = 0; j0 < deg; j0 += 32) {
        int idx = j0 + lane;
        int sl = (idx < deg) ? g_csr_all[base + idx] : 0;
        int mres = deg - j0; if (mres > 32) mres = 32;
#pragma unroll
        for (int jj = 0; jj < 16; jj++) {
            int e2 = 2 * jj + sub;
            int s = __shfl_sync(0xffffffffu, sl, e2);
            if (e2 < mres) {
                float4 v = ((const float4*)(pprev + (size_t)s * 64))[li];
                a.x += v.x; a.y += v.y; a.z += v.z; a.w += v.w;
            }
        }
    }
    a.x += __shfl_xor_sync(0xffffffffu, a.x, 16);
    a.y += __shfl_xor_sync(0xffffffffu, a.y, 16);
    a.z += __shfl_xor_sync(0xffffffffu, a.z, 16);
    a.w += __shfl_xor_sync(0xffffffffu, a.w, 16);
    if (sub == 0) {
        float dv = g_dinv_s[w];
        float dv2 = dv * dv;
        ((float4*)(pnext + (size_t)w * 64))[li] =
            make_float4(dv2 * a.x, dv2 * a.y, dv2 * a.z, dv2 * a.w);
    }
}

// conv5 sum gather over ei_ss.
__global__ void k_sum64_gather(const float* __restrict__ feat, float* __restrict__ acc) {
    int gt = blockIdx.x * blockDim.x + threadIdx.x;
    int w = gt >> 5, lane = gt & 31;
    if (w >= NSn) return;
    int base = g_off_all[NVn + w], deg = g_deg_all[NVn + w];
    int sub = lane >> 4, li = lane & 15;
    float4 a = make_float4(0.f, 0.f, 0.f, 0.f);
    for (int j0 = 0; j0 < deg; j0 += 32) {
        int idx = j0 + lane;
        int sl = (idx < deg) ? g_csr_all[base + idx] : 0;
        int mres = deg - j0; if (mres > 32) mres = 32;
#pragma unroll
        for (int jj = 0; jj < 16; jj++) {
            int e2 = 2 * jj + sub;
            int s = __shfl_sync(0xffffffffu, sl, e2);
            if (e2 < mres) {
                float4 v = ((const float4*)(feat + (size_t)s * 64))[li];
                a.x += v.x; a.y += v.y; a.z += v.z; a.w += v.w;
            }
        }
    }
    a.x += __shfl_xor_sync(0xffffffffu, a.x, 16);
    a.y += __shfl_xor_sync(0xffffffffu, a.y, 16);
    a.z += __shfl_xor_sync(0xffffffffu, a.z, 16);
    a.w += __shfl_xor_sync(0xffffffffu, a.w, 16);
    if (sub == 0)
        ((float4*)(acc + (size_t)w * 64))[li] = a;
}

// TAG output dense: sx6 = relu(b2 + sx5@W2_0 + sum_k (sqd*pk_k)@W2_{k+1})
__global__ void __launch_bounds__(256) k_tag_dense(
        const float* __restrict__ W2, const float* __restrict__ b2) {
    __shared__ float sW[64 * 64];
    __shared__ float sA[64 * AST];
    __shared__ float sSq[64];
    int tid = threadIdx.x;
    int vbase = blockIdx.x * 64;
    if (tid < 64) {
        int v = vbase + tid; if (v >= NSn) v = NSn - 1;
        sSq[tid] = g_sqd_s[v];
    }
    __syncthreads();
    int c4 = (tid & 15) * 4, n0 = (tid >> 4) * 4;
    float acc[4][4];
    float4 bv;

    stage_a64(sA, g_sx5, vbase, nullptr);
    stage_w(sW, W2, 64 * 64);
    __syncthreads();
    bv = *(const float4*)(b2 + c4);
#pragma unroll
    for (int i = 0; i < 4; i++) {
        acc[i][0] = bv.x; acc[i][1] = bv.y; acc[i][2] = bv.z; acc[i][3] = bv.w;
    }
    gemm16(sW, sA, 64, c4, n0, acc);
    __syncthreads();
#pragma unroll
    for (int k = 0; k < 3; k++) {
        stage_a64(sA, g_pk[k], vbase, sSq);
        stage_w(sW, W2 + (size_t)(k + 1) * 4096, 64 * 64);
        __syncthreads();
        gemm16(sW, sA, 64, c4, n0, acc);
        __syncthreads();
    }
#pragma unroll
    for (int i = 0; i < 4; i++) {
        int v = vbase + n0 + i;
        if (v < NSn) {
            float4 o = make_float4(fmaxf(acc[i][0], 0.f), fmaxf(acc[i][1], 0.f),
                                   fmaxf(acc[i][2], 0.f), fmaxf(acc[i][3], 0.f));
            *(float4*)(g_sx6 + (size_t)v * 64 + c4) = o;
        }
    }
}

// conv5 dense + head.
__global__ void __launch_bounds__(256) k_conv5_head(
        const float* __restrict__ W5_l, const float* __restrict__ W5_r,
        const float* __restrict__ b5, const float* __restrict__ Wl,
        const float* __restrict__ bl, float* __restrict__ out) {
    __shared__ float sW[64 * 64];
    __shared__ float sA[64 * AST];
    __shared__ float sInv[64];
    int tid = threadIdx.x;
    int vbase = blockIdx.x * 64;
    if (tid < 64) {
        int v = vbase + tid; if (v >= NSn) v = NSn - 1;
        sInv[tid] = 1.f / fmaxf(g_cntf_s[v], 1.f);
    }
    __syncthreads();
    int c4 = (tid & 15) * 4, n0 = (tid >> 4) * 4;
    float acc[4][4];
    float4 bv;

    stage_a64(sA, g_accs5, vbase, sInv);
    stage_w(sW, W5_l, 64 * 64);
    __syncthreads();
    bv = *(const float4*)(b5 + c4);
#pragma unroll
    for (int i = 0; i < 4; i++) {
        acc[i][0] = bv.x; acc[i][1] = bv.y; acc[i][2] = bv.z; acc[i][3] = bv.w;
    }
    gemm16(sW, sA, 64, c4, n0, acc);
    __syncthreads();
    stage_a64(sA, g_sx6, vbase, nullptr);
    stage_w(sW, W5_r, 64 * 64);
    __syncthreads();
    gemm16(sW, sA, 64, c4, n0, acc);
    __syncthreads();
#pragma unroll
    for (int i = 0; i < 4; i++) {
#pragma unroll
        for (int k = 0; k < 4; k++)
            sA[(c4 + k) * AST + n0 + i] = fmaxf(acc[i][k], 0.f);
    }
    stage_w(sW, Wl, 64 * 8);
    __syncthreads();
#pragma unroll
    for (int u = 0; u < 2; u++) {
        int idx = tid * 2 + u;
        int n = idx >> 3, o = idx & 7;
        float s = bl[o];
#pragma unroll 8
        for (int j = 0; j < 64; j++) s += sA[j * AST + n] * sW[j * 8 + o];
        int v = vbase + n;
        if (v < NSn) out[(size_t)v * 8 + o] = s;
    }
}

// ------------------------------- launch ------------------------------------

extern "C" void kernel_launch(void* const* d_in, const int* in_sizes, int n_in,
                              void* d_out, int out_size) {
    const float* game_x  = (const float*)d_in[0];
    const float* state_x = (const float*)d_in[1];
    const int*   ei_vv   = (const int*)d_in[2];
    const int*   et_vv   = (const int*)d_in[3];
    const int*   ei_h    = (const int*)d_in[4];
    const float* ew_h    = (const float*)d_in[5];
    const int*   ei_in   = (const int*)d_in[6];
    const int*   ei_ss   = (const int*)d_in[7];
    const float* W1_rel  = (const float*)d_in[8];
    const float* W1_root = (const float*)d_in[9];
    const float* b1      = (const float*)d_in[10];
    const float* W12     = (const float*)d_in[11];
    const float* b12     = (const float*)d_in[12];
    const float* W2      = (const float*)d_in[13];
    const float* b2      = (const float*)d_in[14];
    const float* W3_rel  = (const float*)d_in[15];
    const float* W3_root = (const float*)d_in[16];
    const float* b3      = (const float*)d_in[17];
    const float* W32_l   = (const float*)d_in[18];
    const float* W32_r   = (const float*)d_in[19];
    const float* b32     = (const float*)d_in[20];
    const float* W4_l    = (const float*)d_in[21];
    const float* W4_r    = (const float*)d_in[22];
    const float* b4      = (const float*)d_in[23];
    const float* W42_l   = (const float*)d_in[24];
    const float* W42_r   = (const float*)d_in[25];
    const float* b42     = (const float*)d_in[26];
    const float* W5_l    = (const float*)d_in[27];
    const float* W5_r    = (const float*)d_in[28];
    const float* b5      = (const float*)d_in[29];
    const float* Wl      = (const float*)d_in[30];
    const float* bl      = (const float*)d_in[31];
    float* out = (float*)d_out;

    int Evv = in_sizes[2] / 2;
    int Eh  = in_sizes[4] / 2;
    int Ein = in_sizes[6] / 2;
    int Ess = in_sizes[7] / 2;
    int Etot = Evv + Ess + Eh + Ein;

    int* pi_deg;
    float *p_pv, *p_pin, *p_pk, *p_sx6, *p_accs5;
    cudaGetSymbolAddress((void**)&pi_deg,  g_deg_all);
    cudaGetSymbolAddress((void**)&p_pv,    g_pv);
    cudaGetSymbolAddress((void**)&p_pin,   g_pin);
    cudaGetSymbolAddress((void**)&p_pk,    g_pk);
    cudaGetSymbolAddress((void**)&p_sx6,   g_sx6);
    cudaGetSymbolAddress((void**)&p_accs5, g_accs5);

    float* p_pv0 = p_pv;
    float* p_pv1 = p_pv + (size_t)NVn * 8;
    float* p_pk0 = p_pk;
    float* p_pk1 = p_pk + (size_t)NSn * 64;
    float* p_pk2 = p_pk1 + (size_t)NSn * 64;

    const int T = 256;
    auto nb = [](long n, int t) { return (int)((n + t - 1) / t); };
    int nbv_warp = nb((long)NVn * 32, T);
    int nbs_warp = nb((long)NSn * 32, T);
    int ndense = nb(NSn, 64);

    // 0) zero unified degree array
    cudaMemsetAsync(pi_deg, 0, (size_t)NDEG * 4, 0);

    // 1) fused count + pad + weight prep, then scan, then fill
    k_count_pad_prep<<<nb(Etot, T), T>>>(ei_vv, ei_ss, ei_h, ei_in,
                                         Evv, Ess, Eh, Ein,
                                         game_x, W1_rel, W1_root, b1, W12, b12,
                                         W3_rel, W32_l, W4_l, W42_l);
    k_scan<<<nb(NDEG, 1024), 1024>>>(NDEG);
    k_fill_all<<<nb(Etot, T), T>>>(ei_vv, et_vv, ei_ss, ei_h, ew_h, ei_in,
                                   Evv, Ess, Eh, Ein);

    // 2) game graph -> z
    k_rgcn_hop1<<<nbv_warp, T>>>(p_pv0);
    k_hop8_gather<<<nbv_warp, T>>>(p_pv0, p_pv1, 1, 1);
    k_hop8_gather<<<nbv_warp, T>>>(p_pv1, p_pv0, 2, 0);

    // 3) ei_h + ei_in gathers, then state dense chain
    k_gather_hin<<<nbs_warp, T>>>();
    k_state_dense<<<ndense, 256>>>(state_x, W3_root, b3, W32_r, b32,
                                   W4_r, b4, W42_r, b42);

    // 4) TAG-state hops + dense output
    k_hop64p<<<nbs_warp, T>>>(p_pin, p_pk0);
    k_hop64p<<<nbs_warp, T>>>(p_pk0, p_pk1);
    k_hop64p<<<nbs_warp, T>>>(p_pk1, p_pk2);
    k_tag_dense<<<ndense, 256>>>(W2, b2);

    // 5) conv5 gather + dense + head
    k_sum64_gather<<<nbs_warp, T>>>(p_sx6, p_accs5);
    k_conv5_head<<<ndense, 256>>>(W5_l, W5_r, b5, Wl, bl, out);
}

// round 14
// speedup vs baseline: 2.5052x; 1.0028x over previous
#include <cuda_runtime.h>
#include <math.h>

// ---------------------------------------------------------------------------
// StateModelEncoder — round 14: round-13 structure + float4 2-lane hop8
// (16 edges in flight), rgcn c2 derived from deg, gather_hin split per-graph.
// ---------------------------------------------------------------------------

#define NVn 100000
#define NSn 50000
#define EVVmax 1600000
#define ESSmax 800000
#define EHmax  800000
#define EINmax 800000
#define NDEG   (NVn + 3 * NSn)
#define ETOT   (EVVmax + ESSmax + EHmax + EINmax)
#define ZW     36
#define AST    68

// ------------------------- scratch (device globals) ------------------------
__device__ __align__(16) float g_xpad[NVn * 8];
__device__ float g_dinv_v[NVn];
__device__ __align__(16) float g_z[(size_t)NVn * ZW];
__device__ __align__(16) float g_pv[2][NVn * 8];
__device__ __align__(16) float g_WzW[4][40 * 64];
__device__ float g_c0W[4][64];
__device__ __align__(16) float g_aggw[(size_t)NSn * 36];
__device__ __align__(16) float g_aggu[(size_t)NSn * 36];
__device__ __align__(16) float g_aggin[(size_t)NSn * 36];
__device__ float g_wsum[NSn];
__device__ __align__(16) float g_ta[(size_t)NSn * 64];
__device__ __align__(16) float g_tb[(size_t)NSn * 64];
__device__ __align__(16) float g_sx5[(size_t)NSn * 64];
__device__ __align__(16) float g_pin[(size_t)NSn * 64];
__device__ __align__(16) float g_pk[3][(size_t)NSn * 64];
__device__ __align__(16) float g_sx6[(size_t)NSn * 64];
__device__ __align__(16) float g_accs5[(size_t)NSn * 64];
__device__ float g_dinv_s[NSn];
__device__ float g_sqd_s[NSn];
__device__ float g_cntf_s[NSn];

// unified CSR
__device__ int g_deg_all[NDEG];
__device__ int g_off_all[NDEG];
__device__ int g_cur_all[NDEG];
__device__ int g_scan_base;
__device__ int g_csr_all[ETOT];
__device__ float g_csrw[ETOT];

// ------------------ CSR count + pad + weight prep (fused) ------------------
__global__ void k_count_pad_prep(
        const int* __restrict__ ei_vv, const int* __restrict__ ei_ss,
        const int* __restrict__ ei_h,  const int* __restrict__ ei_in,
        int Evv, int Ess, int Eh, int Ein,
        const float* __restrict__ x,
        const float* __restrict__ W1_rel, const float* __restrict__ W1_root,
        const float* __restrict__ b1,
        const float* __restrict__ W12, const float* __restrict__ b12,
        const float* __restrict__ W3_rel, const float* __restrict__ W32_l,
        const float* __restrict__ W4_l,  const float* __restrict__ W42_l) {
    int t0 = blockIdx.x * blockDim.x + threadIdx.x;
    if (t0 == 0) g_scan_base = 0;

    if (t0 < NVn * 8) {
        int v = t0 >> 3, i = t0 & 7;
        float xv = (i < 5) ? x[v * 5 + i] : 0.f;
        g_xpad[t0] = xv;
        if (i < 5) g_z[(size_t)v * ZW + i] = xv;
    }
    if (t0 < 4 * 41 * 64) {
        int m = t0 / (41 * 64);
        int r = t0 % (41 * 64);
        int i = r >> 6, c = r & 63;
        const float* Wm = (m == 0) ? W3_rel : (m == 1) ? W32_l : (m == 2) ? W4_l : W42_l;
        float acc = 0.f;
        if (i < 40) {
            if (i < 35) {
#pragma unroll 8
                for (int j = 0; j < 64; j++) {
                    float wz;
                    if (i < 5)       wz = W1_root[i * 64 + j] + W12[i * 64 + j];
                    else if (i < 20) wz = W1_rel[(i - 5) * 64 + j];
                    else             wz = W12[(i - 15) * 64 + j];
                    acc += wz * Wm[j * 64 + c];
                }
                g_WzW[m][i * 64 + c] = acc;
            }
        } else {
#pragma unroll 8
            for (int j = 0; j < 64; j++) acc += (b1[j] + b12[j]) * Wm[j * 64 + c];
            g_c0W[m][c] = acc;
        }
    }

    int t = t0;
    if (t < Evv) { atomicAdd(g_deg_all + ei_vv[Evv + t], 1); return; }
    t -= Evv;
    if (t < Ess) { atomicAdd(g_deg_all + NVn + ei_ss[Ess + t], 1); return; }
    t -= Ess;
    if (t < Eh)  { atomicAdd(g_deg_all + NVn + NSn + ei_h[Eh + t], 1); return; }
    t -= Eh;
    if (t < Ein) { atomicAdd(g_deg_all + NVn + 2 * NSn + ei_in[Ein + t], 1); }
}

// one-pass scan (arrival-ordered block bases) + dinv/sqd/cnt.
__global__ void k_scan(int n) {
    __shared__ int sh[1024];
    __shared__ int s_base;
    int i = blockIdx.x * 1024 + threadIdx.x;
    int v = (i < n) ? g_deg_all[i] : 0;
    sh[threadIdx.x] = v;
    __syncthreads();
    for (int o = 1; o < 1024; o <<= 1) {
        int t = (threadIdx.x >= o) ? sh[threadIdx.x - o] : 0;
        __syncthreads();
        sh[threadIdx.x] += t;
        __syncthreads();
    }
    if (threadIdx.x == 1023) s_base = atomicAdd(&g_scan_base, sh[1023]);
    __syncthreads();
    if (i < n) {
        int o = s_base + sh[threadIdx.x] - v;
        g_off_all[i] = o;
        g_cur_all[i] = o;
        if (i < NVn) {
            g_dinv_v[i] = (v > 0) ? rsqrtf((float)v) : 0.f;
        } else if (i < NVn + NSn) {
            int s = i - NVn;
            g_dinv_s[s] = (v > 0) ? rsqrtf((float)v) : 0.f;
            g_sqd_s[s]  = sqrtf((float)v);
            g_cntf_s[s] = (float)v;
        }
    }
}

__global__ void k_fill_all(const int* __restrict__ ei_vv, const int* __restrict__ et_vv,
                           const int* __restrict__ ei_ss, const int* __restrict__ ei_h,
                           const float* __restrict__ ew_h, const int* __restrict__ ei_in,
                           int Evv, int Ess, int Eh, int Ein) {
    int t = blockIdx.x * blockDim.x + threadIdx.x;
    if (t < Evv) {
        int slot = atomicAdd(g_cur_all + ei_vv[Evv + t], 1);
        g_csr_all[slot] = ei_vv[t] | (et_vv[t] << 20);
        return;
    }
    t -= Evv;
    if (t < Ess) {
        int slot = atomicAdd(g_cur_all + NVn + ei_ss[Ess + t], 1);
        g_csr_all[slot] = ei_ss[t];
        return;
    }
    t -= Ess;
    if (t < Eh) {
        int slot = atomicAdd(g_cur_all + NVn + NSn + ei_h[Eh + t], 1);
        g_csr_all[slot] = ei_h[t];
        g_csrw[slot] = ew_h[t];
        return;
    }
    t -= Eh;
    if (t < Ein) {
        int slot = atomicAdd(g_cur_all + NVn + 2 * NSn + ei_in[Ein + t], 1);
        g_csr_all[slot] = ei_in[t];
    }
}

// --------------------------- game-graph kernels ----------------------------
// RGCN per-rel means + TAG-game hop1 fused (8-lane subgroups; c2 = deg-c0-c1).
__global__ void k_rgcn_hop1(float* __restrict__ p1) {
    int gt = blockIdx.x * blockDim.x + threadIdx.x;
    int w = gt >> 5, lane = gt & 31;
    if (w >= NVn) return;
    int base = g_off_all[w], deg = g_deg_all[w];
    int sub = lane >> 3, li = lane & 7;
    float a0 = 0.f, a1 = 0.f, a2 = 0.f, ah = 0.f;
    float c0 = 0.f, c1 = 0.f;
#pragma unroll 4
    for (int j = sub; j < deg; j += 4) {
        int pk = g_csr_all[base + j];
        int s = pk & 0xFFFFF, t = pk >> 20;
        float xv = g_xpad[(size_t)s * 8 + li];
        ah += g_dinv_v[s] * xv;
        if (t == 0)      { a0 += xv; c0 += 1.f; }
        else if (t == 1) { a1 += xv; c1 += 1.f; }
        else             { a2 += xv; }
    }
#pragma unroll
    for (int o = 8; o < 32; o <<= 1) {
        a0 += __shfl_xor_sync(0xffffffffu, a0, o);
        a1 += __shfl_xor_sync(0xffffffffu, a1, o);
        a2 += __shfl_xor_sync(0xffffffffu, a2, o);
        ah += __shfl_xor_sync(0xffffffffu, ah, o);
        c0 += __shfl_xor_sync(0xffffffffu, c0, o);
        c1 += __shfl_xor_sync(0xffffffffu, c1, o);
    }
    if (sub == 0) {
        float dvd = g_dinv_v[w];
        float h1 = dvd * ah;
        float c2 = (float)deg - c0 - c1;
        if (li < 5) {
            float* zz = g_z + (size_t)w * ZW;
            zz[5 + li]  = a0 / fmaxf(c0, 1.f);
            zz[10 + li] = a1 / fmaxf(c1, 1.f);
            zz[15 + li] = a2 / fmaxf(c2, 1.f);
            zz[20 + li] = h1;
            if (li == 0) zz[35] = 0.f;
        }
        p1[(size_t)w * 8 + li] = dvd * h1;
    }
}

// TAG-game hop (k=1,2): 2-lane float4 subgroups, 16 edges in flight.
__global__ void k_hop8_gather(const float* __restrict__ pprev, float* __restrict__ pnext,
                              int k, int write_p) {
    int gt = blockIdx.x * blockDim.x + threadIdx.x;
    int w = gt >> 5, lane = gt & 31;
    if (w >= NVn) return;
    int base = g_off_all[w], deg = g_deg_all[w];
    int pair = lane >> 1, h = lane & 1;
    float4 a = make_float4(0.f, 0.f, 0.f, 0.f);
    for (int j = pair; j < deg; j += 16) {
        int s = g_csr_all[base + j] & 0xFFFFF;
        float4 v = ((const float4*)(pprev + (size_t)s * 8))[h];
        a.x += v.x; a.y += v.y; a.z += v.z; a.w += v.w;
    }
#pragma unroll
    for (int o = 2; o < 32; o <<= 1) {
        a.x += __shfl_xor_sync(0xffffffffu, a.x, o);
        a.y += __shfl_xor_sync(0xffffffffu, a.y, o);
        a.z += __shfl_xor_sync(0xffffffffu, a.z, o);
        a.w += __shfl_xor_sync(0xffffffffu, a.w, o);
    }
    if (lane < 2) {
        float dv = g_dinv_v[w];
        float4 hx = make_float4(dv * a.x, dv * a.y, dv * a.z, dv * a.w);
        float* zz = g_z + (size_t)w * ZW + 20 + k * 5;
        if (h == 0) { zz[0] = hx.x; zz[1] = hx.y; zz[2] = hx.z; zz[3] = hx.w; }
        else        { zz[4] = hx.x; }
        if (write_p)
            ((float4*)(pnext + (size_t)w * 8))[h] =
                make_float4(dv * hx.x, dv * hx.y, dv * hx.z, dv * hx.w);
    }
}

// --------- ei_h / ei_in z-gathers (one warp per node per graph) ------------
__global__ void k_gather_hin() {
    int gt = blockIdx.x * blockDim.x + threadIdx.x;
    int w2 = gt >> 5, lane = gt & 31;
    if (w2 >= 2 * NSn) return;
    int sub = lane >> 4, li = lane & 15;
    int isH = (w2 < NSn);
    int w = isH ? w2 : (w2 - NSn);

    if (isH) {   // ei_h: weighted + unweighted + weight-sum
        int base = g_off_all[NVn + NSn + w], deg = g_deg_all[NVn + NSn + w];
        float4 aW = make_float4(0.f, 0.f, 0.f, 0.f);
        float4 aU = make_float4(0.f, 0.f, 0.f, 0.f);
        float wsum = 0.f;
        for (int j0 = 0; j0 < deg; j0 += 32) {
            int idx = j0 + lane;
            int sl = 0; float wl = 0.f;
            if (idx < deg) { sl = g_csr_all[base + idx]; wl = g_csrw[base + idx]; }
            wsum += wl;
            int mres = deg - j0; if (mres > 32) mres = 32;
#pragma unroll
            for (int jj = 0; jj < 16; jj++) {
                int e2 = 2 * jj + sub;
                int s = __shfl_sync(0xffffffffu, sl, e2);
                float wt = __shfl_sync(0xffffffffu, wl, e2);
                if (e2 < mres && li < 9) {
                    float4 t = ((const float4*)(g_z + (size_t)s * ZW))[li];
                    aU.x += t.x; aU.y += t.y; aU.z += t.z; aU.w += t.w;
                    aW.x += wt * t.x; aW.y += wt * t.y; aW.z += wt * t.z; aW.w += wt * t.w;
                }
            }
        }
        aU.x += __shfl_xor_sync(0xffffffffu, aU.x, 16);
        aU.y += __shfl_xor_sync(0xffffffffu, aU.y, 16);
        aU.z += __shfl_xor_sync(0xffffffffu, aU.z, 16);
        aU.w += __shfl_xor_sync(0xffffffffu, aU.w, 16);
        aW.x += __shfl_xor_sync(0xffffffffu, aW.x, 16);
        aW.y += __shfl_xor_sync(0xffffffffu, aW.y, 16);
        aW.z += __shfl_xor_sync(0xffffffffu, aW.z, 16);
        aW.w += __shfl_xor_sync(0xffffffffu, aW.w, 16);
#pragma unroll
        for (int o = 16; o; o >>= 1) wsum += __shfl_xor_sync(0xffffffffu, wsum, o);
        if (sub == 0 && li < 9) {
            ((float4*)(g_aggu + (size_t)w * 36))[li] = aU;
            ((float4*)(g_aggw + (size_t)w * 36))[li] = aW;
        }
        if (lane == 0) g_wsum[w] = wsum;
    } else {     // ei_in: plain sum
        int base = g_off_all[NVn + 2 * NSn + w], deg = g_deg_all[NVn + 2 * NSn + w];
        float4 aU = make_float4(0.f, 0.f, 0.f, 0.f);
        for (int j0 = 0; j0 < deg; j0 += 32) {
            int idx = j0 + lane;
            int sl = (idx < deg) ? g_csr_all[base + idx] : 0;
            int mres = deg - j0; if (mres > 32) mres = 32;
#pragma unroll
            for (int jj = 0; jj < 16; jj++) {
                int e2 = 2 * jj + sub;
                int s = __shfl_sync(0xffffffffu, sl, e2);
                if (e2 < mres && li < 9) {
                    float4 t = ((const float4*)(g_z + (size_t)s * ZW))[li];
                    aU.x += t.x; aU.y += t.y; aU.z += t.z; aU.w += t.w;
                }
            }
        }
        aU.x += __shfl_xor_sync(0xffffffffu, aU.x, 16);
        aU.y += __shfl_xor_sync(0xffffffffu, aU.y, 16);
        aU.z += __shfl_xor_sync(0xffffffffu, aU.z, 16);
        aU.w += __shfl_xor_sync(0xffffffffu, aU.w, 16);
        if (sub == 0 && li < 9)
            ((float4*)(g_aggin + (size_t)w * 36))[li] = aU;
    }
}

// ---------------------- tiled GEMM building blocks -------------------------
__device__ __forceinline__ void stage_w(float* sW, const float* __restrict__ g, int n) {
    for (int e = threadIdx.x; e < n; e += 256) sW[e] = g[e];
}
__device__ __forceinline__ void stage_a64(float* sA, const float* __restrict__ g,
                                          int vbase, const float* sScale) {
    for (int e = threadIdx.x; e < 64 * 64; e += 256) {
        int n = e >> 6, j = e & 63;
        int v = vbase + n; if (v >= NSn) v = NSn - 1;
        float s = sScale ? sScale[n] : 1.f;
        sA[j * AST + n] = g[(size_t)v * 64 + j] * s;
    }
}
__device__ __forceinline__ void stage_a36(float* sA, const float* __restrict__ g,
                                          int vbase, const float* sScale) {
    for (int e = threadIdx.x; e < 64 * 36; e += 256) {
        int n = e / 36, j = e - n * 36;
        int v = vbase + n; if (v >= NSn) v = NSn - 1;
        float s = sScale ? sScale[n] : 1.f;
        sA[j * AST + n] = g[(size_t)v * 36 + j] * s;
    }
}
__device__ __forceinline__ void gemm16(const float* __restrict__ sW, const float* __restrict__ sA,
                                       int J, int c4, int n0, float acc[4][4]) {
#pragma unroll 4
    for (int j = 0; j < J; j++) {
        float4 wv = *(const float4*)(sW + j * 64 + c4);
        float4 av = *(const float4*)(sA + j * AST + n0);
        acc[0][0] += av.x * wv.x; acc[0][1] += av.x * wv.y; acc[0][2] += av.x * wv.z; acc[0][3] += av.x * wv.w;
        acc[1][0] += av.y * wv.x; acc[1][1] += av.y * wv.y; acc[1][2] += av.y * wv.z; acc[1][3] += av.y * wv.w;
        acc[2][0] += av.z * wv.x; acc[2][1] += av.z * wv.y; acc[2][2] += av.z * wv.z; acc[2][3] += av.z * wv.w;
        acc[3][0] += av.w * wv.x; acc[3][1] += av.w * wv.y; acc[3][2] += av.w * wv.z; acc[3][3] += av.w * wv.w;
    }
}

// --------------------- state dense chain (layers 2-5) ----------------------
__global__ void __launch_bounds__(256) k_state_dense(
        const float* __restrict__ state_x, const float* __restrict__ W3_root,
        const float* __restrict__ b3, const float* __restrict__ W32_r,
        const float* __restrict__ b32, const float* __restrict__ W4_r,
        const float* __restrict__ b4, const float* __restrict__ W42_r,
        const float* __restrict__ b42) {
    __shared__ float sW[64 * 64];
    __shared__ float sA[64 * AST];
    __shared__ float sInvH[64], sInvI[64], sWsum[64], sPosH[64], sPosI[64], sDin[64];
    int tid = threadIdx.x;
    int vbase = blockIdx.x * 64;
    if (tid < 64) {
        int v = vbase + tid; if (v >= NSn) v = NSn - 1;
        float ch = (float)g_deg_all[NVn + NSn + v];
        float ci = (float)g_deg_all[NVn + 2 * NSn + v];
        sInvH[tid] = 1.f / fmaxf(ch, 1.f);
        sInvI[tid] = 1.f / fmaxf(ci, 1.f);
        sPosH[tid] = (ch > 0.f) ? 1.f : 0.f;
        sPosI[tid] = (ci > 0.f) ? 1.f : 0.f;
        sWsum[tid] = g_wsum[v];
        sDin[tid]  = g_dinv_s[v];
    }
    __syncthreads();
    int c4 = (tid & 15) * 4, n0 = (tid >> 4) * 4;
    float acc[4][4];
    float4 bv, cv;

    // ---- L2: graph_conv ----
    stage_a36(sA, g_aggw, vbase, nullptr);
    stage_w(sW, g_WzW[0], 35 * 64);
    __syncthreads();
    bv = *(const float4*)(b3 + c4);
    cv = *(const float4*)(g_c0W[0] + c4);
#pragma unroll
    for (int i = 0; i < 4; i++) {
        float ws = sWsum[n0 + i];
        acc[i][0] = bv.x + ws * cv.x; acc[i][1] = bv.y + ws * cv.y;
        acc[i][2] = bv.z + ws * cv.z; acc[i][3] = bv.w + ws * cv.w;
    }
    gemm16(sW, sA, 35, c4, n0, acc);
    __syncthreads();
    for (int e = tid; e < 64 * 5; e += 256) {
        int n = e / 5, j = e - n * 5;
        int v = vbase + n; if (v >= NSn) v = NSn - 1;
        sA[j * AST + n] = state_x[(size_t)v * 5 + j];
    }
    stage_w(sW, W3_root, 5 * 64);
    __syncthreads();
    gemm16(sW, sA, 5, c4, n0, acc);
#pragma unroll
    for (int i = 0; i < 4; i++) {
        int v = vbase + n0 + i;
        if (v < NSn) {
            float4 o = make_float4(fmaxf(acc[i][0], 0.f), fmaxf(acc[i][1], 0.f),
                                   fmaxf(acc[i][2], 0.f), fmaxf(acc[i][3], 0.f));
            *(float4*)(g_ta + (size_t)v * 64 + c4) = o;
        }
    }
    __syncthreads();

    // ---- L3: conv32 ----
    stage_a36(sA, g_aggu, vbase, sInvH);
    stage_w(sW, g_WzW[1], 35 * 64);
    __syncthreads();
    bv = *(const float4*)(b32 + c4);
    cv = *(const float4*)(g_c0W[1] + c4);
#pragma unroll
    for (int i = 0; i < 4; i++) {
        float p = sPosH[n0 + i];
        acc[i][0] = bv.x + p * cv.x; acc[i][1] = bv.y + p * cv.y;
        acc[i][2] = bv.z + p * cv.z; acc[i][3] = bv.w + p * cv.w;
    }
    gemm16(sW, sA, 35, c4, n0, acc);
    __syncthreads();
    stage_a64(sA, g_ta, vbase, nullptr);
    stage_w(sW, W32_r, 64 * 64);
    __syncthreads();
    gemm16(sW, sA, 64, c4, n0, acc);
#pragma unroll
    for (int i = 0; i < 4; i++) {
        int v = vbase + n0 + i;
        if (v < NSn) {
            float4 o = make_float4(fmaxf(acc[i][0], 0.f), fmaxf(acc[i][1], 0.f),
                                   fmaxf(acc[i][2], 0.f), fmaxf(acc[i][3], 0.f));
            *(float4*)(g_tb + (size_t)v * 64 + c4) = o;
        }
    }
    __syncthreads();

    // ---- L4: conv4 ----
    stage_a36(sA, g_aggin, vbase, sInvI);
    stage_w(sW, g_WzW[2], 35 * 64);
    __syncthreads();
    bv = *(const float4*)(b4 + c4);
    cv = *(const float4*)(g_c0W[2] + c4);
#pragma unroll
    for (int i = 0; i < 4; i++) {
        float p = sPosI[n0 + i];
        acc[i][0] = bv.x + p * cv.x; acc[i][1] = bv.y + p * cv.y;
        acc[i][2] = bv.z + p * cv.z; acc[i][3] = bv.w + p * cv.w;
    }
    gemm16(sW, sA, 35, c4, n0, acc);
    __syncthreads();
    stage_a64(sA, g_tb, vbase, nullptr);
    stage_w(sW, W4_r, 64 * 64);
    __syncthreads();
    gemm16(sW, sA, 64, c4, n0, acc);
#pragma unroll
    for (int i = 0; i < 4; i++) {
        int v = vbase + n0 + i;
        if (v < NSn) {
            float4 o = make_float4(fmaxf(acc[i][0], 0.f), fmaxf(acc[i][1], 0.f),
                                   fmaxf(acc[i][2], 0.f), fmaxf(acc[i][3], 0.f));
            *(float4*)(g_ta + (size_t)v * 64 + c4) = o;
        }
    }
    __syncthreads();

    // ---- L5: conv42 -> sx5, pin ----
    stage_a36(sA, g_aggin, vbase, sInvI);
    stage_w(sW, g_WzW[3], 35 * 64);
    __syncthreads();
    bv = *(const float4*)(b42 + c4);
    cv = *(const float4*)(g_c0W[3] + c4);
#pragma unroll
    for (int i = 0; i < 4; i++) {
        float p = sPosI[n0 + i];
        acc[i][0] = bv.x + p * cv.x; acc[i][1] = bv.y + p * cv.y;
        acc[i][2] = bv.z + p * cv.z; acc[i][3] = bv.w + p * cv.w;
    }
    gemm16(sW, sA, 35, c4, n0, acc);
    __syncthreads();
    stage_a64(sA, g_ta, vbase, nullptr);
    stage_w(sW, W42_r, 64 * 64);
    __syncthreads();
    gemm16(sW, sA, 64, c4, n0, acc);
#pragma unroll
    for (int i = 0; i < 4; i++) {
        int v = vbase + n0 + i;
        if (v < NSn) {
            float dv = sDin[n0 + i];
            float4 o = make_float4(fmaxf(acc[i][0], 0.f), fmaxf(acc[i][1], 0.f),
                                   fmaxf(acc[i][2], 0.f), fmaxf(acc[i][3], 0.f));
            *(float4*)(g_sx5 + (size_t)v * 64 + c4) = o;
            *(float4*)(g_pin + (size_t)v * 64 + c4) =
                make_float4(dv * o.x, dv * o.y, dv * o.z, dv * o.w);
        }
    }
}

// TAG-state hop, p-form.
__global__ void k_hop64p(const float* __restrict__ pprev, float* __restrict__ pnext) {
    int gt = blockIdx.x * blockDim.x + threadIdx.x;
    int w = gt >> 5, lane = gt & 31;
    if (w >= NSn) return;
    int base = g_off_all[NVn + w], deg = g_deg_all[NVn + w];
    int sub = lane >> 4, li = lane & 15;
    float4 a = make_float4(0.f, 0.f, 0.f, 0.f);
    for (int j0 = 0; j0 < deg; j0 += 32) {
        int idx = j0 + lane;
        int sl = (idx < deg) ? g_csr_all[base + idx] : 0;
        int mres = deg - j0; if (mres > 32) mres = 32;
#pragma unroll
        for (int jj = 0; jj < 16; jj++) {
            int e2 = 2 * jj + sub;
            int s = __shfl_sync(0xffffffffu, sl, e2);
            if (e2 < mres) {
                float4 v = ((const float4*)(pprev + (size_t)s * 64))[li];
                a.x += v.x; a.y += v.y; a.z += v.z; a.w += v.w;
            }
        }
    }
    a.x += __shfl_xor_sync(0xffffffffu, a.x, 16);
    a.y += __shfl_xor_sync(0xffffffffu, a.y, 16);
    a.z += __shfl_xor_sync(0xffffffffu, a.z, 16);
    a.w += __shfl_xor_sync(0xffffffffu, a.w, 16);
    if (sub == 0) {
        float dv = g_dinv_s[w];
        float dv2 = dv * dv;
        ((float4*)(pnext + (size_t)w * 64))[li] =
            make_float4(dv2 * a.x, dv2 * a.y, dv2 * a.z, dv2 * a.w);
    }
}

// conv5 sum gather over ei_ss.
__global__ void k_sum64_gather(const float* __restrict__ feat, float* __restrict__ acc) {
    int gt = blockIdx.x * blockDim.x + threadIdx.x;
    int w = gt >> 5, lane = gt & 31;
    if (w >= NSn) return;
    int base = g_off_all[NVn + w], deg = g_deg_all[NVn + w];
    int sub = lane >> 4, li = lane & 15;
    float4 a = make_float4(0.f, 0.f, 0.f, 0.f);
    for (int j0 = 0; j0 < deg; j0 += 32) {
        int idx = j0 + lane;
        int sl = (idx < deg) ? g_csr_all[base + idx] : 0;
        int mres = deg - j0; if (mres > 32) mres = 32;
#pragma unroll
        for (int jj = 0; jj < 16; jj++) {
            int e2 = 2 * jj + sub;
            int s = __shfl_sync(0xffffffffu, sl, e2);
            if (e2 < mres) {
                float4 v = ((const float4*)(feat + (size_t)s * 64))[li];
                a.x += v.x; a.y += v.y; a.z += v.z; a.w += v.w;
            }
        }
    }
    a.x += __shfl_xor_sync(0xffffffffu, a.x, 16);
    a.y += __shfl_xor_sync(0xffffffffu, a.y, 16);
    a.z += __shfl_xor_sync(0xffffffffu, a.z, 16);
    a.w += __shfl_xor_sync(0xffffffffu, a.w, 16);
    if (sub == 0)
        ((float4*)(acc + (size_t)w * 64))[li] = a;
}

// TAG output dense.
__global__ void __launch_bounds__(256) k_tag_dense(
        const float* __restrict__ W2, const float* __restrict__ b2) {
    __shared__ float sW[64 * 64];
    __shared__ float sA[64 * AST];
    __shared__ float sSq[64];
    int tid = threadIdx.x;
    int vbase = blockIdx.x * 64;
    if (tid < 64) {
        int v = vbase + tid; if (v >= NSn) v = NSn - 1;
        sSq[tid] = g_sqd_s[v];
    }
    __syncthreads();
    int c4 = (tid & 15) * 4, n0 = (tid >> 4) * 4;
    float acc[4][4];
    float4 bv;

    stage_a64(sA, g_sx5, vbase, nullptr);
    stage_w(sW, W2, 64 * 64);
    __syncthreads();
    bv = *(const float4*)(b2 + c4);
#pragma unroll
    for (int i = 0; i < 4; i++) {
        acc[i][0] = bv.x; acc[i][1] = bv.y; acc[i][2] = bv.z; acc[i][3] = bv.w;
    }
    gemm16(sW, sA, 64, c4, n0, acc);
    __syncthreads();
#pragma unroll
    for (int k = 0; k < 3; k++) {
        stage_a64(sA, g_pk[k], vbase, sSq);
        stage_w(sW, W2 + (size_t)(k + 1) * 4096, 64 * 64);
        __syncthreads();
        gemm16(sW, sA, 64, c4, n0, acc);
        __syncthreads();
    }
#pragma unroll
    for (int i = 0; i < 4; i++) {
        int v = vbase + n0 + i;
        if (v < NSn) {
            float4 o = make_float4(fmaxf(acc[i][0], 0.f), fmaxf(acc[i][1], 0.f),
                                   fmaxf(acc[i][2], 0.f), fmaxf(acc[i][3], 0.f));
            *(float4*)(g_sx6 + (size_t)v * 64 + c4) = o;
        }
    }
}

// conv5 dense + head.
__global__ void __launch_bounds__(256) k_conv5_head(
        const float* __restrict__ W5_l, const float* __restrict__ W5_r,
        const float* __restrict__ b5, const float* __restrict__ Wl,
        const float* __restrict__ bl, float* __restrict__ out) {
    __shared__ float sW[64 * 64];
    __shared__ float sA[64 * AST];
    __shared__ float sInv[64];
    int tid = threadIdx.x;
    int vbase = blockIdx.x * 64;
    if (tid < 64) {
        int v = vbase + tid; if (v >= NSn) v = NSn - 1;
        sInv[tid] = 1.f / fmaxf(g_cntf_s[v], 1.f);
    }
    __syncthreads();
    int c4 = (tid & 15) * 4, n0 = (tid >> 4) * 4;
    float acc[4][4];
    float4 bv;

    stage_a64(sA, g_accs5, vbase, sInv);
    stage_w(sW, W5_l, 64 * 64);
    __syncthreads();
    bv = *(const float4*)(b5 + c4);
#pragma unroll
    for (int i = 0; i < 4; i++) {
        acc[i][0] = bv.x; acc[i][1] = bv.y; acc[i][2] = bv.z; acc[i][3] = bv.w;
    }
    gemm16(sW, sA, 64, c4, n0, acc);
    __syncthreads();
    stage_a64(sA, g_sx6, vbase, nullptr);
    stage_w(sW, W5_r, 64 * 64);
    __syncthreads();
    gemm16(sW, sA, 64, c4, n0, acc);
    __syncthreads();
#pragma unroll
    for (int i = 0; i < 4; i++) {
#pragma unroll
        for (int k = 0; k < 4; k++)
            sA[(c4 + k) * AST + n0 + i] = fmaxf(acc[i][k], 0.f);
    }
    stage_w(sW, Wl, 64 * 8);
    __syncthreads();
#pragma unroll
    for (int u = 0; u < 2; u++) {
        int idx = tid * 2 + u;
        int n = idx >> 3, o = idx & 7;
        float s = bl[o];
#pragma unroll 8
        for (int j = 0; j < 64; j++) s += sA[j * AST + n] * sW[j * 8 + o];
        int v = vbase + n;
        if (v < NSn) out[(size_t)v * 8 + o] = s;
    }
}

// ------------------------------- launch ------------------------------------

extern "C" void kernel_launch(void* const* d_in, const int* in_sizes, int n_in,
                              void* d_out, int out_size) {
    const float* game_x  = (const float*)d_in[0];
    const float* state_x = (const float*)d_in[1];
    const int*   ei_vv   = (const int*)d_in[2];
    const int*   et_vv   = (const int*)d_in[3];
    const int*   ei_h    = (const int*)d_in[4];
    const float* ew_h    = (const float*)d_in[5];
    const int*   ei_in   = (const int*)d_in[6];
    const int*   ei_ss   = (const int*)d_in[7];
    const float* W1_rel  = (const float*)d_in[8];
    const float* W1_root = (const float*)d_in[9];
    const float* b1      = (const float*)d_in[10];
    const float* W12     = (const float*)d_in[11];
    const float* b12     = (const float*)d_in[12];
    const float* W2      = (const float*)d_in[13];
    const float* b2      = (const float*)d_in[14];
    const float* W3_rel  = (const float*)d_in[15];
    const float* W3_root = (const float*)d_in[16];
    const float* b3      = (const float*)d_in[17];
    const float* W32_l   = (const float*)d_in[18];
    const float* W32_r   = (const float*)d_in[19];
    const float* b32     = (const float*)d_in[20];
    const float* W4_l    = (const float*)d_in[21];
    const float* W4_r    = (const float*)d_in[22];
    const float* b4      = (const float*)d_in[23];
    const float* W42_l   = (const float*)d_in[24];
    const float* W42_r   = (const float*)d_in[25];
    const float* b42     = (const float*)d_in[26];
    const float* W5_l    = (const float*)d_in[27];
    const float* W5_r    = (const float*)d_in[28];
    const float* b5      = (const float*)d_in[29];
    const float* Wl      = (const float*)d_in[30];
    const float* bl      = (const float*)d_in[31];
    float* out = (float*)d_out;

    int Evv = in_sizes[2] / 2;
    int Eh  = in_sizes[4] / 2;
    int Ein = in_sizes[6] / 2;
    int Ess = in_sizes[7] / 2;
    int Etot = Evv + Ess + Eh + Ein;

    int* pi_deg;
    float *p_pv, *p_pin, *p_pk, *p_sx6, *p_accs5;
    cudaGetSymbolAddress((void**)&pi_deg,  g_deg_all);
    cudaGetSymbolAddress((void**)&p_pv,    g_pv);
    cudaGetSymbolAddress((void**)&p_pin,   g_pin);
    cudaGetSymbolAddress((void**)&p_pk,    g_pk);
    cudaGetSymbolAddress((void**)&p_sx6,   g_sx6);
    cudaGetSymbolAddress((void**)&p_accs5, g_accs5);

    float* p_pv0 = p_pv;
    float* p_pv1 = p_pv + (size_t)NVn * 8;
    float* p_pk0 = p_pk;
    float* p_pk1 = p_pk + (size_t)NSn * 64;
    float* p_pk2 = p_pk1 + (size_t)NSn * 64;

    const int T = 256;
    auto nb = [](long n, int t) { return (int)((n + t - 1) / t); };
    int nbv_warp = nb((long)NVn * 32, T);
    int nbs_warp = nb((long)NSn * 32, T);
    int ndense = nb(NSn, 64);

    // 0) zero unified degree array
    cudaMemsetAsync(pi_deg, 0, (size_t)NDEG * 4, 0);

    // 1) fused count + pad + weight prep, then scan, then fill
    k_count_pad_prep<<<nb(Etot, T), T>>>(ei_vv, ei_ss, ei_h, ei_in,
                                         Evv, Ess, Eh, Ein,
                                         game_x, W1_rel, W1_root, b1, W12, b12,
                                         W3_rel, W32_l, W4_l, W42_l);
    k_scan<<<nb(NDEG, 1024), 1024>>>(NDEG);
    k_fill_all<<<nb(Etot, T), T>>>(ei_vv, et_vv, ei_ss, ei_h, ew_h, ei_in,
                                   Evv, Ess, Eh, Ein);

    // 2) game graph -> z
    k_rgcn_hop1<<<nbv_warp, T>>>(p_pv0);
    k_hop8_gather<<<nbv_warp, T>>>(p_pv0, p_pv1, 1, 1);
    k_hop8_gather<<<nbv_warp, T>>>(p_pv1, p_pv0, 2, 0);

    // 3) ei_h + ei_in gathers (split), then state dense chain
    k_gather_hin<<<nb((long)2 * NSn * 32, T), T>>>();
    k_state_dense<<<ndense, 256>>>(state_x, W3_root, b3, W32_r, b32,
                                   W4_r, b4, W42_r, b42);

    // 4) TAG-state hops + dense output
    k_hop64p<<<nbs_warp, T>>>(p_pin, p_pk0);
    k_hop64p<<<nbs_warp, T>>>(p_pk0, p_pk1);
    k_hop64p<<<nbs_warp, T>>>(p_pk1, p_pk2);
    k_tag_dense<<<ndense, 256>>>(W2, b2);

    // 5) conv5 gather + dense + head
    k_sum64_gather<<<nbs_warp, T>>>(p_sx6, p_accs5);
    k_conv5_head<<<ndense, 256>>>(W5_l, W5_r, b5, Wl, bl, out);
}